// round 4
// baseline (speedup 1.0000x reference)
#include <cuda_runtime.h>
#include <cstddef>

#define NB 16
#define NPT 4096
#define NS 1024
#define NK 32
#define MROWS (NB*NS*NK)

__device__ __align__(16) float g_pprime[(size_t)NB*NPT*64];
__device__ int                 g_gidx[MROWS];
__device__ __align__(16) float g_zA[(size_t)MROWS*128];
__device__ __align__(16) float g_zB[(size_t)MROWS*64];
__device__ double              g_stat[512];
__device__ float               g_scale[320];
__device__ float               g_shift[320];

__device__ __forceinline__ unsigned long long pk(float lo, float hi) {
    unsigned long long r;
    asm("mov.b64 %0, {%1,%2};" : "=l"(r) : "f"(lo), "f"(hi));
    return r;
}
__device__ __forceinline__ unsigned long long ffma2(unsigned long long a, unsigned long long b, unsigned long long c) {
    unsigned long long d;
    asm("fma.rn.f32x2 %0, %1, %2, %3;" : "=l"(d) : "l"(a), "l"(b), "l"(c));
    return d;
}
__device__ __forceinline__ void upk(unsigned long long v, float& lo, float& hi) {
    asm("mov.b64 {%0,%1}, %2;" : "=f"(lo), "=f"(hi) : "l"(v));
}
__device__ __forceinline__ unsigned f2tf32(float x) {
    unsigned r;
    asm("cvt.rna.tf32.f32 %0, %1;" : "=r"(r) : "f"(x));
    return r;
}
__device__ __forceinline__ void mma_tf32(float* c, const unsigned* a, const unsigned* b) {
    asm volatile("mma.sync.aligned.m16n8k8.row.col.f32.tf32.tf32.f32 "
        "{%0,%1,%2,%3}, {%4,%5,%6,%7}, {%8,%9}, {%0,%1,%2,%3};"
        : "+f"(c[0]), "+f"(c[1]), "+f"(c[2]), "+f"(c[3])
        : "r"(a[0]), "r"(a[1]), "r"(a[2]), "r"(a[3]), "r"(b[0]), "r"(b[1]));
}

__global__ void zero_kernel() { if (threadIdx.x < 512) g_stat[threadIdx.x] = 0.0; }

// ---- FPS: 1 block/batch, 1024 threads, xyz in SMEM, writes new_xyz to d_out ----
__global__ void fps_kernel(const float* __restrict__ xyz, float* __restrict__ out_newxyz) {
    extern __shared__ float fsm[];
    float* sx = fsm; float* sy = fsm + NPT; float* sz = fsm + 2*NPT;
    unsigned long long* sred = (unsigned long long*)(fsm + 3*NPT);
    int* sfar = (int*)(sred + 32);
    int b = blockIdx.x, t = threadIdx.x;
    const float* p = xyz + (size_t)b*NPT*3;
    for (int i = t; i < NPT; i += 1024) { sx[i]=p[3*i]; sy[i]=p[3*i+1]; sz[i]=p[3*i+2]; }
    float dist[4];
    const float INF = __int_as_float(0x7f800000);
    #pragma unroll
    for (int j = 0; j < 4; j++) dist[j] = INF;
    int far = 0;
    __syncthreads();
    for (int it = 0; it < NS; it++) {
        if (t == 0) {
            size_t o = ((size_t)b*NS + it)*3;
            out_newxyz[o] = sx[far]; out_newxyz[o+1] = sy[far]; out_newxyz[o+2] = sz[far];
        }
        if (it == NS-1) break;
        float cx = sx[far], cy = sy[far], cz = sz[far];
        unsigned long long best = 0ull;
        #pragma unroll
        for (int j = 0; j < 4; j++) {
            int pi = t + j*1024;
            float tx = __fadd_rn(sx[pi], -cx), ty = __fadd_rn(sy[pi], -cy), tz = __fadd_rn(sz[pi], -cz);
            float d = __fadd_rn(__fadd_rn(__fmul_rn(tx,tx), __fmul_rn(ty,ty)), __fmul_rn(tz,tz));
            float nd = fminf(dist[j], d);
            dist[j] = nd;
            unsigned long long key = ((unsigned long long)__float_as_uint(nd) << 32)
                                   | (unsigned)(0xFFFFFFFFu - (unsigned)pi);
            best = best > key ? best : key;
        }
        #pragma unroll
        for (int o = 16; o > 0; o >>= 1) {
            unsigned long long v = __shfl_down_sync(0xffffffffu, best, o);
            best = best > v ? best : v;
        }
        if ((t & 31) == 0) sred[t >> 5] = best;
        __syncthreads();
        if (t < 32) {
            unsigned long long v = sred[t];
            #pragma unroll
            for (int o = 16; o > 0; o >>= 1) {
                unsigned long long w = __shfl_down_sync(0xffffffffu, v, o);
                v = v > w ? v : w;
            }
            if (t == 0) *sfar = (int)(0xFFFFFFFFu - (unsigned)(v & 0xFFFFFFFFull));
        }
        __syncthreads();
        far = *sfar;
    }
}

// ---- P' = W0_pts . points  -> (B,N,64) ----
__global__ void __launch_bounds__(256) pprime_kernel(const float* __restrict__ points, const float* __restrict__ w0) {
    __shared__ float Pts[64][128];
    __shared__ float Wt[64][64];
    int b = blockIdx.y, n0 = blockIdx.x*128, t = threadIdx.x;
    for (int i = t; i < 64*64; i += 256) { int o = i>>6, c = i&63; Wt[c][o] = w0[o*67 + 3 + c]; }
    const float* pb = points + (size_t)b*64*NPT;
    for (int i = t; i < 64*128/4; i += 256) {
        int e = i*4, c = e>>7, n = e&127;
        *(float4*)&Pts[c][n] = *(const float4*)(pb + (size_t)c*NPT + n0 + n);
    }
    __syncthreads();
    int cg = t & 15, rg = t >> 4;
    unsigned long long acc[8][2];
    #pragma unroll
    for (int i = 0; i < 8; i++) { acc[i][0]=0ull; acc[i][1]=0ull; }
    #pragma unroll 4
    for (int c = 0; c < 64; c++) {
        ulonglong2 wv = *(const ulonglong2*)&Wt[c][cg*4];
        #pragma unroll
        for (int i = 0; i < 8; i++) {
            float a = Pts[c][rg*8+i];
            unsigned long long aa = pk(a, a);
            acc[i][0] = ffma2(aa, wv.x, acc[i][0]);
            acc[i][1] = ffma2(aa, wv.y, acc[i][1]);
        }
    }
    float* outp = g_pprime + ((size_t)b*NPT + n0)*64;
    #pragma unroll
    for (int i = 0; i < 8; i++) {
        float4 v; upk(acc[i][0], v.x, v.y); upk(acc[i][1], v.z, v.w);
        *(float4*)(outp + (size_t)(rg*8+i)*64 + cg*4) = v;
    }
}

// ---- ball query: warp per query group, ordered ballot scan ----
__global__ void __launch_bounds__(256) bq_kernel(const float* __restrict__ xyz, const float* __restrict__ newxyz) {
    __shared__ float sx[NPT], sy[NPT], sz[NPT];
    int b = blockIdx.y, t = threadIdx.x, w = t>>5, lane = t&31;
    const float* p = xyz + (size_t)b*NPT*3;
    for (int i = t; i < NPT; i += 256) { sx[i]=p[3*i]; sy[i]=p[3*i+1]; sz[i]=p[3*i+2]; }
    __syncthreads();
    for (int q = 0; q < 4; q++) {
        int s = blockIdx.x*32 + w*4 + q;
        const float* nc = newxyz + ((size_t)b*NS + s)*3;
        float cx = nc[0], cy = nc[1], cz = nc[2];
        float cc = __fadd_rn(__fadd_rn(__fmul_rn(cx,cx), __fmul_rn(cy,cy)), __fmul_rn(cz,cz));
        int count = 0, first = 0;
        int* go = g_gidx + ((size_t)b*NS + s)*NK;
        for (int base = 0; base < NPT && count < NK; base += 32) {
            int pi = base + lane;
            float px = sx[pi], py = sy[pi], pz = sz[pi];
            float pp  = __fadd_rn(__fadd_rn(__fmul_rn(px,px), __fmul_rn(py,py)), __fmul_rn(pz,pz));
            float dot = __fadd_rn(__fadd_rn(__fmul_rn(cx,px), __fmul_rn(cy,py)), __fmul_rn(cz,pz));
            float sqr = __fadd_rn(__fadd_rn(cc, pp), -__fmul_rn(2.0f, dot));
            bool in = (sqr <= 0.04f);
            unsigned mask = __ballot_sync(0xffffffffu, in);
            if (count == 0 && mask) first = base + __ffs(mask) - 1;
            if (in) {
                int pos = count + __popc(mask & ((1u << lane) - 1u));
                if (pos < NK) go[pos] = pi;
            }
            count += __popc(mask);
        }
        if (count < NK && lane >= count) go[lane] = first;
    }
}

// ---- layer0: z0 = P'[gidx] + W0_xyz * (xyz[gidx]-center) ----
__global__ void l0_kernel(const float* __restrict__ xyz, const float* __restrict__ w0,
                          const float* __restrict__ newxyz) {
    __shared__ float wx[64], wy[64], wz[64];
    int t = threadIdx.x;
    if (t < 64) { wx[t]=w0[t*67]; wy[t]=w0[t*67+1]; wz[t]=w0[t*67+2]; }
    __syncthreads();
    size_t row = (size_t)blockIdx.x*256 + t;
    int s = (int)((row >> 5) & 1023), b = (int)(row >> 15);
    int g = g_gidx[row];
    const float* nc = newxyz + ((size_t)b*NS + s)*3;
    const float* pt = xyz + ((size_t)b*NPT + g)*3;
    float gx = pt[0]-nc[0], gy = pt[1]-nc[1], gz = pt[2]-nc[2];
    const float4* pr = (const float4*)(g_pprime + ((size_t)b*NPT + g)*64);
    float4* out = (float4*)(g_zA + row*64);
    #pragma unroll
    for (int qq = 0; qq < 16; qq++) {
        float4 v = pr[qq]; int o = qq*4;
        v.x = fmaf(wx[o  ], gx, fmaf(wy[o  ], gy, fmaf(wz[o  ], gz, v.x)));
        v.y = fmaf(wx[o+1], gx, fmaf(wy[o+1], gy, fmaf(wz[o+1], gz, v.y)));
        v.z = fmaf(wx[o+2], gx, fmaf(wy[o+2], gy, fmaf(wz[o+2], gz, v.z)));
        v.w = fmaf(wx[o+3], gx, fmaf(wy[o+3], gy, fmaf(wz[o+3], gz, v.w)));
        out[qq] = v;
    }
}

// ---- per-channel sum/sumsq ----
template<int C, int WHICH>
__global__ void stats_kernel(int statOff) {
    const float* Z = WHICH ? g_zB : g_zA;
    __shared__ double ssum[256], ssq[256];
    int t = threadIdx.x;
    constexpr int ITER = 2048 / (256 / C);
    size_t p = (size_t)blockIdx.x * (2048*C) + t;
    double s = 0.0, q = 0.0;
    for (int i = 0; i < ITER; i++) { double v = (double)Z[p]; s += v; q += v*v; p += 256; }
    ssum[t] = s; ssq[t] = q;
    __syncthreads();
    for (int off = 128; off >= C; off >>= 1) {
        if (t < off) { ssum[t] += ssum[t+off]; ssq[t] += ssq[t+off]; }
        __syncthreads();
    }
    if (t < C) {
        atomicAdd(&g_stat[statOff + t], ssum[t]);
        atomicAdd(&g_stat[statOff + C + t], ssq[t]);
    }
}

__global__ void finalize_kernel(int C, int statOff, int bnOff,
                                const float* __restrict__ g, const float* __restrict__ bb) {
    int c = threadIdx.x;
    if (c >= C) return;
    double inv = 1.0 / (double)MROWS;
    double mean = g_stat[statOff + c] * inv;
    double var  = g_stat[statOff + C + c] * inv - mean*mean;
    double sc = (double)g[c] / sqrt(var + 1e-5);
    g_scale[bnOff + c] = (float)sc;
    g_shift[bnOff + c] = (float)((double)bb[c] - mean * sc);
}

// ---- Tensor-core GEMM (3xTF32 split) with fused BN+ReLU on the input tile ----
// X: [MROWS][64] (g_zA for COUT=64, g_zB for COUT=128), Y = X_bnrelu . W^T
template<int COUT>
__global__ void __launch_bounds__(256) gemm_tc_kernel(const float* __restrict__ W) {
    constexpr int NT  = COUT / 8;       // n-tiles of 8
    constexpr int XST = 72;             // 64 + 8 pad
    constexpr int WST = COUT + 8;
    const float* X = (COUT == 64) ? g_zA : g_zB;
    float*       Y = (COUT == 64) ? g_zB : g_zA;
    const int bnOff = (COUT == 64) ? 0 : 64;
    extern __shared__ float sm[];
    float*    Xs  = sm;                               // [128][XST] f32
    unsigned* Whi = (unsigned*)(sm + 128*XST);        // [64][WST] tf32 bits
    unsigned* Wlo = Whi + 64*WST;
    int t = threadIdx.x;
    size_t row0 = (size_t)blockIdx.x * 128;

    // X tile load + BN+ReLU (f32)
    {
        int c0 = (t*4) & 63;
        float s0=g_scale[bnOff+c0], s1=g_scale[bnOff+c0+1], s2=g_scale[bnOff+c0+2], s3=g_scale[bnOff+c0+3];
        float h0=g_shift[bnOff+c0], h1=g_shift[bnOff+c0+1], h2=g_shift[bnOff+c0+2], h3=g_shift[bnOff+c0+3];
        #pragma unroll
        for (int j = 0; j < 8; j++) {
            int e = t*4 + j*1024;
            float4 v = *(const float4*)(X + row0*64 + e);
            int r = e >> 6;
            float* xd = Xs + (size_t)r*XST + c0;
            xd[0] = fmaxf(fmaf(v.x, s0, h0), 0.f);
            xd[1] = fmaxf(fmaf(v.y, s1, h1), 0.f);
            xd[2] = fmaxf(fmaf(v.z, s2, h2), 0.f);
            xd[3] = fmaxf(fmaf(v.w, s3, h3), 0.f);
        }
    }
    // W load + hi/lo split  (Wt[k=c][n=o])
    for (int i = t; i < COUT*64; i += 256) {
        int o = i >> 6, c = i & 63;
        float wv = W[i];
        unsigned hi = f2tf32(wv);
        float lo = wv - __uint_as_float(hi);
        Whi[c*WST + o] = hi;
        Wlo[c*WST + o] = f2tf32(lo);
    }
    __syncthreads();

    int w = t >> 5, lane = t & 31;
    int g = lane >> 2, tig = lane & 3;
    int r0 = w*16 + g;                      // this thread's base row in tile

    float acc[NT][4];
    #pragma unroll
    for (int nt = 0; nt < NT; nt++) { acc[nt][0]=0.f; acc[nt][1]=0.f; acc[nt][2]=0.f; acc[nt][3]=0.f; }

    #pragma unroll
    for (int kt = 0; kt < 8; kt++) {
        const float* xa = Xs + (size_t)r0*XST + kt*8 + tig;
        float af0 = xa[0], af1 = xa[8*XST], af2 = xa[4], af3 = xa[8*XST + 4];
        unsigned ahi[4], alo[4];
        ahi[0]=f2tf32(af0); alo[0]=f2tf32(af0-__uint_as_float(ahi[0]));
        ahi[1]=f2tf32(af1); alo[1]=f2tf32(af1-__uint_as_float(ahi[1]));
        ahi[2]=f2tf32(af2); alo[2]=f2tf32(af2-__uint_as_float(ahi[2]));
        ahi[3]=f2tf32(af3); alo[3]=f2tf32(af3-__uint_as_float(ahi[3]));
        const unsigned* wh = Whi + (size_t)(kt*8+tig)*WST + g;
        const unsigned* wl = Wlo + (size_t)(kt*8+tig)*WST + g;
        #pragma unroll
        for (int nt = 0; nt < NT; nt++) {
            unsigned bh[2] = { wh[nt*8], wh[nt*8 + 4*WST] };
            unsigned bl[2] = { wl[nt*8], wl[nt*8 + 4*WST] };
            mma_tf32(acc[nt], ahi, bl);
            mma_tf32(acc[nt], alo, bh);
            mma_tf32(acc[nt], ahi, bh);
        }
    }
    // store (row0 + r0, col = nt*8 + 2*tig) and row +8
    float* yr = Y + (row0 + r0)*(size_t)COUT + 2*tig;
    #pragma unroll
    for (int nt = 0; nt < NT; nt++) {
        *(float2*)(yr + nt*8)             = make_float2(acc[nt][0], acc[nt][1]);
        *(float2*)(yr + 8*COUT + nt*8)    = make_float2(acc[nt][2], acc[nt][3]);
    }
}

// ---- BN2+ReLU+max over 32 samples, transposed store ----
__global__ void maxpool_kernel(float* __restrict__ out) {
    int o = threadIdx.x;
    size_t bs = blockIdx.x;
    const float* z = g_zA + bs*NK*128;
    float sc = g_scale[128 + o], sh = g_shift[128 + o];
    float m = 0.f;
    #pragma unroll
    for (int k = 0; k < NK; k++)
        m = fmaxf(m, fmaf(z[(size_t)k*128 + o], sc, sh));
    int b = (int)(bs >> 10), s = (int)(bs & 1023);
    out[(size_t)NB*NS*3 + ((size_t)b*128 + o)*NS + s] = m;
}

extern "C" void kernel_launch(void* const* d_in, const int* in_sizes, int n_in,
                              void* d_out, int out_size) {
    const float* xyz    = (const float*)d_in[0];
    const float* points = (const float*)d_in[1];
    const float* w0 = (const float*)d_in[2];
    const float* g0 = (const float*)d_in[3];
    const float* b0 = (const float*)d_in[4];
    const float* w1 = (const float*)d_in[5];
    const float* g1 = (const float*)d_in[6];
    const float* b1 = (const float*)d_in[7];
    const float* w2 = (const float*)d_in[8];
    const float* g2 = (const float*)d_in[9];
    const float* b2 = (const float*)d_in[10];
    float* out = (float*)d_out;

    const int FPS_SMEM = 3*NPT*4 + 32*8 + 16;
    const int G64_SMEM  = 128*72*4 + 2*64*72*4;    // 73728
    const int G128_SMEM = 128*72*4 + 2*64*136*4;   // 106496
    cudaFuncSetAttribute(fps_kernel, cudaFuncAttributeMaxDynamicSharedMemorySize, FPS_SMEM);
    cudaFuncSetAttribute(gemm_tc_kernel<64>,  cudaFuncAttributeMaxDynamicSharedMemorySize, G64_SMEM);
    cudaFuncSetAttribute(gemm_tc_kernel<128>, cudaFuncAttributeMaxDynamicSharedMemorySize, G128_SMEM);

    zero_kernel<<<1, 512>>>();
    fps_kernel<<<NB, 1024, FPS_SMEM>>>(xyz, out);
    pprime_kernel<<<dim3(NPT/128, NB), 256>>>(points, w0);
    bq_kernel<<<dim3(NS/32, NB), 256>>>(xyz, out);
    l0_kernel<<<MROWS/256, 256>>>(xyz, w0, out);
    stats_kernel<64,0><<<256, 256>>>(0);
    finalize_kernel<<<1, 128>>>(64, 0, 0, g0, b0);
    gemm_tc_kernel<64><<<MROWS/128, 256, G64_SMEM>>>(w1);
    stats_kernel<64,1><<<256, 256>>>(128);
    finalize_kernel<<<1, 128>>>(64, 128, 64, g1, b1);
    gemm_tc_kernel<128><<<MROWS/128, 256, G128_SMEM>>>(w2);
    stats_kernel<128,0><<<256, 256>>>(256);
    finalize_kernel<<<1, 128>>>(128, 256, 128, g2, b2);
    maxpool_kernel<<<NB*NS, 128>>>(out);
    (void)in_sizes; (void)n_in; (void)out_size;
}

// round 5
// speedup vs baseline: 1.8583x; 1.8583x over previous
#include <cuda_runtime.h>
#include <cstddef>

#define NB 16
#define NPT 4096
#define NS 1024
#define NK 32
#define MROWS (NB*NS*NK)
#define FTH 512

__device__ __align__(16) float g_pprime[(size_t)NB*NPT*64];
__device__ int                 g_gidx[MROWS];
__device__ __align__(16) float g_zA[(size_t)MROWS*64];   // z0
__device__ __align__(16) float g_zB[(size_t)MROWS*64];   // z1
__device__ __align__(16) float g_gmax[(size_t)NB*NS*128];
__device__ __align__(16) float g_gmin[(size_t)NB*NS*128];
__device__ double              g_stat[512];
__device__ float               g_scale[320];
__device__ float               g_shift[320];

__device__ __forceinline__ unsigned long long pk(float lo, float hi) {
    unsigned long long r;
    asm("mov.b64 %0, {%1,%2};" : "=l"(r) : "f"(lo), "f"(hi));
    return r;
}
__device__ __forceinline__ unsigned long long ffma2(unsigned long long a, unsigned long long b, unsigned long long c) {
    unsigned long long d;
    asm("fma.rn.f32x2 %0, %1, %2, %3;" : "=l"(d) : "l"(a), "l"(b), "l"(c));
    return d;
}
__device__ __forceinline__ unsigned long long add2(unsigned long long a, unsigned long long b) {
    unsigned long long d;
    asm("add.rn.f32x2 %0, %1, %2;" : "=l"(d) : "l"(a), "l"(b));
    return d;
}
__device__ __forceinline__ unsigned long long mul2(unsigned long long a, unsigned long long b) {
    unsigned long long d;
    asm("mul.rn.f32x2 %0, %1, %2;" : "=l"(d) : "l"(a), "l"(b));
    return d;
}
__device__ __forceinline__ void upk(unsigned long long v, float& lo, float& hi) {
    asm("mov.b64 {%0,%1}, %2;" : "=f"(lo), "=f"(hi) : "l"(v));
}
__device__ __forceinline__ unsigned redux_umax(unsigned v) {
    unsigned r;
    asm("redux.sync.max.u32 %0, %1, 0xffffffff;" : "=r"(r) : "r"(v));
    return r;
}
__device__ __forceinline__ unsigned f2tf32(float x) {
    unsigned r;
    asm("cvt.rna.tf32.f32 %0, %1;" : "=r"(r) : "f"(x));
    return r;
}
__device__ __forceinline__ void mma_tf32(float* c, const unsigned* a, const unsigned* b) {
    asm volatile("mma.sync.aligned.m16n8k8.row.col.f32.tf32.tf32.f32 "
        "{%0,%1,%2,%3}, {%4,%5,%6,%7}, {%8,%9}, {%0,%1,%2,%3};"
        : "+f"(c[0]), "+f"(c[1]), "+f"(c[2]), "+f"(c[3])
        : "r"(a[0]), "r"(a[1]), "r"(a[2]), "r"(a[3]), "r"(b[0]), "r"(b[1]));
}

__global__ void zero_kernel() { if (threadIdx.x < 512) g_stat[threadIdx.x] = 0.0; }

// ---- FPS v2: 512 threads, 8 pts/thread in registers (packed f32x2), redux argmax ----
__global__ void __launch_bounds__(FTH) fps_kernel(const float* __restrict__ xyz, float* __restrict__ out_newxyz) {
    extern __shared__ float fsm[];
    float* sx = fsm; float* sy = fsm + NPT; float* sz = fsm + 2*NPT;
    unsigned* swhi = (unsigned*)(fsm + 3*NPT);
    unsigned* swlo = swhi + 16;
    int* sfar = (int*)(swlo + 16);
    int b = blockIdx.x, t = threadIdx.x;
    const float* p = xyz + (size_t)b*NPT*3;
    for (int i = t; i < NPT; i += FTH) { sx[i]=p[3*i]; sy[i]=p[3*i+1]; sz[i]=p[3*i+2]; }
    __syncthreads();
    unsigned long long pxp[4], pyp[4], pzp[4];
    float dist[8];
    const float INF = __int_as_float(0x7f800000);
    #pragma unroll
    for (int j = 0; j < 4; j++) {
        int p0 = t + (2*j)*FTH, p1 = t + (2*j+1)*FTH;
        pxp[j] = pk(sx[p0], sx[p1]);
        pyp[j] = pk(sy[p0], sy[p1]);
        pzp[j] = pk(sz[p0], sz[p1]);
        dist[2*j] = INF; dist[2*j+1] = INF;
    }
    int far = 0;
    for (int it = 0; it < NS; it++) {
        if (t == 0) {
            size_t o = ((size_t)b*NS + it)*3;
            out_newxyz[o] = sx[far]; out_newxyz[o+1] = sy[far]; out_newxyz[o+2] = sz[far];
        }
        if (it == NS-1) break;
        float cx = sx[far], cy = sy[far], cz = sz[far];
        unsigned long long ncx = pk(-cx,-cx), ncy = pk(-cy,-cy), ncz = pk(-cz,-cz);
        #pragma unroll
        for (int j = 0; j < 4; j++) {
            unsigned long long dx = add2(pxp[j], ncx);
            unsigned long long dy = add2(pyp[j], ncy);
            unsigned long long dz = add2(pzp[j], ncz);
            unsigned long long d2 = add2(add2(mul2(dx,dx), mul2(dy,dy)), mul2(dz,dz));
            float d0, d1; upk(d2, d0, d1);
            dist[2*j]   = fminf(dist[2*j],   d0);
            dist[2*j+1] = fminf(dist[2*j+1], d1);
        }
        float best = dist[0]; int bj = 0;
        #pragma unroll
        for (int k = 1; k < 8; k++) if (dist[k] > best) { best = dist[k]; bj = k; }
        unsigned hi  = __float_as_uint(best);
        unsigned whi = redux_umax(hi);
        unsigned lo  = (hi == whi) ? (0xFFFFFFFFu - (unsigned)(t + bj*FTH)) : 0u;
        unsigned wlo = redux_umax(lo);
        if ((t & 31) == 0) { swhi[t>>5] = whi; swlo[t>>5] = wlo; }
        __syncthreads();
        if (t < 32) {
            unsigned h2 = (t < 16) ? swhi[t] : 0u;
            unsigned l2 = (t < 16) ? swlo[t] : 0u;
            unsigned mh = redux_umax(h2);
            unsigned ml = redux_umax((h2 == mh) ? l2 : 0u);
            if (t == 0) *sfar = (int)(0xFFFFFFFFu - ml);
        }
        __syncthreads();
        far = *sfar;
    }
}

// ---- P' = W0_pts . points  -> (B,N,64) ----
__global__ void __launch_bounds__(256) pprime_kernel(const float* __restrict__ points, const float* __restrict__ w0) {
    __shared__ float Pts[64][128];
    __shared__ float Wt[64][64];
    int b = blockIdx.y, n0 = blockIdx.x*128, t = threadIdx.x;
    for (int i = t; i < 64*64; i += 256) { int o = i>>6, c = i&63; Wt[c][o] = w0[o*67 + 3 + c]; }
    const float* pb = points + (size_t)b*64*NPT;
    for (int i = t; i < 64*128/4; i += 256) {
        int e = i*4, c = e>>7, n = e&127;
        *(float4*)&Pts[c][n] = *(const float4*)(pb + (size_t)c*NPT + n0 + n);
    }
    __syncthreads();
    int cg = t & 15, rg = t >> 4;
    unsigned long long acc[8][2];
    #pragma unroll
    for (int i = 0; i < 8; i++) { acc[i][0]=0ull; acc[i][1]=0ull; }
    #pragma unroll 4
    for (int c = 0; c < 64; c++) {
        ulonglong2 wv = *(const ulonglong2*)&Wt[c][cg*4];
        #pragma unroll
        for (int i = 0; i < 8; i++) {
            float a = Pts[c][rg*8+i];
            unsigned long long aa = pk(a, a);
            acc[i][0] = ffma2(aa, wv.x, acc[i][0]);
            acc[i][1] = ffma2(aa, wv.y, acc[i][1]);
        }
    }
    float* outp = g_pprime + ((size_t)b*NPT + n0)*64;
    #pragma unroll
    for (int i = 0; i < 8; i++) {
        float4 v; upk(acc[i][0], v.x, v.y); upk(acc[i][1], v.z, v.w);
        *(float4*)(outp + (size_t)(rg*8+i)*64 + cg*4) = v;
    }
}

// ---- ball query (frozen arithmetic) ----
__global__ void __launch_bounds__(256) bq_kernel(const float* __restrict__ xyz, const float* __restrict__ newxyz) {
    __shared__ float sx[NPT], sy[NPT], sz[NPT];
    int b = blockIdx.y, t = threadIdx.x, w = t>>5, lane = t&31;
    const float* p = xyz + (size_t)b*NPT*3;
    for (int i = t; i < NPT; i += 256) { sx[i]=p[3*i]; sy[i]=p[3*i+1]; sz[i]=p[3*i+2]; }
    __syncthreads();
    for (int q = 0; q < 4; q++) {
        int s = blockIdx.x*32 + w*4 + q;
        const float* nc = newxyz + ((size_t)b*NS + s)*3;
        float cx = nc[0], cy = nc[1], cz = nc[2];
        float cc = __fadd_rn(__fadd_rn(__fmul_rn(cx,cx), __fmul_rn(cy,cy)), __fmul_rn(cz,cz));
        int count = 0, first = 0;
        int* go = g_gidx + ((size_t)b*NS + s)*NK;
        for (int base = 0; base < NPT && count < NK; base += 32) {
            int pi = base + lane;
            float px = sx[pi], py = sy[pi], pz = sz[pi];
            float pp  = __fadd_rn(__fadd_rn(__fmul_rn(px,px), __fmul_rn(py,py)), __fmul_rn(pz,pz));
            float dot = __fadd_rn(__fadd_rn(__fmul_rn(cx,px), __fmul_rn(cy,py)), __fmul_rn(cz,pz));
            float sqr = __fadd_rn(__fadd_rn(cc, pp), -__fmul_rn(2.0f, dot));
            bool in = (sqr <= 0.04f);
            unsigned mask = __ballot_sync(0xffffffffu, in);
            if (count == 0 && mask) first = base + __ffs(mask) - 1;
            if (in) {
                int pos = count + __popc(mask & ((1u << lane) - 1u));
                if (pos < NK) go[pos] = pi;
            }
            count += __popc(mask);
        }
        if (count < NK && lane >= count) go[lane] = first;
    }
}

// ---- layer0: z0 = P'[gidx] + W0_xyz * (xyz[gidx]-center) ----
__global__ void l0_kernel(const float* __restrict__ xyz, const float* __restrict__ w0,
                          const float* __restrict__ newxyz) {
    __shared__ float wx[64], wy[64], wz[64];
    int t = threadIdx.x;
    if (t < 64) { wx[t]=w0[t*67]; wy[t]=w0[t*67+1]; wz[t]=w0[t*67+2]; }
    __syncthreads();
    size_t row = (size_t)blockIdx.x*256 + t;
    int s = (int)((row >> 5) & 1023), b = (int)(row >> 15);
    int g = g_gidx[row];
    const float* nc = newxyz + ((size_t)b*NS + s)*3;
    const float* pt = xyz + ((size_t)b*NPT + g)*3;
    float gx = pt[0]-nc[0], gy = pt[1]-nc[1], gz = pt[2]-nc[2];
    const float4* pr = (const float4*)(g_pprime + ((size_t)b*NPT + g)*64);
    float4* out = (float4*)(g_zA + row*64);
    #pragma unroll
    for (int qq = 0; qq < 16; qq++) {
        float4 v = pr[qq]; int o = qq*4;
        v.x = fmaf(wx[o  ], gx, fmaf(wy[o  ], gy, fmaf(wz[o  ], gz, v.x)));
        v.y = fmaf(wx[o+1], gx, fmaf(wy[o+1], gy, fmaf(wz[o+1], gz, v.y)));
        v.z = fmaf(wx[o+2], gx, fmaf(wy[o+2], gy, fmaf(wz[o+2], gz, v.z)));
        v.w = fmaf(wx[o+3], gx, fmaf(wy[o+3], gy, fmaf(wz[o+3], gz, v.w)));
        out[qq] = v;
    }
}

// ---- layer-0 stats over g_zA ----
__global__ void stats0_kernel() {
    const float* Z = g_zA;
    __shared__ double ssum[256], ssq[256];
    int t = threadIdx.x;
    size_t p = (size_t)blockIdx.x * (2048*64) + t;
    double s = 0.0, q = 0.0;
    for (int i = 0; i < 512; i++) { double v = (double)Z[p]; s += v; q += v*v; p += 256; }
    ssum[t] = s; ssq[t] = q;
    __syncthreads();
    for (int off = 128; off >= 64; off >>= 1) {
        if (t < off) { ssum[t] += ssum[t+off]; ssq[t] += ssq[t+off]; }
        __syncthreads();
    }
    if (t < 64) {
        atomicAdd(&g_stat[t], ssum[t]);
        atomicAdd(&g_stat[64 + t], ssq[t]);
    }
}

__global__ void finalize_kernel(int C, int statOff, int bnOff,
                                const float* __restrict__ g, const float* __restrict__ bb) {
    int c = threadIdx.x;
    if (c >= C) return;
    double inv = 1.0 / (double)MROWS;
    double mean = g_stat[statOff + c] * inv;
    double var  = g_stat[statOff + C + c] * inv - mean*mean;
    double sc = (double)g[c] / sqrt(var + 1e-5);
    g_scale[bnOff + c] = (float)sc;
    g_shift[bnOff + c] = (float)((double)bb[c] - mean * sc);
}

// ---- TC GEMM (3xTF32) + fused BN+ReLU input + fused stats (+max/min for COUT=128) ----
template<int COUT>
__global__ void __launch_bounds__(256) gemm_tc_kernel(const float* __restrict__ W) {
    constexpr int NT  = COUT / 8;
    constexpr int XST = 72;
    constexpr int WST = COUT + 8;
    constexpr int statOff = (COUT == 64) ? 128 : 256;
    const float* X = (COUT == 64) ? g_zA : g_zB;
    const int bnOff = (COUT == 64) ? 0 : 64;
    extern __shared__ float sm[];
    float*    Xs  = sm;                               // [128][72]
    unsigned* Whi = (unsigned*)(sm + 128*XST);
    unsigned* Wlo = Whi + 64*WST;
    int t = threadIdx.x;
    size_t row0 = (size_t)blockIdx.x * 128;

    {
        int c0 = (t*4) & 63;
        float s0=g_scale[bnOff+c0], s1=g_scale[bnOff+c0+1], s2=g_scale[bnOff+c0+2], s3=g_scale[bnOff+c0+3];
        float h0=g_shift[bnOff+c0], h1=g_shift[bnOff+c0+1], h2=g_shift[bnOff+c0+2], h3=g_shift[bnOff+c0+3];
        #pragma unroll
        for (int j = 0; j < 8; j++) {
            int e = t*4 + j*1024;
            float4 v = *(const float4*)(X + row0*64 + e);
            int r = e >> 6;
            float* xd = Xs + (size_t)r*XST + c0;
            xd[0] = fmaxf(fmaf(v.x, s0, h0), 0.f);
            xd[1] = fmaxf(fmaf(v.y, s1, h1), 0.f);
            xd[2] = fmaxf(fmaf(v.z, s2, h2), 0.f);
            xd[3] = fmaxf(fmaf(v.w, s3, h3), 0.f);
        }
    }
    for (int i = t; i < COUT*64; i += 256) {
        int o = i >> 6, c = i & 63;
        float wv = W[i];
        unsigned hi = f2tf32(wv);
        float lo = wv - __uint_as_float(hi);
        Whi[c*WST + o] = hi;
        Wlo[c*WST + o] = f2tf32(lo);
    }
    __syncthreads();

    int w = t >> 5, lane = t & 31;
    int g = lane >> 2, tig = lane & 3;
    int r0 = w*16 + g;

    float acc[NT][4];
    #pragma unroll
    for (int nt = 0; nt < NT; nt++) { acc[nt][0]=0.f; acc[nt][1]=0.f; acc[nt][2]=0.f; acc[nt][3]=0.f; }

    #pragma unroll
    for (int kt = 0; kt < 8; kt++) {
        const float* xa = Xs + (size_t)r0*XST + kt*8 + tig;
        float af0 = xa[0], af1 = xa[8*XST], af2 = xa[4], af3 = xa[8*XST + 4];
        unsigned ahi[4], alo[4];
        ahi[0]=f2tf32(af0); alo[0]=f2tf32(af0-__uint_as_float(ahi[0]));
        ahi[1]=f2tf32(af1); alo[1]=f2tf32(af1-__uint_as_float(ahi[1]));
        ahi[2]=f2tf32(af2); alo[2]=f2tf32(af2-__uint_as_float(ahi[2]));
        ahi[3]=f2tf32(af3); alo[3]=f2tf32(af3-__uint_as_float(ahi[3]));
        const unsigned* wh = Whi + (size_t)(kt*8+tig)*WST + g;
        const unsigned* wl = Wlo + (size_t)(kt*8+tig)*WST + g;
        #pragma unroll
        for (int nt = 0; nt < NT; nt++) {
            unsigned bh[2] = { wh[nt*8], wh[nt*8 + 4*WST] };
            unsigned bl[2] = { wl[nt*8], wl[nt*8 + 4*WST] };
            mma_tf32(acc[nt], ahi, bl);
            mma_tf32(acc[nt], alo, bh);
            mma_tf32(acc[nt], ahi, bh);
        }
    }
    // z1 must persist for the next GEMM
    if (COUT == 64) {
        float* yr = g_zB + (row0 + r0)*(size_t)64 + 2*tig;
        #pragma unroll
        for (int nt = 0; nt < NT; nt++) {
            *(float2*)(yr + nt*8)          = make_float2(acc[nt][0], acc[nt][1]);
            *(float2*)(yr + 8*64 + nt*8)   = make_float2(acc[nt][2], acc[nt][3]);
        }
    }

    // ---- fused epilogue: per-channel stats (+ group max/min for COUT==128) ----
    __syncthreads();                 // everyone done with Xs/W smem
    float* ssum = sm;                // [COUT]
    float* ssq  = sm + COUT;         // [COUT]
    float* wmax = sm + 2*COUT;       // [8][COUT]
    float* wmin = wmax + 8*COUT;
    if (t < 2*COUT) sm[t] = 0.f;
    __syncthreads();

    #pragma unroll
    for (int nt = 0; nt < NT; nt++) {
        int c0 = nt*8 + 2*tig;
        float a0 = acc[nt][0], a1 = acc[nt][1], a2 = acc[nt][2], a3 = acc[nt][3];
        float sc0 = a0 + a2, sc1 = a1 + a3;
        float qc0 = a0*a0 + a2*a2, qc1 = a1*a1 + a3*a3;
        #pragma unroll
        for (int off = 4; off <= 16; off <<= 1) {
            sc0 += __shfl_xor_sync(0xffffffffu, sc0, off);
            sc1 += __shfl_xor_sync(0xffffffffu, sc1, off);
            qc0 += __shfl_xor_sync(0xffffffffu, qc0, off);
            qc1 += __shfl_xor_sync(0xffffffffu, qc1, off);
        }
        if (g == 0) {
            atomicAdd(&ssum[c0],   sc0); atomicAdd(&ssum[c0+1], sc1);
            atomicAdd(&ssq[c0],    qc0); atomicAdd(&ssq[c0+1],  qc1);
        }
        if (COUT == 128) {
            float m0 = fmaxf(a0, a2), m1 = fmaxf(a1, a3);
            float n0 = fminf(a0, a2), n1 = fminf(a1, a3);
            #pragma unroll
            for (int off = 4; off <= 16; off <<= 1) {
                m0 = fmaxf(m0, __shfl_xor_sync(0xffffffffu, m0, off));
                m1 = fmaxf(m1, __shfl_xor_sync(0xffffffffu, m1, off));
                n0 = fminf(n0, __shfl_xor_sync(0xffffffffu, n0, off));
                n1 = fminf(n1, __shfl_xor_sync(0xffffffffu, n1, off));
            }
            if (g == 0) {
                wmax[w*COUT + c0] = m0; wmax[w*COUT + c0+1] = m1;
                wmin[w*COUT + c0] = n0; wmin[w*COUT + c0+1] = n1;
            }
        }
    }
    __syncthreads();
    if (COUT == 128) {
        size_t grp0 = (size_t)blockIdx.x * 4;
        for (int i = t; i < 4*128; i += 256) {
            int gr = i >> 7, c = i & 127;
            float mx = fmaxf(wmax[(2*gr)*128 + c], wmax[(2*gr+1)*128 + c]);
            float mn = fminf(wmin[(2*gr)*128 + c], wmin[(2*gr+1)*128 + c]);
            g_gmax[(grp0 + gr)*128 + c] = mx;
            g_gmin[(grp0 + gr)*128 + c] = mn;
        }
    }
    if (t < COUT) {
        atomicAdd(&g_stat[statOff + t],        (double)ssum[t]);
        atomicAdd(&g_stat[statOff + COUT + t], (double)ssq[t]);
    }
}

// ---- final output: BN2+ReLU+max via per-group extrema ----
__global__ void output_kernel(float* __restrict__ out) {
    int o = threadIdx.x;
    size_t bs = blockIdx.x;
    float sc = g_scale[128 + o], sh = g_shift[128 + o];
    float mx = g_gmax[bs*128 + o], mn = g_gmin[bs*128 + o];
    float v = (sc > 0.f) ? fmaf(sc, mx, sh) : fmaf(sc, mn, sh);
    int b = (int)(bs >> 10), s = (int)(bs & 1023);
    out[(size_t)NB*NS*3 + ((size_t)b*128 + o)*NS + s] = fmaxf(v, 0.f);
}

extern "C" void kernel_launch(void* const* d_in, const int* in_sizes, int n_in,
                              void* d_out, int out_size) {
    const float* xyz    = (const float*)d_in[0];
    const float* points = (const float*)d_in[1];
    const float* w0 = (const float*)d_in[2];
    const float* g0 = (const float*)d_in[3];
    const float* b0 = (const float*)d_in[4];
    const float* w1 = (const float*)d_in[5];
    const float* g1 = (const float*)d_in[6];
    const float* b1 = (const float*)d_in[7];
    const float* w2 = (const float*)d_in[8];
    const float* g2 = (const float*)d_in[9];
    const float* b2 = (const float*)d_in[10];
    float* out = (float*)d_out;

    const int FPS_SMEM  = 3*NPT*4 + 16*4 + 16*4 + 16;
    const int G64_SMEM  = 128*72*4 + 2*64*72*4;
    const int G128_SMEM = 128*72*4 + 2*64*136*4;
    cudaFuncSetAttribute(fps_kernel, cudaFuncAttributeMaxDynamicSharedMemorySize, FPS_SMEM);
    cudaFuncSetAttribute(gemm_tc_kernel<64>,  cudaFuncAttributeMaxDynamicSharedMemorySize, G64_SMEM);
    cudaFuncSetAttribute(gemm_tc_kernel<128>, cudaFuncAttributeMaxDynamicSharedMemorySize, G128_SMEM);

    zero_kernel<<<1, 512>>>();
    fps_kernel<<<NB, FTH, FPS_SMEM>>>(xyz, out);
    pprime_kernel<<<dim3(NPT/128, NB), 256>>>(points, w0);
    bq_kernel<<<dim3(NS/32, NB), 256>>>(xyz, out);
    l0_kernel<<<MROWS/256, 256>>>(xyz, w0, out);
    stats0_kernel<<<256, 256>>>();
    finalize_kernel<<<1, 128>>>(64, 0, 0, g0, b0);
    gemm_tc_kernel<64><<<MROWS/128, 256, G64_SMEM>>>(w1);
    finalize_kernel<<<1, 128>>>(64, 128, 64, g1, b1);
    gemm_tc_kernel<128><<<MROWS/128, 256, G128_SMEM>>>(w2);
    finalize_kernel<<<1, 128>>>(128, 256, 128, g2, b2);
    output_kernel<<<NB*NS, 128>>>(out);
    (void)in_sizes; (void)n_in; (void)out_size;
}

// round 6
// speedup vs baseline: 2.2113x; 1.1899x over previous
#include <cuda_runtime.h>
#include <cstddef>

#define NB 16
#define NPT 4096
#define NS 1024
#define NK 32
#define MROWS (NB*NS*NK)
#define FTH 512

__device__ __align__(16) float g_pprime[(size_t)NB*NPT*64];
__device__ int                 g_gidx[MROWS];
__device__ __align__(16) float g_zB[(size_t)MROWS*64];   // z1
__device__ __align__(16) float g_gmax[(size_t)NB*NS*128];
__device__ __align__(16) float g_gmin[(size_t)NB*NS*128];
__device__ double              g_stat[512];
__device__ float               g_scale[320];
__device__ float               g_shift[320];

__device__ __forceinline__ unsigned long long pk(float lo, float hi) {
    unsigned long long r;
    asm("mov.b64 %0, {%1,%2};" : "=l"(r) : "f"(lo), "f"(hi));
    return r;
}
__device__ __forceinline__ unsigned long long ffma2(unsigned long long a, unsigned long long b, unsigned long long c) {
    unsigned long long d;
    asm("fma.rn.f32x2 %0, %1, %2, %3;" : "=l"(d) : "l"(a), "l"(b), "l"(c));
    return d;
}
__device__ __forceinline__ unsigned long long add2(unsigned long long a, unsigned long long b) {
    unsigned long long d;
    asm("add.rn.f32x2 %0, %1, %2;" : "=l"(d) : "l"(a), "l"(b));
    return d;
}
__device__ __forceinline__ unsigned long long mul2(unsigned long long a, unsigned long long b) {
    unsigned long long d;
    asm("mul.rn.f32x2 %0, %1, %2;" : "=l"(d) : "l"(a), "l"(b));
    return d;
}
__device__ __forceinline__ void upk(unsigned long long v, float& lo, float& hi) {
    asm("mov.b64 {%0,%1}, %2;" : "=f"(lo), "=f"(hi) : "l"(v));
}
__device__ __forceinline__ unsigned redux_umax(unsigned v) {
    unsigned r;
    asm("redux.sync.max.u32 %0, %1, 0xffffffff;" : "=r"(r) : "r"(v));
    return r;
}
__device__ __forceinline__ unsigned f2tf32(float x) {
    unsigned r;
    asm("cvt.rna.tf32.f32 %0, %1;" : "=r"(r) : "f"(x));
    return r;
}
__device__ __forceinline__ void mma_tf32(float* c, const unsigned* a, const unsigned* b) {
    asm volatile("mma.sync.aligned.m16n8k8.row.col.f32.tf32.tf32.f32 "
        "{%0,%1,%2,%3}, {%4,%5,%6,%7}, {%8,%9}, {%0,%1,%2,%3};"
        : "+f"(c[0]), "+f"(c[1]), "+f"(c[2]), "+f"(c[3])
        : "r"(a[0]), "r"(a[1]), "r"(a[2]), "r"(a[3]), "r"(b[0]), "r"(b[1]));
}

__global__ void zero_kernel() { if (threadIdx.x < 512) g_stat[threadIdx.x] = 0.0; }

// ---- FPS v3: single barrier per iteration, double-buffered warp results ----
__global__ void __launch_bounds__(FTH) fps_kernel(const float* __restrict__ xyz, float* __restrict__ out_newxyz) {
    extern __shared__ float fsm[];
    float* sx = fsm; float* sy = fsm + NPT; float* sz = fsm + 2*NPT;
    unsigned* swhi = (unsigned*)(fsm + 3*NPT);   // [2][16]
    unsigned* swlo = swhi + 32;                  // [2][16]
    int b = blockIdx.x, t = threadIdx.x;
    int w = t >> 5, lane = t & 31;
    const float* p = xyz + (size_t)b*NPT*3;
    for (int i = t; i < NPT; i += FTH) { sx[i]=p[3*i]; sy[i]=p[3*i+1]; sz[i]=p[3*i+2]; }
    __syncthreads();
    unsigned long long pxp[4], pyp[4], pzp[4];
    float dist[8];
    const float INF = __int_as_float(0x7f800000);
    #pragma unroll
    for (int j = 0; j < 4; j++) {
        int p0 = t + (2*j)*FTH, p1 = t + (2*j+1)*FTH;
        pxp[j] = pk(sx[p0], sx[p1]);
        pyp[j] = pk(sy[p0], sy[p1]);
        pzp[j] = pk(sz[p0], sz[p1]);
        dist[2*j] = INF; dist[2*j+1] = INF;
    }
    int far = 0;
    for (int it = 0; it < NS; it++) {
        if (t == 0) {
            size_t o = ((size_t)b*NS + it)*3;
            out_newxyz[o] = sx[far]; out_newxyz[o+1] = sy[far]; out_newxyz[o+2] = sz[far];
        }
        if (it == NS-1) break;
        float cx = sx[far], cy = sy[far], cz = sz[far];
        unsigned long long ncx = pk(-cx,-cx), ncy = pk(-cy,-cy), ncz = pk(-cz,-cz);
        #pragma unroll
        for (int j = 0; j < 4; j++) {
            unsigned long long dx = add2(pxp[j], ncx);
            unsigned long long dy = add2(pyp[j], ncy);
            unsigned long long dz = add2(pzp[j], ncz);
            unsigned long long d2 = add2(add2(mul2(dx,dx), mul2(dy,dy)), mul2(dz,dz));
            float d0, d1; upk(d2, d0, d1);
            dist[2*j]   = fminf(dist[2*j],   d0);
            dist[2*j+1] = fminf(dist[2*j+1], d1);
        }
        float best = dist[0]; int bj = 0;
        #pragma unroll
        for (int k = 1; k < 8; k++) if (dist[k] > best) { best = dist[k]; bj = k; }
        unsigned hi  = __float_as_uint(best);
        unsigned whi = redux_umax(hi);
        unsigned lo  = (hi == whi) ? (0xFFFFFFFFu - (unsigned)(t + bj*FTH)) : 0u;
        unsigned wlo = redux_umax(lo);
        int buf = (it & 1) << 4;
        if (lane == 0) { swhi[buf + w] = whi; swlo[buf + w] = wlo; }
        __syncthreads();
        unsigned h2 = swhi[buf + (lane & 15)];
        unsigned l2 = swlo[buf + (lane & 15)];
        unsigned mh = redux_umax(h2);
        unsigned ml = redux_umax((h2 == mh) ? l2 : 0u);
        far = (int)(0xFFFFFFFFu - ml);
    }
}

// ---- P' = W0_pts . points  -> (B,N,64) ----
__global__ void __launch_bounds__(256) pprime_kernel(const float* __restrict__ points, const float* __restrict__ w0) {
    __shared__ float Pts[64][128];
    __shared__ float Wt[64][64];
    int b = blockIdx.y, n0 = blockIdx.x*128, t = threadIdx.x;
    for (int i = t; i < 64*64; i += 256) { int o = i>>6, c = i&63; Wt[c][o] = w0[o*67 + 3 + c]; }
    const float* pb = points + (size_t)b*64*NPT;
    for (int i = t; i < 64*128/4; i += 256) {
        int e = i*4, c = e>>7, n = e&127;
        *(float4*)&Pts[c][n] = *(const float4*)(pb + (size_t)c*NPT + n0 + n);
    }
    __syncthreads();
    int cg = t & 15, rg = t >> 4;
    unsigned long long acc[8][2];
    #pragma unroll
    for (int i = 0; i < 8; i++) { acc[i][0]=0ull; acc[i][1]=0ull; }
    #pragma unroll 4
    for (int c = 0; c < 64; c++) {
        ulonglong2 wv = *(const ulonglong2*)&Wt[c][cg*4];
        #pragma unroll
        for (int i = 0; i < 8; i++) {
            float a = Pts[c][rg*8+i];
            unsigned long long aa = pk(a, a);
            acc[i][0] = ffma2(aa, wv.x, acc[i][0]);
            acc[i][1] = ffma2(aa, wv.y, acc[i][1]);
        }
    }
    float* outp = g_pprime + ((size_t)b*NPT + n0)*64;
    #pragma unroll
    for (int i = 0; i < 8; i++) {
        float4 v; upk(acc[i][0], v.x, v.y); upk(acc[i][1], v.z, v.w);
        *(float4*)(outp + (size_t)(rg*8+i)*64 + cg*4) = v;
    }
}

// ---- ball query (frozen arithmetic) ----
__global__ void __launch_bounds__(256) bq_kernel(const float* __restrict__ xyz, const float* __restrict__ newxyz) {
    __shared__ float sx[NPT], sy[NPT], sz[NPT];
    int b = blockIdx.y, t = threadIdx.x, w = t>>5, lane = t&31;
    const float* p = xyz + (size_t)b*NPT*3;
    for (int i = t; i < NPT; i += 256) { sx[i]=p[3*i]; sy[i]=p[3*i+1]; sz[i]=p[3*i+2]; }
    __syncthreads();
    for (int q = 0; q < 4; q++) {
        int s = blockIdx.x*32 + w*4 + q;
        const float* nc = newxyz + ((size_t)b*NS + s)*3;
        float cx = nc[0], cy = nc[1], cz = nc[2];
        float cc = __fadd_rn(__fadd_rn(__fmul_rn(cx,cx), __fmul_rn(cy,cy)), __fmul_rn(cz,cz));
        int count = 0, first = 0;
        int* go = g_gidx + ((size_t)b*NS + s)*NK;
        for (int base = 0; base < NPT && count < NK; base += 32) {
            int pi = base + lane;
            float px = sx[pi], py = sy[pi], pz = sz[pi];
            float pp  = __fadd_rn(__fadd_rn(__fmul_rn(px,px), __fmul_rn(py,py)), __fmul_rn(pz,pz));
            float dot = __fadd_rn(__fadd_rn(__fmul_rn(cx,px), __fmul_rn(cy,py)), __fmul_rn(cz,pz));
            float sqr = __fadd_rn(__fadd_rn(cc, pp), -__fmul_rn(2.0f, dot));
            bool in = (sqr <= 0.04f);
            unsigned mask = __ballot_sync(0xffffffffu, in);
            if (count == 0 && mask) first = base + __ffs(mask) - 1;
            if (in) {
                int pos = count + __popc(mask & ((1u << lane) - 1u));
                if (pos < NK) go[pos] = pi;
            }
            count += __popc(mask);
        }
        if (count < NK && lane >= count) go[lane] = first;
    }
}

// ---- layer-0 stats directly from gather (z0 never materialized) ----
__global__ void __launch_bounds__(256) stats0g_kernel(const float* __restrict__ xyz,
                                                      const float* __restrict__ w0,
                                                      const float* __restrict__ newxyz) {
    __shared__ float wx[64], wy[64], wz[64];
    __shared__ float ssum[4][64], ssq[4][64];
    int t = threadIdx.x;
    if (t < 64) { wx[t]=w0[t*67]; wy[t]=w0[t*67+1]; wz[t]=w0[t*67+2]; }
    __syncthreads();
    int c = t & 63, rl = t >> 6;
    float wxc = wx[c], wyc = wy[c], wzc = wz[c];
    float s = 0.f, q = 0.f;
    size_t base = (size_t)blockIdx.x * 1024;
    for (int i = 0; i < 256; i++) {
        size_t row = base + i*4 + rl;
        int g = g_gidx[row];
        int ss = (int)((row >> 5) & 1023), b = (int)(row >> 15);
        const float* nc = newxyz + ((size_t)b*NS + ss)*3;
        const float* pt = xyz + ((size_t)b*NPT + g)*3;
        float gx = pt[0]-nc[0], gy = pt[1]-nc[1], gz = pt[2]-nc[2];
        float v = g_pprime[((size_t)b*NPT + g)*64 + c];
        v = fmaf(wxc, gx, fmaf(wyc, gy, fmaf(wzc, gz, v)));
        s += v; q = fmaf(v, v, q);
    }
    ssum[rl][c] = s; ssq[rl][c] = q;
    __syncthreads();
    if (t < 64) {
        double S = (double)ssum[0][t] + (double)ssum[1][t] + (double)ssum[2][t] + (double)ssum[3][t];
        double Q = (double)ssq[0][t]  + (double)ssq[1][t]  + (double)ssq[2][t]  + (double)ssq[3][t];
        atomicAdd(&g_stat[t], S);
        atomicAdd(&g_stat[64 + t], Q);
    }
}

__global__ void finalize_kernel(int C, int statOff, int bnOff,
                                const float* __restrict__ g, const float* __restrict__ bb) {
    int c = threadIdx.x;
    if (c >= C) return;
    double inv = 1.0 / (double)MROWS;
    double mean = g_stat[statOff + c] * inv;
    double var  = g_stat[statOff + C + c] * inv - mean*mean;
    double sc = (double)g[c] / sqrt(var + 1e-5);
    g_scale[bnOff + c] = (float)sc;
    g_shift[bnOff + c] = (float)((double)bb[c] - mean * sc);
}

// ---- TC GEMM (3xTF32). COUT=64: X gathered from pprime (fused l0+BN0+ReLU).
//      COUT=128: X = g_zB with BN1+ReLU. Fused stats epilogue; COUT=128 adds max/min. ----
template<int COUT>
__global__ void __launch_bounds__(256) gemm_tc_kernel(const float* __restrict__ W,
                                                      const float* __restrict__ w0,
                                                      const float* __restrict__ xyz,
                                                      const float* __restrict__ newxyz) {
    constexpr int NT  = COUT / 8;
    constexpr int XST = 72;
    constexpr int WST = COUT + 8;
    constexpr int statOff = (COUT == 64) ? 128 : 256;
    extern __shared__ float sm[];
    float*    Xs  = sm;                               // [128][72]
    unsigned* Whi = (unsigned*)(sm + 128*XST);
    unsigned* Wlo = Whi + 64*WST;
    float*    aux = (float*)(Wlo + 64*WST);           // gather tables (COUT==64): wx,wy,wz,bsc,bsh
    int t = threadIdx.x;
    size_t row0 = (size_t)blockIdx.x * 128;

    // W load + hi/lo split
    for (int i = t; i < COUT*64; i += 256) {
        int o = i >> 6, c = i & 63;
        float wv = W[i];
        unsigned hi = f2tf32(wv);
        float lo = wv - __uint_as_float(hi);
        Whi[c*WST + o] = hi;
        Wlo[c*WST + o] = f2tf32(lo);
    }

    if (COUT == 64) {
        float* wxs = aux; float* wys = aux+64; float* wzs = aux+128;
        float* bsc = aux+192; float* bsh = aux+256;
        if (t < 64) {
            wxs[t] = w0[t*67]; wys[t] = w0[t*67+1]; wzs[t] = w0[t*67+2];
            bsc[t] = g_scale[t]; bsh[t] = g_shift[t];
        }
        __syncthreads();
        // gather-build X tile: 2 threads per row, 32 channels each
        int r = t >> 1, half = t & 1;
        size_t row = row0 + r;
        int g = g_gidx[row];
        int ss = (int)((row >> 5) & 1023), b = (int)(row >> 15);
        const float* nc = newxyz + ((size_t)b*NS + ss)*3;
        const float* pt = xyz + ((size_t)b*NPT + g)*3;
        float gx = pt[0]-nc[0], gy = pt[1]-nc[1], gz = pt[2]-nc[2];
        const float4* pr = (const float4*)(g_pprime + ((size_t)b*NPT + g)*64 + half*32);
        float* xd = Xs + (size_t)r*XST + half*32;
        #pragma unroll
        for (int qq = 0; qq < 8; qq++) {
            float4 v = pr[qq]; int c = half*32 + qq*4;
            float z0 = fmaf(wxs[c  ], gx, fmaf(wys[c  ], gy, fmaf(wzs[c  ], gz, v.x)));
            float z1 = fmaf(wxs[c+1], gx, fmaf(wys[c+1], gy, fmaf(wzs[c+1], gz, v.y)));
            float z2 = fmaf(wxs[c+2], gx, fmaf(wys[c+2], gy, fmaf(wzs[c+2], gz, v.z)));
            float z3 = fmaf(wxs[c+3], gx, fmaf(wys[c+3], gy, fmaf(wzs[c+3], gz, v.w)));
            xd[qq*4+0] = fmaxf(fmaf(z0, bsc[c  ], bsh[c  ]), 0.f);
            xd[qq*4+1] = fmaxf(fmaf(z1, bsc[c+1], bsh[c+1]), 0.f);
            xd[qq*4+2] = fmaxf(fmaf(z2, bsc[c+2], bsh[c+2]), 0.f);
            xd[qq*4+3] = fmaxf(fmaf(z3, bsc[c+3], bsh[c+3]), 0.f);
        }
    } else {
        int c0 = (t*4) & 63;
        float s0=g_scale[64+c0], s1=g_scale[64+c0+1], s2=g_scale[64+c0+2], s3=g_scale[64+c0+3];
        float h0=g_shift[64+c0], h1=g_shift[64+c0+1], h2=g_shift[64+c0+2], h3=g_shift[64+c0+3];
        #pragma unroll
        for (int j = 0; j < 8; j++) {
            int e = t*4 + j*1024;
            float4 v = *(const float4*)(g_zB + row0*64 + e);
            int r = e >> 6;
            float* xd = Xs + (size_t)r*XST + c0;
            xd[0] = fmaxf(fmaf(v.x, s0, h0), 0.f);
            xd[1] = fmaxf(fmaf(v.y, s1, h1), 0.f);
            xd[2] = fmaxf(fmaf(v.z, s2, h2), 0.f);
            xd[3] = fmaxf(fmaf(v.w, s3, h3), 0.f);
        }
    }
    __syncthreads();

    int w = t >> 5, lane = t & 31;
    int g = lane >> 2, tig = lane & 3;
    int r0 = w*16 + g;

    float acc[NT][4];
    #pragma unroll
    for (int nt = 0; nt < NT; nt++) { acc[nt][0]=0.f; acc[nt][1]=0.f; acc[nt][2]=0.f; acc[nt][3]=0.f; }

    #pragma unroll
    for (int kt = 0; kt < 8; kt++) {
        const float* xa = Xs + (size_t)r0*XST + kt*8 + tig;
        float af0 = xa[0], af1 = xa[8*XST], af2 = xa[4], af3 = xa[8*XST + 4];
        unsigned ahi[4], alo[4];
        ahi[0]=f2tf32(af0); alo[0]=f2tf32(af0-__uint_as_float(ahi[0]));
        ahi[1]=f2tf32(af1); alo[1]=f2tf32(af1-__uint_as_float(ahi[1]));
        ahi[2]=f2tf32(af2); alo[2]=f2tf32(af2-__uint_as_float(ahi[2]));
        ahi[3]=f2tf32(af3); alo[3]=f2tf32(af3-__uint_as_float(ahi[3]));
        const unsigned* wh = Whi + (size_t)(kt*8+tig)*WST + g;
        const unsigned* wl = Wlo + (size_t)(kt*8+tig)*WST + g;
        #pragma unroll
        for (int nt = 0; nt < NT; nt++) {
            unsigned bh[2] = { wh[nt*8], wh[nt*8 + 4*WST] };
            unsigned bl[2] = { wl[nt*8], wl[nt*8 + 4*WST] };
            mma_tf32(acc[nt], ahi, bl);
            mma_tf32(acc[nt], alo, bh);
            mma_tf32(acc[nt], ahi, bh);
        }
    }
    if (COUT == 64) {
        float* yr = g_zB + (row0 + r0)*(size_t)64 + 2*tig;
        #pragma unroll
        for (int nt = 0; nt < NT; nt++) {
            *(float2*)(yr + nt*8)          = make_float2(acc[nt][0], acc[nt][1]);
            *(float2*)(yr + 8*64 + nt*8)   = make_float2(acc[nt][2], acc[nt][3]);
        }
    }

    // ---- fused epilogue: stats (+ group max/min for COUT==128) ----
    __syncthreads();
    float* ssum = sm;
    float* ssq  = sm + COUT;
    float* wmax = sm + 2*COUT;       // [8][COUT]
    float* wmin = wmax + 8*COUT;
    if (t < 2*COUT) sm[t] = 0.f;
    __syncthreads();

    #pragma unroll
    for (int nt = 0; nt < NT; nt++) {
        int c0 = nt*8 + 2*tig;
        float a0 = acc[nt][0], a1 = acc[nt][1], a2 = acc[nt][2], a3 = acc[nt][3];
        float sc0 = a0 + a2, sc1 = a1 + a3;
        float qc0 = a0*a0 + a2*a2, qc1 = a1*a1 + a3*a3;
        #pragma unroll
        for (int off = 4; off <= 16; off <<= 1) {
            sc0 += __shfl_xor_sync(0xffffffffu, sc0, off);
            sc1 += __shfl_xor_sync(0xffffffffu, sc1, off);
            qc0 += __shfl_xor_sync(0xffffffffu, qc0, off);
            qc1 += __shfl_xor_sync(0xffffffffu, qc1, off);
        }
        if (g == 0) {
            atomicAdd(&ssum[c0],   sc0); atomicAdd(&ssum[c0+1], sc1);
            atomicAdd(&ssq[c0],    qc0); atomicAdd(&ssq[c0+1],  qc1);
        }
        if (COUT == 128) {
            float m0 = fmaxf(a0, a2), m1 = fmaxf(a1, a3);
            float n0 = fminf(a0, a2), n1 = fminf(a1, a3);
            #pragma unroll
            for (int off = 4; off <= 16; off <<= 1) {
                m0 = fmaxf(m0, __shfl_xor_sync(0xffffffffu, m0, off));
                m1 = fmaxf(m1, __shfl_xor_sync(0xffffffffu, m1, off));
                n0 = fminf(n0, __shfl_xor_sync(0xffffffffu, n0, off));
                n1 = fminf(n1, __shfl_xor_sync(0xffffffffu, n1, off));
            }
            if (g == 0) {
                wmax[w*COUT + c0] = m0; wmax[w*COUT + c0+1] = m1;
                wmin[w*COUT + c0] = n0; wmin[w*COUT + c0+1] = n1;
            }
        }
    }
    __syncthreads();
    if (COUT == 128) {
        size_t grp0 = (size_t)blockIdx.x * 4;
        for (int i = t; i < 4*128; i += 256) {
            int gr = i >> 7, c = i & 127;
            float mx = fmaxf(wmax[(2*gr)*128 + c], wmax[(2*gr+1)*128 + c]);
            float mn = fminf(wmin[(2*gr)*128 + c], wmin[(2*gr+1)*128 + c]);
            g_gmax[(grp0 + gr)*128 + c] = mx;
            g_gmin[(grp0 + gr)*128 + c] = mn;
        }
    }
    if (t < COUT) {
        atomicAdd(&g_stat[statOff + t],        (double)ssum[t]);
        atomicAdd(&g_stat[statOff + COUT + t], (double)ssq[t]);
    }
}

// ---- final output: BN2+ReLU+max via per-group extrema ----
__global__ void output_kernel(float* __restrict__ out) {
    int o = threadIdx.x;
    size_t bs = blockIdx.x;
    float sc = g_scale[128 + o], sh = g_shift[128 + o];
    float mx = g_gmax[bs*128 + o], mn = g_gmin[bs*128 + o];
    float v = (sc > 0.f) ? fmaf(sc, mx, sh) : fmaf(sc, mn, sh);
    int b = (int)(bs >> 10), s = (int)(bs & 1023);
    out[(size_t)NB*NS*3 + ((size_t)b*128 + o)*NS + s] = fmaxf(v, 0.f);
}

extern "C" void kernel_launch(void* const* d_in, const int* in_sizes, int n_in,
                              void* d_out, int out_size) {
    const float* xyz    = (const float*)d_in[0];
    const float* points = (const float*)d_in[1];
    const float* w0 = (const float*)d_in[2];
    const float* g0 = (const float*)d_in[3];
    const float* b0 = (const float*)d_in[4];
    const float* w1 = (const float*)d_in[5];
    const float* g1 = (const float*)d_in[6];
    const float* b1 = (const float*)d_in[7];
    const float* w2 = (const float*)d_in[8];
    const float* g2 = (const float*)d_in[9];
    const float* b2 = (const float*)d_in[10];
    float* out = (float*)d_out;

    const int FPS_SMEM  = 3*NPT*4 + 64*4;
    const int G64_SMEM  = 128*72*4 + 2*64*72*4 + 320*4;
    const int G128_SMEM = 128*72*4 + 2*64*136*4;
    cudaFuncSetAttribute(fps_kernel, cudaFuncAttributeMaxDynamicSharedMemorySize, FPS_SMEM);
    cudaFuncSetAttribute(gemm_tc_kernel<64>,  cudaFuncAttributeMaxDynamicSharedMemorySize, G64_SMEM);
    cudaFuncSetAttribute(gemm_tc_kernel<128>, cudaFuncAttributeMaxDynamicSharedMemorySize, G128_SMEM);

    zero_kernel<<<1, 512>>>();
    fps_kernel<<<NB, FTH, FPS_SMEM>>>(xyz, out);
    pprime_kernel<<<dim3(NPT/128, NB), 256>>>(points, w0);
    bq_kernel<<<dim3(NS/32, NB), 256>>>(xyz, out);
    stats0g_kernel<<<512, 256>>>(xyz, w0, out);
    finalize_kernel<<<1, 128>>>(64, 0, 0, g0, b0);
    gemm_tc_kernel<64><<<MROWS/128, 256, G64_SMEM>>>(w1, w0, xyz, out);
    finalize_kernel<<<1, 128>>>(64, 128, 64, g1, b1);
    gemm_tc_kernel<128><<<MROWS/128, 256, G128_SMEM>>>(w2, nullptr, nullptr, nullptr);
    finalize_kernel<<<1, 128>>>(128, 256, 128, g2, b2);
    output_kernel<<<NB*NS, 128>>>(out);
    (void)in_sizes; (void)n_in; (void)out_size;
}

// round 8
// speedup vs baseline: 2.2152x; 1.0018x over previous
#include <cuda_runtime.h>
#include <cstddef>

#define NB 16
#define NPT 4096
#define NS 1024
#define NK 32
#define MROWS (NB*NS*NK)
#define FTH 512

__device__ __align__(16) float g_pprime[(size_t)NB*NPT*64];
__device__ int                 g_gidx[MROWS];
__device__ __align__(16) float g_zB[(size_t)MROWS*64];   // z1
__device__ __align__(16) float g_gmax[(size_t)NB*NS*128];
__device__ __align__(16) float g_gmin[(size_t)NB*NS*128];
__device__ double              g_stat[512];
__device__ float               g_scale[320];
__device__ float               g_shift[320];
__device__ int                 g_fpsflag[NB];
__device__ int                 g_bqcnt[NB];
__device__ int                 g_ppcnt[NB];

__device__ __forceinline__ unsigned long long pk(float lo, float hi) {
    unsigned long long r;
    asm("mov.b64 %0, {%1,%2};" : "=l"(r) : "f"(lo), "f"(hi));
    return r;
}
__device__ __forceinline__ unsigned long long ffma2(unsigned long long a, unsigned long long b, unsigned long long c) {
    unsigned long long d;
    asm("fma.rn.f32x2 %0, %1, %2, %3;" : "=l"(d) : "l"(a), "l"(b), "l"(c));
    return d;
}
__device__ __forceinline__ unsigned long long add2(unsigned long long a, unsigned long long b) {
    unsigned long long d;
    asm("add.rn.f32x2 %0, %1, %2;" : "=l"(d) : "l"(a), "l"(b));
    return d;
}
__device__ __forceinline__ unsigned long long mul2(unsigned long long a, unsigned long long b) {
    unsigned long long d;
    asm("mul.rn.f32x2 %0, %1, %2;" : "=l"(d) : "l"(a), "l"(b));
    return d;
}
__device__ __forceinline__ void upk(unsigned long long v, float& lo, float& hi) {
    asm("mov.b64 {%0,%1}, %2;" : "=f"(lo), "=f"(hi) : "l"(v));
}
__device__ __forceinline__ unsigned redux_umax(unsigned v) {
    unsigned r;
    asm("redux.sync.max.u32 %0, %1, 0xffffffff;" : "=r"(r) : "r"(v));
    return r;
}
__device__ __forceinline__ unsigned f2tf32(float x) {
    unsigned r;
    asm("cvt.rna.tf32.f32 %0, %1;" : "=r"(r) : "f"(x));
    return r;
}
__device__ __forceinline__ void mma_tf32(float* c, const unsigned* a, const unsigned* b) {
    asm volatile("mma.sync.aligned.m16n8k8.row.col.f32.tf32.tf32.f32 "
        "{%0,%1,%2,%3}, {%4,%5,%6,%7}, {%8,%9}, {%0,%1,%2,%3};"
        : "+f"(c[0]), "+f"(c[1]), "+f"(c[2]), "+f"(c[3])
        : "r"(a[0]), "r"(a[1]), "r"(a[2]), "r"(a[3]), "r"(b[0]), "r"(b[1]));
}
__device__ __forceinline__ void spin_until(volatile int* p, int target) {
    while (*p < target) __nanosleep(64);
}

__global__ void zero_kernel() {
    int t = threadIdx.x;
    if (t < 512) g_stat[t] = 0.0;
    if (t < NB) { g_fpsflag[t] = 0; g_bqcnt[t] = 0; g_ppcnt[t] = 0; }
}

// =================== mega front kernel ===================
// blocks [0,16)      : fps(b)                 -> g_fpsflag[b]=1
// blocks [16,528)    : pprime (b, n0)         -> g_ppcnt[b]++
// blocks [528,1040)  : bq (b, sb) wait fps    -> g_bqcnt[b]++
// blocks [1040,1552) : stats0 (b, sb) wait bq==32 && pp==32
__global__ void __launch_bounds__(FTH) front_kernel(const float* __restrict__ xyz,
                                                    const float* __restrict__ points,
                                                    const float* __restrict__ w0,
                                                    float* __restrict__ out_newxyz) {
    extern __shared__ float dsm[];
    int bid = blockIdx.x;
    int t = threadIdx.x;

    if (bid < 16) {
        // ---------------- FPS ----------------
        int b = bid;
        float* sx = dsm; float* sy = dsm + NPT; float* sz = dsm + 2*NPT;
        unsigned* swhi = (unsigned*)(dsm + 3*NPT);   // [2][16]
        unsigned* swlo = swhi + 32;
        int w = t >> 5, lane = t & 31;
        const float* p = xyz + (size_t)b*NPT*3;
        for (int i = t; i < NPT; i += FTH) { sx[i]=p[3*i]; sy[i]=p[3*i+1]; sz[i]=p[3*i+2]; }
        __syncthreads();
        unsigned long long pxp[4], pyp[4], pzp[4];
        float dist[8];
        const float INF = __int_as_float(0x7f800000);
        #pragma unroll
        for (int j = 0; j < 4; j++) {
            int p0 = t + (2*j)*FTH, p1 = t + (2*j+1)*FTH;
            pxp[j] = pk(sx[p0], sx[p1]);
            pyp[j] = pk(sy[p0], sy[p1]);
            pzp[j] = pk(sz[p0], sz[p1]);
            dist[2*j] = INF; dist[2*j+1] = INF;
        }
        int far = 0;
        for (int it = 0; it < NS; it++) {
            if (t == 0) {
                size_t o = ((size_t)b*NS + it)*3;
                out_newxyz[o] = sx[far]; out_newxyz[o+1] = sy[far]; out_newxyz[o+2] = sz[far];
            }
            if (it == NS-1) break;
            float cx = sx[far], cy = sy[far], cz = sz[far];
            unsigned long long ncx = pk(-cx,-cx), ncy = pk(-cy,-cy), ncz = pk(-cz,-cz);
            #pragma unroll
            for (int j = 0; j < 4; j++) {
                unsigned long long dx = add2(pxp[j], ncx);
                unsigned long long dy = add2(pyp[j], ncy);
                unsigned long long dz = add2(pzp[j], ncz);
                unsigned long long d2 = add2(add2(mul2(dx,dx), mul2(dy,dy)), mul2(dz,dz));
                float d0, d1; upk(d2, d0, d1);
                dist[2*j]   = fminf(dist[2*j],   d0);
                dist[2*j+1] = fminf(dist[2*j+1], d1);
            }
            float m0 = fmaxf(dist[0], dist[1]), m1 = fmaxf(dist[2], dist[3]);
            float m2 = fmaxf(dist[4], dist[5]), m3 = fmaxf(dist[6], dist[7]);
            float best = fmaxf(fmaxf(m0, m1), fmaxf(m2, m3));
            unsigned inv = 0u;
            #pragma unroll
            for (int k = 0; k < 8; k++) {
                unsigned cand = 0xFFFFFFFFu - (unsigned)(t + k*FTH);
                if (dist[k] == best && cand > inv) inv = cand;
            }
            unsigned hi  = __float_as_uint(best);
            unsigned whi = redux_umax(hi);
            unsigned lo  = (hi == whi) ? inv : 0u;
            unsigned wlo = redux_umax(lo);
            int buf = (it & 1) << 4;
            if (lane == 0) { swhi[buf + w] = whi; swlo[buf + w] = wlo; }
            __syncthreads();
            unsigned h2 = swhi[buf + (lane & 15)];
            unsigned l2 = swlo[buf + (lane & 15)];
            unsigned mh = redux_umax(h2);
            unsigned ml = redux_umax((h2 == mh) ? l2 : 0u);
            far = (int)(0xFFFFFFFFu - ml);
        }
        if (t == 0) { __threadfence(); atomicExch(&g_fpsflag[b], 1); }

    } else if (bid < 528) {
        // ---------------- pprime (512 threads) ----------------
        int idx = bid - 16;
        int b = idx >> 5, n0 = (idx & 31) * 128;
        float* Pts = dsm;                 // [64][128]
        float* Wt  = dsm + 64*128;        // [64][64]
        for (int i = t; i < 64*64; i += FTH) { int o = i>>6, c = i&63; Wt[c*64 + o] = w0[o*67 + 3 + c]; }
        const float* pb = points + (size_t)b*64*NPT;
        for (int i = t; i < 64*128/4; i += FTH) {
            int e = i*4, c = e>>7, n = e&127;
            *(float4*)&Pts[c*128 + n] = *(const float4*)(pb + (size_t)c*NPT + n0 + n);
        }
        __syncthreads();
        int cg = t & 15, rg = t >> 4;     // cg 0..15, rg 0..31
        unsigned long long acc[4][2];
        #pragma unroll
        for (int i = 0; i < 4; i++) { acc[i][0]=0ull; acc[i][1]=0ull; }
        #pragma unroll 4
        for (int c = 0; c < 64; c++) {
            ulonglong2 wv = *(const ulonglong2*)&Wt[c*64 + cg*4];
            #pragma unroll
            for (int i = 0; i < 4; i++) {
                float a = Pts[c*128 + rg*4 + i];
                unsigned long long aa = pk(a, a);
                acc[i][0] = ffma2(aa, wv.x, acc[i][0]);
                acc[i][1] = ffma2(aa, wv.y, acc[i][1]);
            }
        }
        float* outp = g_pprime + ((size_t)b*NPT + n0)*64;
        #pragma unroll
        for (int i = 0; i < 4; i++) {
            float4 v; upk(acc[i][0], v.x, v.y); upk(acc[i][1], v.z, v.w);
            *(float4*)(outp + (size_t)(rg*4+i)*64 + cg*4) = v;
        }
        __threadfence();
        __syncthreads();
        if (t == 0) atomicAdd(&g_ppcnt[b], 1);

    } else if (bid < 1040) {
        // ---------------- ball query (512 threads, 16 warps x 2 queries) ----------------
        int idx = bid - 528;
        int b = idx >> 5, sb = idx & 31;
        float* sx = dsm; float* sy = dsm + NPT; float* sz = dsm + 2*NPT; float* spp = dsm + 3*NPT;
        int w = t>>5, lane = t&31;
        const float* p = xyz + (size_t)b*NPT*3;
        for (int i = t; i < NPT; i += FTH) {
            float px = p[3*i], py = p[3*i+1], pz = p[3*i+2];
            sx[i]=px; sy[i]=py; sz[i]=pz;
            spp[i] = __fadd_rn(__fadd_rn(__fmul_rn(px,px), __fmul_rn(py,py)), __fmul_rn(pz,pz));
        }
        if (t == 0) { spin_until(&g_fpsflag[b], 1); __threadfence(); }
        __syncthreads();
        const float* newxyz = out_newxyz;
        for (int q = 0; q < 2; q++) {
            int s = sb*32 + w*2 + q;
            const float* nc = newxyz + ((size_t)b*NS + s)*3;
            float cx = nc[0], cy = nc[1], cz = nc[2];
            float cc = __fadd_rn(__fadd_rn(__fmul_rn(cx,cx), __fmul_rn(cy,cy)), __fmul_rn(cz,cz));
            int count = 0, first = 0;
            int* go = g_gidx + ((size_t)b*NS + s)*NK;
            for (int base = 0; base < NPT && count < NK; base += 32) {
                int pi = base + lane;
                float px = sx[pi], py = sy[pi], pz = sz[pi];
                float pp  = spp[pi];
                float dot = __fadd_rn(__fadd_rn(__fmul_rn(cx,px), __fmul_rn(cy,py)), __fmul_rn(cz,pz));
                float sqr = __fadd_rn(__fadd_rn(cc, pp), -__fmul_rn(2.0f, dot));
                bool in = (sqr <= 0.04f);
                unsigned mask = __ballot_sync(0xffffffffu, in);
                if (count == 0 && mask) first = base + __ffs(mask) - 1;
                if (in) {
                    int pos = count + __popc(mask & ((1u << lane) - 1u));
                    if (pos < NK) go[pos] = pi;
                }
                count += __popc(mask);
            }
            if (count < NK && lane >= count) go[lane] = first;
        }
        __threadfence();
        __syncthreads();
        if (t == 0) atomicAdd(&g_bqcnt[b], 1);

    } else {
        // ---------------- layer-0 stats from gather (512 threads, 8 row-lanes) ----------------
        int idx = bid - 1040;
        int b = idx >> 5, sb = idx & 31;
        float* wx = dsm; float* wy = dsm + 64; float* wz = dsm + 128;
        float* ssum = dsm + 192;          // [8][64]
        float* ssq  = dsm + 192 + 512;    // [8][64]
        if (t < 64) { wx[t]=w0[t*67]; wy[t]=w0[t*67+1]; wz[t]=w0[t*67+2]; }
        if (t == 0) {
            spin_until(&g_bqcnt[b], 32);
            spin_until(&g_ppcnt[b], 32);
            __threadfence();
        }
        __syncthreads();
        int c = t & 63, rl = t >> 6;
        float wxc = wx[c], wyc = wy[c], wzc = wz[c];
        float s = 0.f, q = 0.f;
        size_t base = (size_t)b * (MROWS/NB) + (size_t)sb * 1024;
        const float* newxyz = out_newxyz;
        for (int i = 0; i < 128; i++) {
            size_t row = base + i*8 + rl;
            int g = g_gidx[row];
            int ss = (int)((row >> 5) & 1023);
            const float* nc = newxyz + ((size_t)b*NS + ss)*3;
            const float* pt = xyz + ((size_t)b*NPT + g)*3;
            float gx = pt[0]-nc[0], gy = pt[1]-nc[1], gz = pt[2]-nc[2];
            float v = g_pprime[((size_t)b*NPT + g)*64 + c];
            v = fmaf(wxc, gx, fmaf(wyc, gy, fmaf(wzc, gz, v)));
            s += v; q = fmaf(v, v, q);
        }
        ssum[rl*64 + c] = s; ssq[rl*64 + c] = q;
        __syncthreads();
        if (t < 64) {
            double S = 0.0, Q = 0.0;
            #pragma unroll
            for (int r = 0; r < 8; r++) { S += (double)ssum[r*64 + t]; Q += (double)ssq[r*64 + t]; }
            atomicAdd(&g_stat[t], S);
            atomicAdd(&g_stat[64 + t], Q);
        }
    }
}

__global__ void finalize_kernel(int C, int statOff, int bnOff,
                                const float* __restrict__ g, const float* __restrict__ bb) {
    int c = threadIdx.x;
    if (c >= C) return;
    double inv = 1.0 / (double)MROWS;
    double mean = g_stat[statOff + c] * inv;
    double var  = g_stat[statOff + C + c] * inv - mean*mean;
    double sc = (double)g[c] / sqrt(var + 1e-5);
    g_scale[bnOff + c] = (float)sc;
    g_shift[bnOff + c] = (float)((double)bb[c] - mean * sc);
}

// ---- TC GEMM (3xTF32). COUT=64: X gathered from pprime (fused l0+BN0+ReLU).
//      COUT=128: X = g_zB with BN1+ReLU. Fused stats epilogue; COUT=128 adds max/min. ----
template<int COUT>
__global__ void __launch_bounds__(256) gemm_tc_kernel(const float* __restrict__ W,
                                                      const float* __restrict__ w0,
                                                      const float* __restrict__ xyz,
                                                      const float* __restrict__ newxyz) {
    constexpr int NT  = COUT / 8;
    constexpr int XST = 72;
    constexpr int WST = COUT + 8;
    constexpr int statOff = (COUT == 64) ? 128 : 256;
    extern __shared__ float sm[];
    float*    Xs  = sm;                               // [128][72]
    unsigned* Whi = (unsigned*)(sm + 128*XST);
    unsigned* Wlo = Whi + 64*WST;
    float*    aux = (float*)(Wlo + 64*WST);
    int t = threadIdx.x;
    size_t row0 = (size_t)blockIdx.x * 128;

    for (int i = t; i < COUT*64; i += 256) {
        int o = i >> 6, c = i & 63;
        float wv = W[i];
        unsigned hi = f2tf32(wv);
        float lo = wv - __uint_as_float(hi);
        Whi[c*WST + o] = hi;
        Wlo[c*WST + o] = f2tf32(lo);
    }

    if (COUT == 64) {
        float* wxs = aux; float* wys = aux+64; float* wzs = aux+128;
        float* bsc = aux+192; float* bsh = aux+256;
        if (t < 64) {
            wxs[t] = w0[t*67]; wys[t] = w0[t*67+1]; wzs[t] = w0[t*67+2];
            bsc[t] = g_scale[t]; bsh[t] = g_shift[t];
        }
        __syncthreads();
        int r = t >> 1, half = t & 1;
        size_t row = row0 + r;
        int g = g_gidx[row];
        int ss = (int)((row >> 5) & 1023), b = (int)(row >> 15);
        const float* nc = newxyz + ((size_t)b*NS + ss)*3;
        const float* pt = xyz + ((size_t)b*NPT + g)*3;
        float gx = pt[0]-nc[0], gy = pt[1]-nc[1], gz = pt[2]-nc[2];
        const float4* pr = (const float4*)(g_pprime + ((size_t)b*NPT + g)*64 + half*32);
        float* xd = Xs + (size_t)r*XST + half*32;
        #pragma unroll
        for (int qq = 0; qq < 8; qq++) {
            float4 v = pr[qq]; int c = half*32 + qq*4;
            float z0 = fmaf(wxs[c  ], gx, fmaf(wys[c  ], gy, fmaf(wzs[c  ], gz, v.x)));
            float z1 = fmaf(wxs[c+1], gx, fmaf(wys[c+1], gy, fmaf(wzs[c+1], gz, v.y)));
            float z2 = fmaf(wxs[c+2], gx, fmaf(wys[c+2], gy, fmaf(wzs[c+2], gz, v.z)));
            float z3 = fmaf(wxs[c+3], gx, fmaf(wys[c+3], gy, fmaf(wzs[c+3], gz, v.w)));
            xd[qq*4+0] = fmaxf(fmaf(z0, bsc[c  ], bsh[c  ]), 0.f);
            xd[qq*4+1] = fmaxf(fmaf(z1, bsc[c+1], bsh[c+1]), 0.f);
            xd[qq*4+2] = fmaxf(fmaf(z2, bsc[c+2], bsh[c+2]), 0.f);
            xd[qq*4+3] = fmaxf(fmaf(z3, bsc[c+3], bsh[c+3]), 0.f);
        }
    } else {
        int c0 = (t*4) & 63;
        float s0=g_scale[64+c0], s1=g_scale[64+c0+1], s2=g_scale[64+c0+2], s3=g_scale[64+c0+3];
        float h0=g_shift[64+c0], h1=g_shift[64+c0+1], h2=g_shift[64+c0+2], h3=g_shift[64+c0+3];
        #pragma unroll
        for (int j = 0; j < 8; j++) {
            int e = t*4 + j*1024;
            float4 v = *(const float4*)(g_zB + row0*64 + e);
            int r = e >> 6;
            float* xd = Xs + (size_t)r*XST + c0;
            xd[0] = fmaxf(fmaf(v.x, s0, h0), 0.f);
            xd[1] = fmaxf(fmaf(v.y, s1, h1), 0.f);
            xd[2] = fmaxf(fmaf(v.z, s2, h2), 0.f);
            xd[3] = fmaxf(fmaf(v.w, s3, h3), 0.f);
        }
    }
    __syncthreads();

    int w = t >> 5, lane = t & 31;
    int g = lane >> 2, tig = lane & 3;
    int r0 = w*16 + g;

    float acc[NT][4];
    #pragma unroll
    for (int nt = 0; nt < NT; nt++) { acc[nt][0]=0.f; acc[nt][1]=0.f; acc[nt][2]=0.f; acc[nt][3]=0.f; }

    #pragma unroll
    for (int kt = 0; kt < 8; kt++) {
        const float* xa = Xs + (size_t)r0*XST + kt*8 + tig;
        float af0 = xa[0], af1 = xa[8*XST], af2 = xa[4], af3 = xa[8*XST + 4];
        unsigned ahi[4], alo[4];
        ahi[0]=f2tf32(af0); alo[0]=f2tf32(af0-__uint_as_float(ahi[0]));
        ahi[1]=f2tf32(af1); alo[1]=f2tf32(af1-__uint_as_float(ahi[1]));
        ahi[2]=f2tf32(af2); alo[2]=f2tf32(af2-__uint_as_float(ahi[2]));
        ahi[3]=f2tf32(af3); alo[3]=f2tf32(af3-__uint_as_float(ahi[3]));
        const unsigned* wh = Whi + (size_t)(kt*8+tig)*WST + g;
        const unsigned* wl = Wlo + (size_t)(kt*8+tig)*WST + g;
        #pragma unroll
        for (int nt = 0; nt < NT; nt++) {
            unsigned bh[2] = { wh[nt*8], wh[nt*8 + 4*WST] };
            unsigned bl[2] = { wl[nt*8], wl[nt*8 + 4*WST] };
            mma_tf32(acc[nt], ahi, bl);
            mma_tf32(acc[nt], alo, bh);
            mma_tf32(acc[nt], ahi, bh);
        }
    }
    if (COUT == 64) {
        float* yr = g_zB + (row0 + r0)*(size_t)64 + 2*tig;
        #pragma unroll
        for (int nt = 0; nt < NT; nt++) {
            *(float2*)(yr + nt*8)          = make_float2(acc[nt][0], acc[nt][1]);
            *(float2*)(yr + 8*64 + nt*8)   = make_float2(acc[nt][2], acc[nt][3]);
        }
    }

    __syncthreads();
    float* ssum = sm;
    float* ssq  = sm + COUT;
    float* wmax = sm + 2*COUT;
    float* wmin = wmax + 8*COUT;
    if (t < 2*COUT) sm[t] = 0.f;
    __syncthreads();

    #pragma unroll
    for (int nt = 0; nt < NT; nt++) {
        int c0 = nt*8 + 2*tig;
        float a0 = acc[nt][0], a1 = acc[nt][1], a2 = acc[nt][2], a3 = acc[nt][3];
        float sc0 = a0 + a2, sc1 = a1 + a3;
        float qc0 = a0*a0 + a2*a2, qc1 = a1*a1 + a3*a3;
        #pragma unroll
        for (int off = 4; off <= 16; off <<= 1) {
            sc0 += __shfl_xor_sync(0xffffffffu, sc0, off);
            sc1 += __shfl_xor_sync(0xffffffffu, sc1, off);
            qc0 += __shfl_xor_sync(0xffffffffu, qc0, off);
            qc1 += __shfl_xor_sync(0xffffffffu, qc1, off);
        }
        if (g == 0) {
            atomicAdd(&ssum[c0],   sc0); atomicAdd(&ssum[c0+1], sc1);
            atomicAdd(&ssq[c0],    qc0); atomicAdd(&ssq[c0+1],  qc1);
        }
        if (COUT == 128) {
            float m0 = fmaxf(a0, a2), m1 = fmaxf(a1, a3);
            float n0 = fminf(a0, a2), n1 = fminf(a1, a3);
            #pragma unroll
            for (int off = 4; off <= 16; off <<= 1) {
                m0 = fmaxf(m0, __shfl_xor_sync(0xffffffffu, m0, off));
                m1 = fmaxf(m1, __shfl_xor_sync(0xffffffffu, m1, off));
                n0 = fminf(n0, __shfl_xor_sync(0xffffffffu, n0, off));
                n1 = fminf(n1, __shfl_xor_sync(0xffffffffu, n1, off));
            }
            if (g == 0) {
                wmax[w*COUT + c0] = m0; wmax[w*COUT + c0+1] = m1;
                wmin[w*COUT + c0] = n0; wmin[w*COUT + c0+1] = n1;
            }
        }
    }
    __syncthreads();
    if (COUT == 128) {
        size_t grp0 = (size_t)blockIdx.x * 4;
        for (int i = t; i < 4*128; i += 256) {
            int gr = i >> 7, c = i & 127;
            float mx = fmaxf(wmax[(2*gr)*128 + c], wmax[(2*gr+1)*128 + c]);
            float mn = fminf(wmin[(2*gr)*128 + c], wmin[(2*gr+1)*128 + c]);
            g_gmax[(grp0 + gr)*128 + c] = mx;
            g_gmin[(grp0 + gr)*128 + c] = mn;
        }
    }
    if (t < COUT) {
        atomicAdd(&g_stat[statOff + t],        (double)ssum[t]);
        atomicAdd(&g_stat[statOff + COUT + t], (double)ssq[t]);
    }
}

// ---- final output: BN2+ReLU+max via per-group extrema ----
__global__ void output_kernel(float* __restrict__ out) {
    int o = threadIdx.x;
    size_t bs = blockIdx.x;
    float sc = g_scale[128 + o], sh = g_shift[128 + o];
    float mx = g_gmax[bs*128 + o], mn = g_gmin[bs*128 + o];
    float v = (sc > 0.f) ? fmaf(sc, mx, sh) : fmaf(sc, mn, sh);
    int b = (int)(bs >> 10), s = (int)(bs & 1023);
    out[(size_t)NB*NS*3 + ((size_t)b*128 + o)*NS + s] = fmaxf(v, 0.f);
}

extern "C" void kernel_launch(void* const* d_in, const int* in_sizes, int n_in,
                              void* d_out, int out_size) {
    const float* xyz    = (const float*)d_in[0];
    const float* points = (const float*)d_in[1];
    const float* w0 = (const float*)d_in[2];
    const float* g0 = (const float*)d_in[3];
    const float* b0 = (const float*)d_in[4];
    const float* w1 = (const float*)d_in[5];
    const float* g1 = (const float*)d_in[6];
    const float* b1 = (const float*)d_in[7];
    const float* w2 = (const float*)d_in[8];
    const float* g2 = (const float*)d_in[9];
    const float* b2 = (const float*)d_in[10];
    float* out = (float*)d_out;

    const int FRONT_SMEM = 4*NPT*4;                    // 65536 (bq role is the max)
    const int G64_SMEM   = 128*72*4 + 2*64*72*4 + 320*4;
    const int G128_SMEM  = 128*72*4 + 2*64*136*4;
    cudaFuncSetAttribute(front_kernel, cudaFuncAttributeMaxDynamicSharedMemorySize, FRONT_SMEM);
    cudaFuncSetAttribute(gemm_tc_kernel<64>,  cudaFuncAttributeMaxDynamicSharedMemorySize, G64_SMEM);
    cudaFuncSetAttribute(gemm_tc_kernel<128>, cudaFuncAttributeMaxDynamicSharedMemorySize, G128_SMEM);

    zero_kernel<<<1, 512>>>();
    front_kernel<<<1552, FTH, FRONT_SMEM>>>(xyz, points, w0, out);
    finalize_kernel<<<1, 128>>>(64, 0, 0, g0, b0);
    gemm_tc_kernel<64><<<MROWS/128, 256, G64_SMEM>>>(w1, w0, xyz, out);
    finalize_kernel<<<1, 128>>>(64, 128, 64, g1, b1);
    gemm_tc_kernel<128><<<MROWS/128, 256, G128_SMEM>>>(w2, nullptr, nullptr, nullptr);
    finalize_kernel<<<1, 128>>>(128, 256, 128, g2, b2);
    output_kernel<<<NB*NS, 128>>>(out);
    (void)in_sizes; (void)n_in; (void)out_size;
}

// round 9
// speedup vs baseline: 2.2790x; 1.0288x over previous
#include <cuda_runtime.h>
#include <cstddef>

#define NB 16
#define NPT 4096
#define NS 1024
#define NK 32
#define MROWS (NB*NS*NK)
#define FTH 512

__device__ __align__(16) float g_pprime[(size_t)NB*NPT*64];
__device__ int                 g_gidx[MROWS];
__device__ __align__(16) float g_zB[(size_t)MROWS*64];   // z1
__device__ __align__(16) float g_gmax[(size_t)NB*NS*128];
__device__ __align__(16) float g_gmin[(size_t)NB*NS*128];
__device__ double              g_stat[512];
__device__ float               g_scale[320];
__device__ float               g_shift[320];
__device__ int                 g_fpsflag[NB];
__device__ int                 g_bqcnt[NB];
__device__ int                 g_ppcnt[NB];

__device__ __forceinline__ unsigned long long pk(float lo, float hi) {
    unsigned long long r;
    asm("mov.b64 %0, {%1,%2};" : "=l"(r) : "f"(lo), "f"(hi));
    return r;
}
__device__ __forceinline__ unsigned long long ffma2(unsigned long long a, unsigned long long b, unsigned long long c) {
    unsigned long long d;
    asm("fma.rn.f32x2 %0, %1, %2, %3;" : "=l"(d) : "l"(a), "l"(b), "l"(c));
    return d;
}
__device__ __forceinline__ unsigned long long add2(unsigned long long a, unsigned long long b) {
    unsigned long long d;
    asm("add.rn.f32x2 %0, %1, %2;" : "=l"(d) : "l"(a), "l"(b));
    return d;
}
__device__ __forceinline__ unsigned long long mul2(unsigned long long a, unsigned long long b) {
    unsigned long long d;
    asm("mul.rn.f32x2 %0, %1, %2;" : "=l"(d) : "l"(a), "l"(b));
    return d;
}
__device__ __forceinline__ void upk(unsigned long long v, float& lo, float& hi) {
    asm("mov.b64 {%0,%1}, %2;" : "=f"(lo), "=f"(hi) : "l"(v));
}
__device__ __forceinline__ unsigned redux_umax(unsigned v) {
    unsigned r;
    asm("redux.sync.max.u32 %0, %1, 0xffffffff;" : "=r"(r) : "r"(v));
    return r;
}
__device__ __forceinline__ unsigned f2tf32(float x) {
    unsigned r;
    asm("cvt.rna.tf32.f32 %0, %1;" : "=r"(r) : "f"(x));
    return r;
}
__device__ __forceinline__ void mma_tf32(float* c, const unsigned* a, const unsigned* b) {
    asm volatile("mma.sync.aligned.m16n8k8.row.col.f32.tf32.tf32.f32 "
        "{%0,%1,%2,%3}, {%4,%5,%6,%7}, {%8,%9}, {%0,%1,%2,%3};"
        : "+f"(c[0]), "+f"(c[1]), "+f"(c[2]), "+f"(c[3])
        : "r"(a[0]), "r"(a[1]), "r"(a[2]), "r"(a[3]), "r"(b[0]), "r"(b[1]));
}
__device__ __forceinline__ void spin_until(volatile int* p, int target) {
    while (*p < target) __nanosleep(64);
}

__global__ void zero_kernel() {
    int t = threadIdx.x;
    if (t < 512) g_stat[t] = 0.0;
    if (t < NB) { g_fpsflag[t] = 0; g_bqcnt[t] = 0; g_ppcnt[t] = 0; }
}

// =================== mega front kernel (unchanged from R8) ===================
__global__ void __launch_bounds__(FTH) front_kernel(const float* __restrict__ xyz,
                                                    const float* __restrict__ points,
                                                    const float* __restrict__ w0,
                                                    float* __restrict__ out_newxyz) {
    extern __shared__ float dsm[];
    int bid = blockIdx.x;
    int t = threadIdx.x;

    if (bid < 16) {
        int b = bid;
        float* sx = dsm; float* sy = dsm + NPT; float* sz = dsm + 2*NPT;
        unsigned* swhi = (unsigned*)(dsm + 3*NPT);
        unsigned* swlo = swhi + 32;
        int w = t >> 5, lane = t & 31;
        const float* p = xyz + (size_t)b*NPT*3;
        for (int i = t; i < NPT; i += FTH) { sx[i]=p[3*i]; sy[i]=p[3*i+1]; sz[i]=p[3*i+2]; }
        __syncthreads();
        unsigned long long pxp[4], pyp[4], pzp[4];
        float dist[8];
        const float INF = __int_as_float(0x7f800000);
        #pragma unroll
        for (int j = 0; j < 4; j++) {
            int p0 = t + (2*j)*FTH, p1 = t + (2*j+1)*FTH;
            pxp[j] = pk(sx[p0], sx[p1]);
            pyp[j] = pk(sy[p0], sy[p1]);
            pzp[j] = pk(sz[p0], sz[p1]);
            dist[2*j] = INF; dist[2*j+1] = INF;
        }
        int far = 0;
        for (int it = 0; it < NS; it++) {
            if (t == 0) {
                size_t o = ((size_t)b*NS + it)*3;
                out_newxyz[o] = sx[far]; out_newxyz[o+1] = sy[far]; out_newxyz[o+2] = sz[far];
            }
            if (it == NS-1) break;
            float cx = sx[far], cy = sy[far], cz = sz[far];
            unsigned long long ncx = pk(-cx,-cx), ncy = pk(-cy,-cy), ncz = pk(-cz,-cz);
            #pragma unroll
            for (int j = 0; j < 4; j++) {
                unsigned long long dx = add2(pxp[j], ncx);
                unsigned long long dy = add2(pyp[j], ncy);
                unsigned long long dz = add2(pzp[j], ncz);
                unsigned long long d2 = add2(add2(mul2(dx,dx), mul2(dy,dy)), mul2(dz,dz));
                float d0, d1; upk(d2, d0, d1);
                dist[2*j]   = fminf(dist[2*j],   d0);
                dist[2*j+1] = fminf(dist[2*j+1], d1);
            }
            float m0 = fmaxf(dist[0], dist[1]), m1 = fmaxf(dist[2], dist[3]);
            float m2 = fmaxf(dist[4], dist[5]), m3 = fmaxf(dist[6], dist[7]);
            float best = fmaxf(fmaxf(m0, m1), fmaxf(m2, m3));
            unsigned inv = 0u;
            #pragma unroll
            for (int k = 0; k < 8; k++) {
                unsigned cand = 0xFFFFFFFFu - (unsigned)(t + k*FTH);
                if (dist[k] == best && cand > inv) inv = cand;
            }
            unsigned hi  = __float_as_uint(best);
            unsigned whi = redux_umax(hi);
            unsigned lo  = (hi == whi) ? inv : 0u;
            unsigned wlo = redux_umax(lo);
            int buf = (it & 1) << 4;
            if (lane == 0) { swhi[buf + w] = whi; swlo[buf + w] = wlo; }
            __syncthreads();
            unsigned h2 = swhi[buf + (lane & 15)];
            unsigned l2 = swlo[buf + (lane & 15)];
            unsigned mh = redux_umax(h2);
            unsigned ml = redux_umax((h2 == mh) ? l2 : 0u);
            far = (int)(0xFFFFFFFFu - ml);
        }
        if (t == 0) { __threadfence(); atomicExch(&g_fpsflag[b], 1); }

    } else if (bid < 528) {
        int idx = bid - 16;
        int b = idx >> 5, n0 = (idx & 31) * 128;
        float* Pts = dsm;
        float* Wt  = dsm + 64*128;
        for (int i = t; i < 64*64; i += FTH) { int o = i>>6, c = i&63; Wt[c*64 + o] = w0[o*67 + 3 + c]; }
        const float* pb = points + (size_t)b*64*NPT;
        for (int i = t; i < 64*128/4; i += FTH) {
            int e = i*4, c = e>>7, n = e&127;
            *(float4*)&Pts[c*128 + n] = *(const float4*)(pb + (size_t)c*NPT + n0 + n);
        }
        __syncthreads();
        int cg = t & 15, rg = t >> 4;
        unsigned long long acc[4][2];
        #pragma unroll
        for (int i = 0; i < 4; i++) { acc[i][0]=0ull; acc[i][1]=0ull; }
        #pragma unroll 4
        for (int c = 0; c < 64; c++) {
            ulonglong2 wv = *(const ulonglong2*)&Wt[c*64 + cg*4];
            #pragma unroll
            for (int i = 0; i < 4; i++) {
                float a = Pts[c*128 + rg*4 + i];
                unsigned long long aa = pk(a, a);
                acc[i][0] = ffma2(aa, wv.x, acc[i][0]);
                acc[i][1] = ffma2(aa, wv.y, acc[i][1]);
            }
        }
        float* outp = g_pprime + ((size_t)b*NPT + n0)*64;
        #pragma unroll
        for (int i = 0; i < 4; i++) {
            float4 v; upk(acc[i][0], v.x, v.y); upk(acc[i][1], v.z, v.w);
            *(float4*)(outp + (size_t)(rg*4+i)*64 + cg*4) = v;
        }
        __threadfence();
        __syncthreads();
        if (t == 0) atomicAdd(&g_ppcnt[b], 1);

    } else if (bid < 1040) {
        int idx = bid - 528;
        int b = idx >> 5, sb = idx & 31;
        float* sx = dsm; float* sy = dsm + NPT; float* sz = dsm + 2*NPT; float* spp = dsm + 3*NPT;
        int w = t>>5, lane = t&31;
        const float* p = xyz + (size_t)b*NPT*3;
        for (int i = t; i < NPT; i += FTH) {
            float px = p[3*i], py = p[3*i+1], pz = p[3*i+2];
            sx[i]=px; sy[i]=py; sz[i]=pz;
            spp[i] = __fadd_rn(__fadd_rn(__fmul_rn(px,px), __fmul_rn(py,py)), __fmul_rn(pz,pz));
        }
        if (t == 0) { spin_until(&g_fpsflag[b], 1); __threadfence(); }
        __syncthreads();
        const float* newxyz = out_newxyz;
        for (int q = 0; q < 2; q++) {
            int s = sb*32 + w*2 + q;
            const float* nc = newxyz + ((size_t)b*NS + s)*3;
            float cx = nc[0], cy = nc[1], cz = nc[2];
            float cc = __fadd_rn(__fadd_rn(__fmul_rn(cx,cx), __fmul_rn(cy,cy)), __fmul_rn(cz,cz));
            int count = 0, first = 0;
            int* go = g_gidx + ((size_t)b*NS + s)*NK;
            for (int base = 0; base < NPT && count < NK; base += 32) {
                int pi = base + lane;
                float px = sx[pi], py = sy[pi], pz = sz[pi];
                float pp  = spp[pi];
                float dot = __fadd_rn(__fadd_rn(__fmul_rn(cx,px), __fmul_rn(cy,py)), __fmul_rn(cz,pz));
                float sqr = __fadd_rn(__fadd_rn(cc, pp), -__fmul_rn(2.0f, dot));
                bool in = (sqr <= 0.04f);
                unsigned mask = __ballot_sync(0xffffffffu, in);
                if (count == 0 && mask) first = base + __ffs(mask) - 1;
                if (in) {
                    int pos = count + __popc(mask & ((1u << lane) - 1u));
                    if (pos < NK) go[pos] = pi;
                }
                count += __popc(mask);
            }
            if (count < NK && lane >= count) go[lane] = first;
        }
        __threadfence();
        __syncthreads();
        if (t == 0) atomicAdd(&g_bqcnt[b], 1);

    } else {
        int idx = bid - 1040;
        int b = idx >> 5, sb = idx & 31;
        float* wx = dsm; float* wy = dsm + 64; float* wz = dsm + 128;
        float* ssum = dsm + 192;
        float* ssq  = dsm + 192 + 512;
        if (t < 64) { wx[t]=w0[t*67]; wy[t]=w0[t*67+1]; wz[t]=w0[t*67+2]; }
        if (t == 0) {
            spin_until(&g_bqcnt[b], 32);
            spin_until(&g_ppcnt[b], 32);
            __threadfence();
        }
        __syncthreads();
        int c = t & 63, rl = t >> 6;
        float wxc = wx[c], wyc = wy[c], wzc = wz[c];
        float s = 0.f, q = 0.f;
        size_t base = (size_t)b * (MROWS/NB) + (size_t)sb * 1024;
        const float* newxyz = out_newxyz;
        for (int i = 0; i < 128; i++) {
            size_t row = base + i*8 + rl;
            int g = g_gidx[row];
            int ss = (int)((row >> 5) & 1023);
            const float* nc = newxyz + ((size_t)b*NS + ss)*3;
            const float* pt = xyz + ((size_t)b*NPT + g)*3;
            float gx = pt[0]-nc[0], gy = pt[1]-nc[1], gz = pt[2]-nc[2];
            float v = g_pprime[((size_t)b*NPT + g)*64 + c];
            v = fmaf(wxc, gx, fmaf(wyc, gy, fmaf(wzc, gz, v)));
            s += v; q = fmaf(v, v, q);
        }
        ssum[rl*64 + c] = s; ssq[rl*64 + c] = q;
        __syncthreads();
        if (t < 64) {
            double S = 0.0, Q = 0.0;
            #pragma unroll
            for (int r = 0; r < 8; r++) { S += (double)ssum[r*64 + t]; Q += (double)ssq[r*64 + t]; }
            atomicAdd(&g_stat[t], S);
            atomicAdd(&g_stat[64 + t], Q);
        }
    }
}

__global__ void finalize_kernel(int C, int statOff, int bnOff,
                                const float* __restrict__ g, const float* __restrict__ bb) {
    int c = threadIdx.x;
    if (c >= C) return;
    double inv = 1.0 / (double)MROWS;
    double mean = g_stat[statOff + c] * inv;
    double var  = g_stat[statOff + C + c] * inv - mean*mean;
    double sc = (double)g[c] / sqrt(var + 1e-5);
    g_scale[bnOff + c] = (float)sc;
    g_shift[bnOff + c] = (float)((double)bb[c] - mean * sc);
}

// ---- TC GEMM v2: 128 threads, 4 warps x 32 rows (2 A-frags per warp) ----
template<int COUT>
__global__ void __launch_bounds__(128) gemm_tc_kernel(const float* __restrict__ W,
                                                      const float* __restrict__ w0,
                                                      const float* __restrict__ xyz,
                                                      const float* __restrict__ newxyz) {
    constexpr int XST = 68;                 // 4g+tig -> conflict-free A loads
    constexpr int WST = COUT + 8;           // 8tig+g -> conflict-free B loads
    constexpr int NH  = COUT / 64;
    constexpr int statOff = (COUT == 64) ? 128 : 256;
    extern __shared__ float sm[];
    float*    Xs   = sm;                              // [128][68]
    unsigned* Whi  = (unsigned*)(sm + 128*XST);       // [64][WST]
    unsigned* Wlo  = Whi + 64*WST;
    float*    sstat = (float*)(Wlo + 64*WST);         // [2*COUT]
    float*    aux  = sstat + 2*COUT;                  // COUT==64: 320 floats
    int t = threadIdx.x;
    size_t row0 = (size_t)blockIdx.x * 128;

    for (int i = t; i < COUT*64; i += 128) {
        int o = i >> 6, c = i & 63;
        float wv = W[i];
        unsigned hi = f2tf32(wv);
        Whi[c*WST + o] = hi;
        Wlo[c*WST + o] = f2tf32(wv - __uint_as_float(hi));
    }
    for (int i = t; i < 2*COUT; i += 128) sstat[i] = 0.f;

    if (COUT == 64) {
        if (t < 64) {
            aux[t]     = w0[t*67];   aux[64+t]  = w0[t*67+1]; aux[128+t] = w0[t*67+2];
            aux[192+t] = g_scale[t]; aux[256+t] = g_shift[t];
        }
        __syncthreads();
        #pragma unroll
        for (int j = 0; j < 2; j++) {
            int idx = t + j*128;
            int r = idx >> 1, half = idx & 1;
            size_t row = row0 + r;
            int g = g_gidx[row];
            int ss = (int)((row >> 5) & 1023), b = (int)(row >> 15);
            const float* nc = newxyz + ((size_t)b*NS + ss)*3;
            const float* pt = xyz + ((size_t)b*NPT + g)*3;
            float gx = pt[0]-nc[0], gy = pt[1]-nc[1], gz = pt[2]-nc[2];
            const float4* pr = (const float4*)(g_pprime + ((size_t)b*NPT + g)*64 + half*32);
            float* xd = Xs + (size_t)r*XST + half*32;
            #pragma unroll
            for (int qq = 0; qq < 8; qq++) {
                float4 v = pr[qq]; int c = half*32 + qq*4;
                float z0 = fmaf(aux[c  ], gx, fmaf(aux[64+c  ], gy, fmaf(aux[128+c  ], gz, v.x)));
                float z1 = fmaf(aux[c+1], gx, fmaf(aux[64+c+1], gy, fmaf(aux[128+c+1], gz, v.y)));
                float z2 = fmaf(aux[c+2], gx, fmaf(aux[64+c+2], gy, fmaf(aux[128+c+2], gz, v.z)));
                float z3 = fmaf(aux[c+3], gx, fmaf(aux[64+c+3], gy, fmaf(aux[128+c+3], gz, v.w)));
                float4 o4;
                o4.x = fmaxf(fmaf(z0, aux[192+c  ], aux[256+c  ]), 0.f);
                o4.y = fmaxf(fmaf(z1, aux[192+c+1], aux[256+c+1]), 0.f);
                o4.z = fmaxf(fmaf(z2, aux[192+c+2], aux[256+c+2]), 0.f);
                o4.w = fmaxf(fmaf(z3, aux[192+c+3], aux[256+c+3]), 0.f);
                *(float4*)(xd + qq*4) = o4;
            }
        }
    } else {
        int c0 = (t*4) & 63;
        float s0=g_scale[64+c0], s1=g_scale[64+c0+1], s2=g_scale[64+c0+2], s3=g_scale[64+c0+3];
        float h0=g_shift[64+c0], h1=g_shift[64+c0+1], h2=g_shift[64+c0+2], h3=g_shift[64+c0+3];
        #pragma unroll
        for (int j = 0; j < 16; j++) {
            int e = t*4 + j*512;
            float4 v = *(const float4*)(g_zB + row0*64 + e);
            int r = e >> 6;
            float4 o4;
            o4.x = fmaxf(fmaf(v.x, s0, h0), 0.f);
            o4.y = fmaxf(fmaf(v.y, s1, h1), 0.f);
            o4.z = fmaxf(fmaf(v.z, s2, h2), 0.f);
            o4.w = fmaxf(fmaf(v.w, s3, h3), 0.f);
            *(float4*)(Xs + (size_t)r*XST + c0) = o4;
        }
    }
    __syncthreads();

    int w = t >> 5, lane = t & 31;
    int g = lane >> 2, tig = lane & 3;
    int rbase = w*32 + g;

    #pragma unroll
    for (int nh = 0; nh < NH; nh++) {
        float acc0[8][4], acc1[8][4];
        #pragma unroll
        for (int nt = 0; nt < 8; nt++) {
            acc0[nt][0]=0.f; acc0[nt][1]=0.f; acc0[nt][2]=0.f; acc0[nt][3]=0.f;
            acc1[nt][0]=0.f; acc1[nt][1]=0.f; acc1[nt][2]=0.f; acc1[nt][3]=0.f;
        }
        #pragma unroll
        for (int kt = 0; kt < 8; kt++) {
            const float* xa = Xs + (size_t)rbase*XST + kt*8 + tig;
            float af0 = xa[0],        af1 = xa[8*XST],        af2 = xa[4],         af3 = xa[8*XST+4];
            float bf0 = xa[16*XST],   bf1 = xa[24*XST],       bf2 = xa[16*XST+4],  bf3 = xa[24*XST+4];
            unsigned ah0[4], al0[4], ah1[4], al1[4];
            ah0[0]=f2tf32(af0); al0[0]=f2tf32(af0-__uint_as_float(ah0[0]));
            ah0[1]=f2tf32(af1); al0[1]=f2tf32(af1-__uint_as_float(ah0[1]));
            ah0[2]=f2tf32(af2); al0[2]=f2tf32(af2-__uint_as_float(ah0[2]));
            ah0[3]=f2tf32(af3); al0[3]=f2tf32(af3-__uint_as_float(ah0[3]));
            ah1[0]=f2tf32(bf0); al1[0]=f2tf32(bf0-__uint_as_float(ah1[0]));
            ah1[1]=f2tf32(bf1); al1[1]=f2tf32(bf1-__uint_as_float(ah1[1]));
            ah1[2]=f2tf32(bf2); al1[2]=f2tf32(bf2-__uint_as_float(ah1[2]));
            ah1[3]=f2tf32(bf3); al1[3]=f2tf32(bf3-__uint_as_float(ah1[3]));
            const unsigned* wh = Whi + (size_t)(kt*8+tig)*WST + g + nh*64;
            const unsigned* wl = Wlo + (size_t)(kt*8+tig)*WST + g + nh*64;
            #pragma unroll
            for (int nt = 0; nt < 8; nt++) {
                unsigned bh[2] = { wh[nt*8], wh[nt*8 + 4*WST] };
                unsigned bl[2] = { wl[nt*8], wl[nt*8 + 4*WST] };
                mma_tf32(acc0[nt], ah0, bl);
                mma_tf32(acc0[nt], al0, bh);
                mma_tf32(acc0[nt], ah0, bh);
                mma_tf32(acc1[nt], ah1, bl);
                mma_tf32(acc1[nt], al1, bh);
                mma_tf32(acc1[nt], ah1, bh);
            }
        }

        if (COUT == 64) {
            float* yr = g_zB + (row0 + rbase)*(size_t)64 + 2*tig;
            #pragma unroll
            for (int nt = 0; nt < 8; nt++) {
                *(float2*)(yr + nt*8)           = make_float2(acc0[nt][0], acc0[nt][1]);
                *(float2*)(yr + 8*64 + nt*8)    = make_float2(acc0[nt][2], acc0[nt][3]);
                *(float2*)(yr + 16*64 + nt*8)   = make_float2(acc1[nt][0], acc1[nt][1]);
                *(float2*)(yr + 24*64 + nt*8)   = make_float2(acc1[nt][2], acc1[nt][3]);
            }
        }

        // stats (+ maxmin for COUT==128); warp covers exactly one (b,s) group
        #pragma unroll
        for (int nt = 0; nt < 8; nt++) {
            int c0 = nh*64 + nt*8 + 2*tig;
            float a0=acc0[nt][0], a1=acc0[nt][1], a2=acc0[nt][2], a3=acc0[nt][3];
            float b0=acc1[nt][0], b1=acc1[nt][1], b2=acc1[nt][2], b3=acc1[nt][3];
            float sc0 = (a0 + a2) + (b0 + b2);
            float sc1 = (a1 + a3) + (b1 + b3);
            float qc0 = (a0*a0 + a2*a2) + (b0*b0 + b2*b2);
            float qc1 = (a1*a1 + a3*a3) + (b1*b1 + b3*b3);
            #pragma unroll
            for (int off = 4; off <= 16; off <<= 1) {
                sc0 += __shfl_xor_sync(0xffffffffu, sc0, off);
                sc1 += __shfl_xor_sync(0xffffffffu, sc1, off);
                qc0 += __shfl_xor_sync(0xffffffffu, qc0, off);
                qc1 += __shfl_xor_sync(0xffffffffu, qc1, off);
            }
            if (g == 0) {
                atomicAdd(&sstat[c0],        sc0); atomicAdd(&sstat[c0+1],        sc1);
                atomicAdd(&sstat[COUT+c0],   qc0); atomicAdd(&sstat[COUT+c0+1],   qc1);
            }
            if (COUT == 128) {
                float m0 = fmaxf(fmaxf(a0, a2), fmaxf(b0, b2));
                float m1 = fmaxf(fmaxf(a1, a3), fmaxf(b1, b3));
                float n0 = fminf(fminf(a0, a2), fminf(b0, b2));
                float n1 = fminf(fminf(a1, a3), fminf(b1, b3));
                #pragma unroll
                for (int off = 4; off <= 16; off <<= 1) {
                    m0 = fmaxf(m0, __shfl_xor_sync(0xffffffffu, m0, off));
                    m1 = fmaxf(m1, __shfl_xor_sync(0xffffffffu, m1, off));
                    n0 = fminf(n0, __shfl_xor_sync(0xffffffffu, n0, off));
                    n1 = fminf(n1, __shfl_xor_sync(0xffffffffu, n1, off));
                }
                if (g == 0) {
                    size_t grp = (size_t)blockIdx.x*4 + w;
                    g_gmax[grp*128 + c0] = m0; g_gmax[grp*128 + c0+1] = m1;
                    g_gmin[grp*128 + c0] = n0; g_gmin[grp*128 + c0+1] = n1;
                }
            }
        }
    }
    __syncthreads();
    for (int i = t; i < COUT; i += 128) {
        atomicAdd(&g_stat[statOff + i],        (double)sstat[i]);
        atomicAdd(&g_stat[statOff + COUT + i], (double)sstat[COUT + i]);
    }
}

// ---- final output: BN2+ReLU+max via per-group extrema ----
__global__ void output_kernel(float* __restrict__ out) {
    int o = threadIdx.x;
    size_t bs = blockIdx.x;
    float sc = g_scale[128 + o], sh = g_shift[128 + o];
    float mx = g_gmax[bs*128 + o], mn = g_gmin[bs*128 + o];
    float v = (sc > 0.f) ? fmaf(sc, mx, sh) : fmaf(sc, mn, sh);
    int b = (int)(bs >> 10), s = (int)(bs & 1023);
    out[(size_t)NB*NS*3 + ((size_t)b*128 + o)*NS + s] = fmaxf(v, 0.f);
}

extern "C" void kernel_launch(void* const* d_in, const int* in_sizes, int n_in,
                              void* d_out, int out_size) {
    const float* xyz    = (const float*)d_in[0];
    const float* points = (const float*)d_in[1];
    const float* w0 = (const float*)d_in[2];
    const float* g0 = (const float*)d_in[3];
    const float* b0 = (const float*)d_in[4];
    const float* w1 = (const float*)d_in[5];
    const float* g1 = (const float*)d_in[6];
    const float* b1 = (const float*)d_in[7];
    const float* w2 = (const float*)d_in[8];
    const float* g2 = (const float*)d_in[9];
    const float* b2 = (const float*)d_in[10];
    float* out = (float*)d_out;

    const int FRONT_SMEM = 4*NPT*4;
    const int G64_SMEM   = 128*68*4 + 2*64*72*4  + 2*64*4  + 320*4;   // 73472
    const int G128_SMEM  = 128*68*4 + 2*64*136*4 + 2*128*4;           // 105472
    cudaFuncSetAttribute(front_kernel, cudaFuncAttributeMaxDynamicSharedMemorySize, FRONT_SMEM);
    cudaFuncSetAttribute(gemm_tc_kernel<64>,  cudaFuncAttributeMaxDynamicSharedMemorySize, G64_SMEM);
    cudaFuncSetAttribute(gemm_tc_kernel<128>, cudaFuncAttributeMaxDynamicSharedMemorySize, G128_SMEM);

    zero_kernel<<<1, 512>>>();
    front_kernel<<<1552, FTH, FRONT_SMEM>>>(xyz, points, w0, out);
    finalize_kernel<<<1, 128>>>(64, 0, 0, g0, b0);
    gemm_tc_kernel<64><<<MROWS/128, 128, G64_SMEM>>>(w1, w0, xyz, out);
    finalize_kernel<<<1, 128>>>(64, 128, 64, g1, b1);
    gemm_tc_kernel<128><<<MROWS/128, 128, G128_SMEM>>>(w2, nullptr, nullptr, nullptr);
    finalize_kernel<<<1, 128>>>(128, 256, 128, g2, b2);
    output_kernel<<<NB*NS, 128>>>(out);
    (void)in_sizes; (void)n_in; (void)out_size;
}

// round 10
// speedup vs baseline: 2.5677x; 1.1267x over previous
#include <cuda_runtime.h>
#include <cstddef>

#define NB 16
#define NPT 4096
#define NS 1024
#define NK 32
#define MROWS (NB*NS*NK)
#define FTH 512

__device__ __align__(16) float g_pprime[(size_t)NB*NPT*64];
__device__ int                 g_gidx[MROWS];
__device__ __align__(16) float g_zB[(size_t)MROWS*64];   // z1
__device__ __align__(16) float g_gmax[(size_t)NB*NS*128];
__device__ __align__(16) float g_gmin[(size_t)NB*NS*128];
__device__ double              g_stat[512];
__device__ float               g_scale[320];
__device__ float               g_shift[320];
__device__ int                 g_fpsprog[NB];
__device__ int                 g_bqdone[NB*32];
__device__ int                 g_ppcnt[NB];

__device__ __forceinline__ unsigned long long pk(float lo, float hi) {
    unsigned long long r;
    asm("mov.b64 %0, {%1,%2};" : "=l"(r) : "f"(lo), "f"(hi));
    return r;
}
__device__ __forceinline__ unsigned long long ffma2(unsigned long long a, unsigned long long b, unsigned long long c) {
    unsigned long long d;
    asm("fma.rn.f32x2 %0, %1, %2, %3;" : "=l"(d) : "l"(a), "l"(b), "l"(c));
    return d;
}
__device__ __forceinline__ unsigned long long add2(unsigned long long a, unsigned long long b) {
    unsigned long long d;
    asm("add.rn.f32x2 %0, %1, %2;" : "=l"(d) : "l"(a), "l"(b));
    return d;
}
__device__ __forceinline__ unsigned long long mul2(unsigned long long a, unsigned long long b) {
    unsigned long long d;
    asm("mul.rn.f32x2 %0, %1, %2;" : "=l"(d) : "l"(a), "l"(b));
    return d;
}
__device__ __forceinline__ void upk(unsigned long long v, float& lo, float& hi) {
    asm("mov.b64 {%0,%1}, %2;" : "=f"(lo), "=f"(hi) : "l"(v));
}
__device__ __forceinline__ unsigned redux_umax(unsigned v) {
    unsigned r;
    asm("redux.sync.max.u32 %0, %1, 0xffffffff;" : "=r"(r) : "r"(v));
    return r;
}
__device__ __forceinline__ unsigned f2tf32(float x) {
    unsigned r;
    asm("cvt.rna.tf32.f32 %0, %1;" : "=r"(r) : "f"(x));
    return r;
}
__device__ __forceinline__ void mma_tf32(float* c, const unsigned* a, const unsigned* b) {
    asm volatile("mma.sync.aligned.m16n8k8.row.col.f32.tf32.tf32.f32 "
        "{%0,%1,%2,%3}, {%4,%5,%6,%7}, {%8,%9}, {%0,%1,%2,%3};"
        : "+f"(c[0]), "+f"(c[1]), "+f"(c[2]), "+f"(c[3])
        : "r"(a[0]), "r"(a[1]), "r"(a[2]), "r"(a[3]), "r"(b[0]), "r"(b[1]));
}
__device__ __forceinline__ void spin_until(volatile int* p, int target) {
    while (*p < target) __nanosleep(64);
}

__global__ void zero_kernel() {
    int t = threadIdx.x;
    if (t < 512) { g_stat[t] = 0.0; g_bqdone[t] = 0; }
    if (t < NB) { g_fpsprog[t] = 0; g_ppcnt[t] = 0; }
}

// =================== mega front kernel with fps progress pipelining ===================
// blocks [0,16)      : fps(b)           -> g_fpsprog[b] += 32 every 32 iters
// blocks [16,528)    : pprime (b, n0)   -> g_ppcnt[b]++
// blocks [528,1040)  : bq (b, sb) waits fpsprog >= (sb+1)*32 -> g_bqdone[b*32+sb]=1
// blocks [1040,1552) : stats0 (b, sb) waits bqdone[b,sb] && pp==32
__global__ void __launch_bounds__(FTH) front_kernel(const float* __restrict__ xyz,
                                                    const float* __restrict__ points,
                                                    const float* __restrict__ w0,
                                                    float* __restrict__ out_newxyz) {
    extern __shared__ float dsm[];
    int bid = blockIdx.x;
    int t = threadIdx.x;

    if (bid < 16) {
        int b = bid;
        float* sx = dsm; float* sy = dsm + NPT; float* sz = dsm + 2*NPT;
        unsigned* swhi = (unsigned*)(dsm + 3*NPT);
        unsigned* swlo = swhi + 32;
        int w = t >> 5, lane = t & 31;
        const float* p = xyz + (size_t)b*NPT*3;
        for (int i = t; i < NPT; i += FTH) { sx[i]=p[3*i]; sy[i]=p[3*i+1]; sz[i]=p[3*i+2]; }
        __syncthreads();
        unsigned long long pxp[4], pyp[4], pzp[4];
        float dist[8];
        const float INF = __int_as_float(0x7f800000);
        #pragma unroll
        for (int j = 0; j < 4; j++) {
            int p0 = t + (2*j)*FTH, p1 = t + (2*j+1)*FTH;
            pxp[j] = pk(sx[p0], sx[p1]);
            pyp[j] = pk(sy[p0], sy[p1]);
            pzp[j] = pk(sz[p0], sz[p1]);
            dist[2*j] = INF; dist[2*j+1] = INF;
        }
        int far = 0;
        for (int it = 0; it < NS; it++) {
            if (t == 0) {
                size_t o = ((size_t)b*NS + it)*3;
                out_newxyz[o] = sx[far]; out_newxyz[o+1] = sy[far]; out_newxyz[o+2] = sz[far];
                if (((it+1) & 31) == 0) { __threadfence(); atomicExch(&g_fpsprog[b], it+1); }
            }
            if (it == NS-1) break;
            float cx = sx[far], cy = sy[far], cz = sz[far];
            unsigned long long ncx = pk(-cx,-cx), ncy = pk(-cy,-cy), ncz = pk(-cz,-cz);
            #pragma unroll
            for (int j = 0; j < 4; j++) {
                unsigned long long dx = add2(pxp[j], ncx);
                unsigned long long dy = add2(pyp[j], ncy);
                unsigned long long dz = add2(pzp[j], ncz);
                unsigned long long d2 = add2(add2(mul2(dx,dx), mul2(dy,dy)), mul2(dz,dz));
                float d0, d1; upk(d2, d0, d1);
                dist[2*j]   = fminf(dist[2*j],   d0);
                dist[2*j+1] = fminf(dist[2*j+1], d1);
            }
            float m0 = fmaxf(dist[0], dist[1]), m1 = fmaxf(dist[2], dist[3]);
            float m2 = fmaxf(dist[4], dist[5]), m3 = fmaxf(dist[6], dist[7]);
            float best = fmaxf(fmaxf(m0, m1), fmaxf(m2, m3));
            unsigned inv = 0u;
            #pragma unroll
            for (int k = 0; k < 8; k++) {
                unsigned cand = 0xFFFFFFFFu - (unsigned)(t + k*FTH);
                if (dist[k] == best && cand > inv) inv = cand;
            }
            unsigned hi  = __float_as_uint(best);
            unsigned whi = redux_umax(hi);
            unsigned lo  = (hi == whi) ? inv : 0u;
            unsigned wlo = redux_umax(lo);
            int buf = (it & 1) << 4;
            if (lane == 0) { swhi[buf + w] = whi; swlo[buf + w] = wlo; }
            __syncthreads();
            unsigned h2 = swhi[buf + (lane & 15)];
            unsigned l2 = swlo[buf + (lane & 15)];
            unsigned mh = redux_umax(h2);
            unsigned ml = redux_umax((h2 == mh) ? l2 : 0u);
            far = (int)(0xFFFFFFFFu - ml);
        }

    } else if (bid < 528) {
        int idx = bid - 16;
        int b = idx >> 5, n0 = (idx & 31) * 128;
        float* Pts = dsm;
        float* Wt  = dsm + 64*128;
        for (int i = t; i < 64*64; i += FTH) { int o = i>>6, c = i&63; Wt[c*64 + o] = w0[o*67 + 3 + c]; }
        const float* pb = points + (size_t)b*64*NPT;
        for (int i = t; i < 64*128/4; i += FTH) {
            int e = i*4, c = e>>7, n = e&127;
            *(float4*)&Pts[c*128 + n] = *(const float4*)(pb + (size_t)c*NPT + n0 + n);
        }
        __syncthreads();
        int cg = t & 15, rg = t >> 4;
        unsigned long long acc[4][2];
        #pragma unroll
        for (int i = 0; i < 4; i++) { acc[i][0]=0ull; acc[i][1]=0ull; }
        #pragma unroll 4
        for (int c = 0; c < 64; c++) {
            ulonglong2 wv = *(const ulonglong2*)&Wt[c*64 + cg*4];
            #pragma unroll
            for (int i = 0; i < 4; i++) {
                float a = Pts[c*128 + rg*4 + i];
                unsigned long long aa = pk(a, a);
                acc[i][0] = ffma2(aa, wv.x, acc[i][0]);
                acc[i][1] = ffma2(aa, wv.y, acc[i][1]);
            }
        }
        float* outp = g_pprime + ((size_t)b*NPT + n0)*64;
        #pragma unroll
        for (int i = 0; i < 4; i++) {
            float4 v; upk(acc[i][0], v.x, v.y); upk(acc[i][1], v.z, v.w);
            *(float4*)(outp + (size_t)(rg*4+i)*64 + cg*4) = v;
        }
        __threadfence();
        __syncthreads();
        if (t == 0) atomicAdd(&g_ppcnt[b], 1);

    } else if (bid < 1040) {
        int idx = bid - 528;
        int b = idx >> 5, sb = idx & 31;
        float* sx = dsm; float* sy = dsm + NPT; float* sz = dsm + 2*NPT; float* spp = dsm + 3*NPT;
        int w = t>>5, lane = t&31;
        const float* p = xyz + (size_t)b*NPT*3;
        for (int i = t; i < NPT; i += FTH) {
            float px = p[3*i], py = p[3*i+1], pz = p[3*i+2];
            sx[i]=px; sy[i]=py; sz[i]=pz;
            spp[i] = __fadd_rn(__fadd_rn(__fmul_rn(px,px), __fmul_rn(py,py)), __fmul_rn(pz,pz));
        }
        if (t == 0) { spin_until(&g_fpsprog[b], (sb+1)*32); __threadfence(); }
        __syncthreads();
        const float* newxyz = out_newxyz;
        for (int q = 0; q < 2; q++) {
            int s = sb*32 + w*2 + q;
            const float* nc = newxyz + ((size_t)b*NS + s)*3;
            float cx = nc[0], cy = nc[1], cz = nc[2];
            float cc = __fadd_rn(__fadd_rn(__fmul_rn(cx,cx), __fmul_rn(cy,cy)), __fmul_rn(cz,cz));
            int count = 0, first = 0;
            int* go = g_gidx + ((size_t)b*NS + s)*NK;
            for (int base = 0; base < NPT && count < NK; base += 32) {
                int pi = base + lane;
                float px = sx[pi], py = sy[pi], pz = sz[pi];
                float pp  = spp[pi];
                float dot = __fadd_rn(__fadd_rn(__fmul_rn(cx,px), __fmul_rn(cy,py)), __fmul_rn(cz,pz));
                float sqr = __fadd_rn(__fadd_rn(cc, pp), -__fmul_rn(2.0f, dot));
                bool in = (sqr <= 0.04f);
                unsigned mask = __ballot_sync(0xffffffffu, in);
                if (count == 0 && mask) first = base + __ffs(mask) - 1;
                if (in) {
                    int pos = count + __popc(mask & ((1u << lane) - 1u));
                    if (pos < NK) go[pos] = pi;
                }
                count += __popc(mask);
            }
            if (count < NK && lane >= count) go[lane] = first;
        }
        __threadfence();
        __syncthreads();
        if (t == 0) atomicExch(&g_bqdone[b*32 + sb], 1);

    } else {
        int idx = bid - 1040;
        int b = idx >> 5, sb = idx & 31;
        float* wx = dsm; float* wy = dsm + 64; float* wz = dsm + 128;
        float* ssum = dsm + 192;
        float* ssq  = dsm + 192 + 512;
        if (t < 64) { wx[t]=w0[t*67]; wy[t]=w0[t*67+1]; wz[t]=w0[t*67+2]; }
        if (t == 0) {
            spin_until(&g_bqdone[b*32 + sb], 1);
            spin_until(&g_ppcnt[b], 32);
            __threadfence();
        }
        __syncthreads();
        int c = t & 63, rl = t >> 6;
        float wxc = wx[c], wyc = wy[c], wzc = wz[c];
        float s = 0.f, q = 0.f;
        size_t base = (size_t)b * (MROWS/NB) + (size_t)sb * 1024;
        const float* newxyz = out_newxyz;
        for (int i = 0; i < 128; i++) {
            size_t row = base + i*8 + rl;
            int g = g_gidx[row];
            int ss = (int)((row >> 5) & 1023);
            const float* nc = newxyz + ((size_t)b*NS + ss)*3;
            const float* pt = xyz + ((size_t)b*NPT + g)*3;
            float gx = pt[0]-nc[0], gy = pt[1]-nc[1], gz = pt[2]-nc[2];
            float v = g_pprime[((size_t)b*NPT + g)*64 + c];
            v = fmaf(wxc, gx, fmaf(wyc, gy, fmaf(wzc, gz, v)));
            s += v; q = fmaf(v, v, q);
        }
        ssum[rl*64 + c] = s; ssq[rl*64 + c] = q;
        __syncthreads();
        if (t < 64) {
            double S = 0.0, Q = 0.0;
            #pragma unroll
            for (int r = 0; r < 8; r++) { S += (double)ssum[r*64 + t]; Q += (double)ssq[r*64 + t]; }
            atomicAdd(&g_stat[t], S);
            atomicAdd(&g_stat[64 + t], Q);
        }
    }
}

__global__ void finalize_kernel(int C, int statOff, int bnOff,
                                const float* __restrict__ g, const float* __restrict__ bb) {
    int c = threadIdx.x;
    if (c >= C) return;
    double inv = 1.0 / (double)MROWS;
    double mean = g_stat[statOff + c] * inv;
    double var  = g_stat[statOff + C + c] * inv - mean*mean;
    double sc = (double)g[c] / sqrt(var + 1e-5);
    g_scale[bnOff + c] = (float)sc;
    g_shift[bnOff + c] = (float)((double)bb[c] - mean * sc);
}

// ---- TC GEMM v3: 256 threads, 8 warps x 32 rows, 256-row tiles, staged W chunks ----
template<int COUT>
__global__ void __launch_bounds__(256) gemm_tc_kernel(const float* __restrict__ W,
                                                      const float* __restrict__ w0,
                                                      const float* __restrict__ xyz,
                                                      const float* __restrict__ newxyz) {
    constexpr int XST = 68;
    constexpr int WST = 72;
    constexpr int NH  = COUT / 64;
    constexpr int statOff = (COUT == 64) ? 128 : 256;
    extern __shared__ float sm[];
    float*    Xs    = sm;                               // [256][68]
    unsigned* Whi   = (unsigned*)(sm + 256*XST);        // [64][72] chunk
    unsigned* Wlo   = Whi + 64*WST;
    float*    sstat = (float*)(Wlo + 64*WST);           // [2*COUT]
    float*    aux   = sstat + 2*COUT;                   // COUT==64: 320 floats
    int t = threadIdx.x;
    size_t row0 = (size_t)blockIdx.x * 256;

    for (int i = t; i < 2*COUT; i += 256) sstat[i] = 0.f;

    if (COUT == 64) {
        if (t < 64) {
            aux[t]     = w0[t*67];   aux[64+t]  = w0[t*67+1]; aux[128+t] = w0[t*67+2];
            aux[192+t] = g_scale[t]; aux[256+t] = g_shift[t];
        }
        __syncthreads();
        #pragma unroll
        for (int j = 0; j < 2; j++) {
            int idx = t + j*256;
            int r = idx >> 1, half = idx & 1;
            size_t row = row0 + r;
            int g = g_gidx[row];
            int ss = (int)((row >> 5) & 1023), b = (int)(row >> 15);
            const float* nc = newxyz + ((size_t)b*NS + ss)*3;
            const float* pt = xyz + ((size_t)b*NPT + g)*3;
            float gx = pt[0]-nc[0], gy = pt[1]-nc[1], gz = pt[2]-nc[2];
            const float4* pr = (const float4*)(g_pprime + ((size_t)b*NPT + g)*64 + half*32);
            float* xd = Xs + (size_t)r*XST + half*32;
            #pragma unroll
            for (int qq = 0; qq < 8; qq++) {
                float4 v = pr[qq]; int c = half*32 + qq*4;
                float z0 = fmaf(aux[c  ], gx, fmaf(aux[64+c  ], gy, fmaf(aux[128+c  ], gz, v.x)));
                float z1 = fmaf(aux[c+1], gx, fmaf(aux[64+c+1], gy, fmaf(aux[128+c+1], gz, v.y)));
                float z2 = fmaf(aux[c+2], gx, fmaf(aux[64+c+2], gy, fmaf(aux[128+c+2], gz, v.z)));
                float z3 = fmaf(aux[c+3], gx, fmaf(aux[64+c+3], gy, fmaf(aux[128+c+3], gz, v.w)));
                float4 o4;
                o4.x = fmaxf(fmaf(z0, aux[192+c  ], aux[256+c  ]), 0.f);
                o4.y = fmaxf(fmaf(z1, aux[192+c+1], aux[256+c+1]), 0.f);
                o4.z = fmaxf(fmaf(z2, aux[192+c+2], aux[256+c+2]), 0.f);
                o4.w = fmaxf(fmaf(z3, aux[192+c+3], aux[256+c+3]), 0.f);
                *(float4*)(xd + qq*4) = o4;
            }
        }
    } else {
        int c0 = (t*4) & 63;
        float s0=g_scale[64+c0], s1=g_scale[64+c0+1], s2=g_scale[64+c0+2], s3=g_scale[64+c0+3];
        float h0=g_shift[64+c0], h1=g_shift[64+c0+1], h2=g_shift[64+c0+2], h3=g_shift[64+c0+3];
        #pragma unroll
        for (int j = 0; j < 16; j++) {
            int e = t*4 + j*1024;
            float4 v = *(const float4*)(g_zB + row0*64 + e);
            int r = e >> 6;
            float4 o4;
            o4.x = fmaxf(fmaf(v.x, s0, h0), 0.f);
            o4.y = fmaxf(fmaf(v.y, s1, h1), 0.f);
            o4.z = fmaxf(fmaf(v.z, s2, h2), 0.f);
            o4.w = fmaxf(fmaf(v.w, s3, h3), 0.f);
            *(float4*)(Xs + (size_t)r*XST + c0) = o4;
        }
    }

    int w = t >> 5, lane = t & 31;
    int g = lane >> 2, tig = lane & 3;
    int rbase = w*32 + g;

    #pragma unroll
    for (int nh = 0; nh < NH; nh++) {
        __syncthreads();      // Xs built / prior epilogue drained before W chunk (re)load
        for (int i = t; i < 64*64; i += 256) {
            int o = i >> 6, c = i & 63;
            float wv = W[(size_t)(nh*64 + o)*64 + c];
            unsigned hi = f2tf32(wv);
            Whi[c*WST + o] = hi;
            Wlo[c*WST + o] = f2tf32(wv - __uint_as_float(hi));
        }
        __syncthreads();

        float acc0[8][4], acc1[8][4];
        #pragma unroll
        for (int nt = 0; nt < 8; nt++) {
            acc0[nt][0]=0.f; acc0[nt][1]=0.f; acc0[nt][2]=0.f; acc0[nt][3]=0.f;
            acc1[nt][0]=0.f; acc1[nt][1]=0.f; acc1[nt][2]=0.f; acc1[nt][3]=0.f;
        }
        #pragma unroll
        for (int kt = 0; kt < 8; kt++) {
            const float* xa = Xs + (size_t)rbase*XST + kt*8 + tig;
            float af0 = xa[0],        af1 = xa[8*XST],        af2 = xa[4],         af3 = xa[8*XST+4];
            float bf0 = xa[16*XST],   bf1 = xa[24*XST],       bf2 = xa[16*XST+4],  bf3 = xa[24*XST+4];
            unsigned ah0[4], al0[4], ah1[4], al1[4];
            ah0[0]=f2tf32(af0); al0[0]=f2tf32(af0-__uint_as_float(ah0[0]));
            ah0[1]=f2tf32(af1); al0[1]=f2tf32(af1-__uint_as_float(ah0[1]));
            ah0[2]=f2tf32(af2); al0[2]=f2tf32(af2-__uint_as_float(ah0[2]));
            ah0[3]=f2tf32(af3); al0[3]=f2tf32(af3-__uint_as_float(ah0[3]));
            ah1[0]=f2tf32(bf0); al1[0]=f2tf32(bf0-__uint_as_float(ah1[0]));
            ah1[1]=f2tf32(bf1); al1[1]=f2tf32(bf1-__uint_as_float(ah1[1]));
            ah1[2]=f2tf32(bf2); al1[2]=f2tf32(bf2-__uint_as_float(ah1[2]));
            ah1[3]=f2tf32(bf3); al1[3]=f2tf32(bf3-__uint_as_float(ah1[3]));
            const unsigned* wh = Whi + (size_t)(kt*8+tig)*WST + g;
            const unsigned* wl = Wlo + (size_t)(kt*8+tig)*WST + g;
            #pragma unroll
            for (int nt = 0; nt < 8; nt++) {
                unsigned bh[2] = { wh[nt*8], wh[nt*8 + 4*WST] };
                unsigned bl[2] = { wl[nt*8], wl[nt*8 + 4*WST] };
                mma_tf32(acc0[nt], ah0, bl);
                mma_tf32(acc0[nt], al0, bh);
                mma_tf32(acc0[nt], ah0, bh);
                mma_tf32(acc1[nt], ah1, bl);
                mma_tf32(acc1[nt], al1, bh);
                mma_tf32(acc1[nt], ah1, bh);
            }
        }

        if (COUT == 64) {
            float* yr = g_zB + (row0 + rbase)*(size_t)64 + 2*tig;
            #pragma unroll
            for (int nt = 0; nt < 8; nt++) {
                *(float2*)(yr + nt*8)           = make_float2(acc0[nt][0], acc0[nt][1]);
                *(float2*)(yr + 8*64 + nt*8)    = make_float2(acc0[nt][2], acc0[nt][3]);
                *(float2*)(yr + 16*64 + nt*8)   = make_float2(acc1[nt][0], acc1[nt][1]);
                *(float2*)(yr + 24*64 + nt*8)   = make_float2(acc1[nt][2], acc1[nt][3]);
            }
        }

        // stats (+ maxmin for COUT==128); warp covers exactly one (b,s) group (32 rows)
        #pragma unroll
        for (int nt = 0; nt < 8; nt++) {
            int c0 = nh*64 + nt*8 + 2*tig;
            float a0=acc0[nt][0], a1=acc0[nt][1], a2=acc0[nt][2], a3=acc0[nt][3];
            float b0=acc1[nt][0], b1=acc1[nt][1], b2=acc1[nt][2], b3=acc1[nt][3];
            float sc0 = (a0 + a2) + (b0 + b2);
            float sc1 = (a1 + a3) + (b1 + b3);
            float qc0 = (a0*a0 + a2*a2) + (b0*b0 + b2*b2);
            float qc1 = (a1*a1 + a3*a3) + (b1*b1 + b3*b3);
            #pragma unroll
            for (int off = 4; off <= 16; off <<= 1) {
                sc0 += __shfl_xor_sync(0xffffffffu, sc0, off);
                sc1 += __shfl_xor_sync(0xffffffffu, sc1, off);
                qc0 += __shfl_xor_sync(0xffffffffu, qc0, off);
                qc1 += __shfl_xor_sync(0xffffffffu, qc1, off);
            }
            if (g == 0) {
                atomicAdd(&sstat[c0],        sc0); atomicAdd(&sstat[c0+1],        sc1);
                atomicAdd(&sstat[COUT+c0],   qc0); atomicAdd(&sstat[COUT+c0+1],   qc1);
            }
            if (COUT == 128) {
                float m0 = fmaxf(fmaxf(a0, a2), fmaxf(b0, b2));
                float m1 = fmaxf(fmaxf(a1, a3), fmaxf(b1, b3));
                float n0 = fminf(fminf(a0, a2), fminf(b0, b2));
                float n1 = fminf(fminf(a1, a3), fminf(b1, b3));
                #pragma unroll
                for (int off = 4; off <= 16; off <<= 1) {
                    m0 = fmaxf(m0, __shfl_xor_sync(0xffffffffu, m0, off));
                    m1 = fmaxf(m1, __shfl_xor_sync(0xffffffffu, m1, off));
                    n0 = fminf(n0, __shfl_xor_sync(0xffffffffu, n0, off));
                    n1 = fminf(n1, __shfl_xor_sync(0xffffffffu, n1, off));
                }
                if (g == 0) {
                    size_t grp = (size_t)blockIdx.x*8 + w;
                    g_gmax[grp*128 + c0] = m0; g_gmax[grp*128 + c0+1] = m1;
                    g_gmin[grp*128 + c0] = n0; g_gmin[grp*128 + c0+1] = n1;
                }
            }
        }
    }
    __syncthreads();
    for (int i = t; i < COUT; i += 256) {
        atomicAdd(&g_stat[statOff + i],        (double)sstat[i]);
        atomicAdd(&g_stat[statOff + COUT + i], (double)sstat[COUT + i]);
    }
}

// ---- final output: BN2+ReLU+max via per-group extrema ----
__global__ void output_kernel(float* __restrict__ out) {
    int o = threadIdx.x;
    size_t bs = blockIdx.x;
    float sc = g_scale[128 + o], sh = g_shift[128 + o];
    float mx = g_gmax[bs*128 + o], mn = g_gmin[bs*128 + o];
    float v = (sc > 0.f) ? fmaf(sc, mx, sh) : fmaf(sc, mn, sh);
    int b = (int)(bs >> 10), s = (int)(bs & 1023);
    out[(size_t)NB*NS*3 + ((size_t)b*128 + o)*NS + s] = fmaxf(v, 0.f);
}

extern "C" void kernel_launch(void* const* d_in, const int* in_sizes, int n_in,
                              void* d_out, int out_size) {
    const float* xyz    = (const float*)d_in[0];
    const float* points = (const float*)d_in[1];
    const float* w0 = (const float*)d_in[2];
    const float* g0 = (const float*)d_in[3];
    const float* b0 = (const float*)d_in[4];
    const float* w1 = (const float*)d_in[5];
    const float* g1 = (const float*)d_in[6];
    const float* b1 = (const float*)d_in[7];
    const float* w2 = (const float*)d_in[8];
    const float* g2 = (const float*)d_in[9];
    const float* b2 = (const float*)d_in[10];
    float* out = (float*)d_out;

    const int FRONT_SMEM = 4*NPT*4;
    const int G64_SMEM   = 256*68*4 + 2*64*72*4 + 2*64*4 + 320*4;    // 108288
    const int G128_SMEM  = 256*68*4 + 2*64*72*4 + 2*128*4;           // 107520
    cudaFuncSetAttribute(front_kernel, cudaFuncAttributeMaxDynamicSharedMemorySize, FRONT_SMEM);
    cudaFuncSetAttribute(gemm_tc_kernel<64>,  cudaFuncAttributeMaxDynamicSharedMemorySize, G64_SMEM);
    cudaFuncSetAttribute(gemm_tc_kernel<128>, cudaFuncAttributeMaxDynamicSharedMemorySize, G128_SMEM);

    zero_kernel<<<1, 512>>>();
    front_kernel<<<1552, FTH, FRONT_SMEM>>>(xyz, points, w0, out);
    finalize_kernel<<<1, 128>>>(64, 0, 0, g0, b0);
    gemm_tc_kernel<64><<<MROWS/256, 256, G64_SMEM>>>(w1, w0, xyz, out);
    finalize_kernel<<<1, 128>>>(64, 128, 64, g1, b1);
    gemm_tc_kernel<128><<<MROWS/256, 256, G128_SMEM>>>(w2, nullptr, nullptr, nullptr);
    finalize_kernel<<<1, 128>>>(128, 256, 128, g2, b2);
    output_kernel<<<NB*NS, 128>>>(out);
    (void)in_sizes; (void)n_in; (void)out_size;
}

// round 11
// speedup vs baseline: 2.9227x; 1.1382x over previous
#include <cuda_runtime.h>
#include <cstddef>

#define NB 16
#define NPT 4096
#define NS 1024
#define NK 32
#define MROWS (NB*NS*NK)
#define FTH 512

__device__ __align__(16) float g_pprime[(size_t)NB*NPT*64];
__device__ int                 g_gidx[MROWS];
__device__ __align__(16) float g_zB[(size_t)MROWS*64];   // z1
__device__ __align__(16) float g_gmax[(size_t)NB*NS*128];
__device__ __align__(16) float g_gmin[(size_t)NB*NS*128];
__device__ double              g_stat[512];
__device__ float               g_scale[320];
__device__ float               g_shift[320];
__device__ int                 g_fpsprog[NB];
__device__ int                 g_bqdone[NB*32];
__device__ int                 g_ppcnt[NB];

__device__ __forceinline__ unsigned long long pk(float lo, float hi) {
    unsigned long long r;
    asm("mov.b64 %0, {%1,%2};" : "=l"(r) : "f"(lo), "f"(hi));
    return r;
}
__device__ __forceinline__ unsigned long long ffma2(unsigned long long a, unsigned long long b, unsigned long long c) {
    unsigned long long d;
    asm("fma.rn.f32x2 %0, %1, %2, %3;" : "=l"(d) : "l"(a), "l"(b), "l"(c));
    return d;
}
__device__ __forceinline__ unsigned long long add2(unsigned long long a, unsigned long long b) {
    unsigned long long d;
    asm("add.rn.f32x2 %0, %1, %2;" : "=l"(d) : "l"(a), "l"(b));
    return d;
}
__device__ __forceinline__ unsigned long long mul2(unsigned long long a, unsigned long long b) {
    unsigned long long d;
    asm("mul.rn.f32x2 %0, %1, %2;" : "=l"(d) : "l"(a), "l"(b));
    return d;
}
__device__ __forceinline__ void upk(unsigned long long v, float& lo, float& hi) {
    asm("mov.b64 {%0,%1}, %2;" : "=f"(lo), "=f"(hi) : "l"(v));
}
__device__ __forceinline__ unsigned redux_umax(unsigned v) {
    unsigned r;
    asm("redux.sync.max.u32 %0, %1, 0xffffffff;" : "=r"(r) : "r"(v));
    return r;
}
// pack (even,odd) floats into bf16x2 word: low 16 bits = even element
__device__ __forceinline__ unsigned pack_bf16x2(float even, float odd) {
    unsigned d;
    asm("cvt.rn.bf16x2.f32 %0, %1, %2;" : "=r"(d) : "f"(odd), "f"(even));
    return d;
}
__device__ __forceinline__ float bf16lo_f32(unsigned p) { return __uint_as_float(p << 16); }
__device__ __forceinline__ float bf16hi_f32(unsigned p) { return __uint_as_float(p & 0xffff0000u); }

__device__ __forceinline__ void mma_bf16(float* c, const unsigned* a, const unsigned* b) {
    asm volatile("mma.sync.aligned.m16n8k16.row.col.f32.bf16.bf16.f32 "
        "{%0,%1,%2,%3}, {%4,%5,%6,%7}, {%8,%9}, {%0,%1,%2,%3};"
        : "+f"(c[0]), "+f"(c[1]), "+f"(c[2]), "+f"(c[3])
        : "r"(a[0]), "r"(a[1]), "r"(a[2]), "r"(a[3]), "r"(b[0]), "r"(b[1]));
}
__device__ __forceinline__ void spin_until(volatile int* p, int target) {
    while (*p < target) __nanosleep(64);
}

__global__ void zero_kernel() {
    int t = threadIdx.x;
    if (t < 512) { g_stat[t] = 0.0; g_bqdone[t] = 0; }
    if (t < NB) { g_fpsprog[t] = 0; g_ppcnt[t] = 0; }
}

// =================== mega front kernel with fps progress pipelining (unchanged) ===================
__global__ void __launch_bounds__(FTH) front_kernel(const float* __restrict__ xyz,
                                                    const float* __restrict__ points,
                                                    const float* __restrict__ w0,
                                                    float* __restrict__ out_newxyz) {
    extern __shared__ float dsm[];
    int bid = blockIdx.x;
    int t = threadIdx.x;

    if (bid < 16) {
        int b = bid;
        float* sx = dsm; float* sy = dsm + NPT; float* sz = dsm + 2*NPT;
        unsigned* swhi = (unsigned*)(dsm + 3*NPT);
        unsigned* swlo = swhi + 32;
        int w = t >> 5, lane = t & 31;
        const float* p = xyz + (size_t)b*NPT*3;
        for (int i = t; i < NPT; i += FTH) { sx[i]=p[3*i]; sy[i]=p[3*i+1]; sz[i]=p[3*i+2]; }
        __syncthreads();
        unsigned long long pxp[4], pyp[4], pzp[4];
        float dist[8];
        const float INF = __int_as_float(0x7f800000);
        #pragma unroll
        for (int j = 0; j < 4; j++) {
            int p0 = t + (2*j)*FTH, p1 = t + (2*j+1)*FTH;
            pxp[j] = pk(sx[p0], sx[p1]);
            pyp[j] = pk(sy[p0], sy[p1]);
            pzp[j] = pk(sz[p0], sz[p1]);
            dist[2*j] = INF; dist[2*j+1] = INF;
        }
        int far = 0;
        for (int it = 0; it < NS; it++) {
            if (t == 0) {
                size_t o = ((size_t)b*NS + it)*3;
                out_newxyz[o] = sx[far]; out_newxyz[o+1] = sy[far]; out_newxyz[o+2] = sz[far];
                if (((it+1) & 31) == 0) { __threadfence(); atomicExch(&g_fpsprog[b], it+1); }
            }
            if (it == NS-1) break;
            float cx = sx[far], cy = sy[far], cz = sz[far];
            unsigned long long ncx = pk(-cx,-cx), ncy = pk(-cy,-cy), ncz = pk(-cz,-cz);
            #pragma unroll
            for (int j = 0; j < 4; j++) {
                unsigned long long dx = add2(pxp[j], ncx);
                unsigned long long dy = add2(pyp[j], ncy);
                unsigned long long dz = add2(pzp[j], ncz);
                unsigned long long d2 = add2(add2(mul2(dx,dx), mul2(dy,dy)), mul2(dz,dz));
                float d0, d1; upk(d2, d0, d1);
                dist[2*j]   = fminf(dist[2*j],   d0);
                dist[2*j+1] = fminf(dist[2*j+1], d1);
            }
            float m0 = fmaxf(dist[0], dist[1]), m1 = fmaxf(dist[2], dist[3]);
            float m2 = fmaxf(dist[4], dist[5]), m3 = fmaxf(dist[6], dist[7]);
            float best = fmaxf(fmaxf(m0, m1), fmaxf(m2, m3));
            unsigned inv = 0u;
            #pragma unroll
            for (int k = 0; k < 8; k++) {
                unsigned cand = 0xFFFFFFFFu - (unsigned)(t + k*FTH);
                if (dist[k] == best && cand > inv) inv = cand;
            }
            unsigned hi  = __float_as_uint(best);
            unsigned whi = redux_umax(hi);
            unsigned lo  = (hi == whi) ? inv : 0u;
            unsigned wlo = redux_umax(lo);
            int buf = (it & 1) << 4;
            if (lane == 0) { swhi[buf + w] = whi; swlo[buf + w] = wlo; }
            __syncthreads();
            unsigned h2 = swhi[buf + (lane & 15)];
            unsigned l2 = swlo[buf + (lane & 15)];
            unsigned mh = redux_umax(h2);
            unsigned ml = redux_umax((h2 == mh) ? l2 : 0u);
            far = (int)(0xFFFFFFFFu - ml);
        }

    } else if (bid < 528) {
        int idx = bid - 16;
        int b = idx >> 5, n0 = (idx & 31) * 128;
        float* Pts = dsm;
        float* Wt  = dsm + 64*128;
        for (int i = t; i < 64*64; i += FTH) { int o = i>>6, c = i&63; Wt[c*64 + o] = w0[o*67 + 3 + c]; }
        const float* pb = points + (size_t)b*64*NPT;
        for (int i = t; i < 64*128/4; i += FTH) {
            int e = i*4, c = e>>7, n = e&127;
            *(float4*)&Pts[c*128 + n] = *(const float4*)(pb + (size_t)c*NPT + n0 + n);
        }
        __syncthreads();
        int cg = t & 15, rg = t >> 4;
        unsigned long long acc[4][2];
        #pragma unroll
        for (int i = 0; i < 4; i++) { acc[i][0]=0ull; acc[i][1]=0ull; }
        #pragma unroll 4
        for (int c = 0; c < 64; c++) {
            ulonglong2 wv = *(const ulonglong2*)&Wt[c*64 + cg*4];
            #pragma unroll
            for (int i = 0; i < 4; i++) {
                float a = Pts[c*128 + rg*4 + i];
                unsigned long long aa = pk(a, a);
                acc[i][0] = ffma2(aa, wv.x, acc[i][0]);
                acc[i][1] = ffma2(aa, wv.y, acc[i][1]);
            }
        }
        float* outp = g_pprime + ((size_t)b*NPT + n0)*64;
        #pragma unroll
        for (int i = 0; i < 4; i++) {
            float4 v; upk(acc[i][0], v.x, v.y); upk(acc[i][1], v.z, v.w);
            *(float4*)(outp + (size_t)(rg*4+i)*64 + cg*4) = v;
        }
        __threadfence();
        __syncthreads();
        if (t == 0) atomicAdd(&g_ppcnt[b], 1);

    } else if (bid < 1040) {
        int idx = bid - 528;
        int b = idx >> 5, sb = idx & 31;
        float* sx = dsm; float* sy = dsm + NPT; float* sz = dsm + 2*NPT; float* spp = dsm + 3*NPT;
        int w = t>>5, lane = t&31;
        const float* p = xyz + (size_t)b*NPT*3;
        for (int i = t; i < NPT; i += FTH) {
            float px = p[3*i], py = p[3*i+1], pz = p[3*i+2];
            sx[i]=px; sy[i]=py; sz[i]=pz;
            spp[i] = __fadd_rn(__fadd_rn(__fmul_rn(px,px), __fmul_rn(py,py)), __fmul_rn(pz,pz));
        }
        if (t == 0) { spin_until(&g_fpsprog[b], (sb+1)*32); __threadfence(); }
        __syncthreads();
        const float* newxyz = out_newxyz;
        for (int q = 0; q < 2; q++) {
            int s = sb*32 + w*2 + q;
            const float* nc = newxyz + ((size_t)b*NS + s)*3;
            float cx = nc[0], cy = nc[1], cz = nc[2];
            float cc = __fadd_rn(__fadd_rn(__fmul_rn(cx,cx), __fmul_rn(cy,cy)), __fmul_rn(cz,cz));
            int count = 0, first = 0;
            int* go = g_gidx + ((size_t)b*NS + s)*NK;
            for (int base = 0; base < NPT && count < NK; base += 32) {
                int pi = base + lane;
                float px = sx[pi], py = sy[pi], pz = sz[pi];
                float pp  = spp[pi];
                float dot = __fadd_rn(__fadd_rn(__fmul_rn(cx,px), __fmul_rn(cy,py)), __fmul_rn(cz,pz));
                float sqr = __fadd_rn(__fadd_rn(cc, pp), -__fmul_rn(2.0f, dot));
                bool in = (sqr <= 0.04f);
                unsigned mask = __ballot_sync(0xffffffffu, in);
                if (count == 0 && mask) first = base + __ffs(mask) - 1;
                if (in) {
                    int pos = count + __popc(mask & ((1u << lane) - 1u));
                    if (pos < NK) go[pos] = pi;
                }
                count += __popc(mask);
            }
            if (count < NK && lane >= count) go[lane] = first;
        }
        __threadfence();
        __syncthreads();
        if (t == 0) atomicExch(&g_bqdone[b*32 + sb], 1);

    } else {
        int idx = bid - 1040;
        int b = idx >> 5, sb = idx & 31;
        float* wx = dsm; float* wy = dsm + 64; float* wz = dsm + 128;
        float* ssum = dsm + 192;
        float* ssq  = dsm + 192 + 512;
        if (t < 64) { wx[t]=w0[t*67]; wy[t]=w0[t*67+1]; wz[t]=w0[t*67+2]; }
        if (t == 0) {
            spin_until(&g_bqdone[b*32 + sb], 1);
            spin_until(&g_ppcnt[b], 32);
            __threadfence();
        }
        __syncthreads();
        int c = t & 63, rl = t >> 6;
        float wxc = wx[c], wyc = wy[c], wzc = wz[c];
        float s = 0.f, q = 0.f;
        size_t base = (size_t)b * (MROWS/NB) + (size_t)sb * 1024;
        const float* newxyz = out_newxyz;
        for (int i = 0; i < 128; i++) {
            size_t row = base + i*8 + rl;
            int g = g_gidx[row];
            int ss = (int)((row >> 5) & 1023);
            const float* nc = newxyz + ((size_t)b*NS + ss)*3;
            const float* pt = xyz + ((size_t)b*NPT + g)*3;
            float gx = pt[0]-nc[0], gy = pt[1]-nc[1], gz = pt[2]-nc[2];
            float v = g_pprime[((size_t)b*NPT + g)*64 + c];
            v = fmaf(wxc, gx, fmaf(wyc, gy, fmaf(wzc, gz, v)));
            s += v; q = fmaf(v, v, q);
        }
        ssum[rl*64 + c] = s; ssq[rl*64 + c] = q;
        __syncthreads();
        if (t < 64) {
            double S = 0.0, Q = 0.0;
            #pragma unroll
            for (int r = 0; r < 8; r++) { S += (double)ssum[r*64 + t]; Q += (double)ssq[r*64 + t]; }
            atomicAdd(&g_stat[t], S);
            atomicAdd(&g_stat[64 + t], Q);
        }
    }
}

__global__ void finalize_kernel(int C, int statOff, int bnOff,
                                const float* __restrict__ g, const float* __restrict__ bb) {
    int c = threadIdx.x;
    if (c >= C) return;
    double inv = 1.0 / (double)MROWS;
    double mean = g_stat[statOff + c] * inv;
    double var  = g_stat[statOff + C + c] * inv - mean*mean;
    double sc = (double)g[c] / sqrt(var + 1e-5);
    g_scale[bnOff + c] = (float)sc;
    g_shift[bnOff + c] = (float)((double)bb[c] - mean * sc);
}

// ---- TC GEMM v4: 3xBF16 (m16n8k16), hi/lo split precomputed in SMEM ----
// 256 threads, 8 warps x 32 rows, 256-row tiles. X packed bf16x2 kpair-major.
template<int COUT>
__global__ void __launch_bounds__(256) gemm_tc_kernel(const float* __restrict__ W,
                                                      const float* __restrict__ w0,
                                                      const float* __restrict__ xyz,
                                                      const float* __restrict__ newxyz) {
    constexpr int XSP = 36;     // kpair stride (banks 4g+tig conflict-free)
    constexpr int WSP = 72;     // n stride (banks 8tig+g conflict-free)
    constexpr int NH  = COUT / 64;
    constexpr int statOff = (COUT == 64) ? 128 : 256;
    extern __shared__ float sm[];
    unsigned* Xhi   = (unsigned*)sm;                  // [256][36]
    unsigned* Xlo   = Xhi + 256*XSP;
    unsigned* Whi   = Xlo + 256*XSP;                  // [32][72]
    unsigned* Wlo   = Whi + 32*WSP;
    float*    sstat = (float*)(Wlo + 32*WSP);         // [2*COUT]
    float*    aux   = sstat + 2*COUT;                 // COUT==64: 320 floats
    int t = threadIdx.x;
    size_t row0 = (size_t)blockIdx.x * 256;

    for (int i = t; i < 2*COUT; i += 256) sstat[i] = 0.f;

    if (COUT == 64) {
        if (t < 64) {
            aux[t]     = w0[t*67];   aux[64+t]  = w0[t*67+1]; aux[128+t] = w0[t*67+2];
            aux[192+t] = g_scale[t]; aux[256+t] = g_shift[t];
        }
        __syncthreads();
        #pragma unroll
        for (int j = 0; j < 2; j++) {
            int idx = t + j*256;
            int r = idx >> 1, half = idx & 1;
            size_t row = row0 + r;
            int g = g_gidx[row];
            int ss = (int)((row >> 5) & 1023), b = (int)(row >> 15);
            const float* nc = newxyz + ((size_t)b*NS + ss)*3;
            const float* pt = xyz + ((size_t)b*NPT + g)*3;
            float gx = pt[0]-nc[0], gy = pt[1]-nc[1], gz = pt[2]-nc[2];
            const float4* pr = (const float4*)(g_pprime + ((size_t)b*NPT + g)*64 + half*32);
            #pragma unroll
            for (int qq = 0; qq < 8; qq++) {
                float4 v = pr[qq]; int c = half*32 + qq*4;
                float z0 = fmaf(aux[c  ], gx, fmaf(aux[64+c  ], gy, fmaf(aux[128+c  ], gz, v.x)));
                float z1 = fmaf(aux[c+1], gx, fmaf(aux[64+c+1], gy, fmaf(aux[128+c+1], gz, v.y)));
                float z2 = fmaf(aux[c+2], gx, fmaf(aux[64+c+2], gy, fmaf(aux[128+c+2], gz, v.z)));
                float z3 = fmaf(aux[c+3], gx, fmaf(aux[64+c+3], gy, fmaf(aux[128+c+3], gz, v.w)));
                float v0 = fmaxf(fmaf(z0, aux[192+c  ], aux[256+c  ]), 0.f);
                float v1 = fmaxf(fmaf(z1, aux[192+c+1], aux[256+c+1]), 0.f);
                float v2 = fmaxf(fmaf(z2, aux[192+c+2], aux[256+c+2]), 0.f);
                float v3 = fmaxf(fmaf(z3, aux[192+c+3], aux[256+c+3]), 0.f);
                unsigned ph0 = pack_bf16x2(v0, v1);
                unsigned ph1 = pack_bf16x2(v2, v3);
                unsigned pl0 = pack_bf16x2(v0 - bf16lo_f32(ph0), v1 - bf16hi_f32(ph0));
                unsigned pl1 = pack_bf16x2(v2 - bf16lo_f32(ph1), v3 - bf16hi_f32(ph1));
                int kp = c >> 1;
                *(uint2*)(Xhi + (size_t)r*XSP + kp) = make_uint2(ph0, ph1);
                *(uint2*)(Xlo + (size_t)r*XSP + kp) = make_uint2(pl0, pl1);
            }
        }
    } else {
        int c0 = (t*4) & 63;
        float s0=g_scale[64+c0], s1=g_scale[64+c0+1], s2=g_scale[64+c0+2], s3=g_scale[64+c0+3];
        float h0=g_shift[64+c0], h1=g_shift[64+c0+1], h2=g_shift[64+c0+2], h3=g_shift[64+c0+3];
        #pragma unroll
        for (int j = 0; j < 16; j++) {
            int e = t*4 + j*1024;
            float4 v = *(const float4*)(g_zB + row0*64 + e);
            int r = e >> 6;
            float v0 = fmaxf(fmaf(v.x, s0, h0), 0.f);
            float v1 = fmaxf(fmaf(v.y, s1, h1), 0.f);
            float v2 = fmaxf(fmaf(v.z, s2, h2), 0.f);
            float v3 = fmaxf(fmaf(v.w, s3, h3), 0.f);
            unsigned ph0 = pack_bf16x2(v0, v1);
            unsigned ph1 = pack_bf16x2(v2, v3);
            unsigned pl0 = pack_bf16x2(v0 - bf16lo_f32(ph0), v1 - bf16hi_f32(ph0));
            unsigned pl1 = pack_bf16x2(v2 - bf16lo_f32(ph1), v3 - bf16hi_f32(ph1));
            int kp = c0 >> 1;
            *(uint2*)(Xhi + (size_t)r*XSP + kp) = make_uint2(ph0, ph1);
            *(uint2*)(Xlo + (size_t)r*XSP + kp) = make_uint2(pl0, pl1);
        }
    }

    int w = t >> 5, lane = t & 31;
    int g = lane >> 2, tig = lane & 3;
    int rbase = w*32 + g;

    #pragma unroll
    for (int nh = 0; nh < NH; nh++) {
        __syncthreads();      // X build done / prior epilogue drained before W chunk (re)load
        for (int i = t; i < 64*32; i += 256) {
            int n = i >> 5, kp = i & 31;
            float2 wv = *(const float2*)(W + (size_t)(nh*64 + n)*64 + 2*kp);
            unsigned ph = pack_bf16x2(wv.x, wv.y);
            unsigned pl = pack_bf16x2(wv.x - bf16lo_f32(ph), wv.y - bf16hi_f32(ph));
            Whi[kp*WSP + n] = ph;
            Wlo[kp*WSP + n] = pl;
        }
        __syncthreads();

        float acc0[8][4], acc1[8][4];
        #pragma unroll
        for (int nt = 0; nt < 8; nt++) {
            acc0[nt][0]=0.f; acc0[nt][1]=0.f; acc0[nt][2]=0.f; acc0[nt][3]=0.f;
            acc1[nt][0]=0.f; acc1[nt][1]=0.f; acc1[nt][2]=0.f; acc1[nt][3]=0.f;
        }
        #pragma unroll
        for (int kt = 0; kt < 4; kt++) {
            int xb0 = rbase*XSP + kt*8 + tig;
            unsigned ah0[4], al0[4], ah1[4], al1[4];
            ah0[0] = Xhi[xb0];            ah0[1] = Xhi[xb0 + 8*XSP];
            ah0[2] = Xhi[xb0 + 4];        ah0[3] = Xhi[xb0 + 8*XSP + 4];
            al0[0] = Xlo[xb0];            al0[1] = Xlo[xb0 + 8*XSP];
            al0[2] = Xlo[xb0 + 4];        al0[3] = Xlo[xb0 + 8*XSP + 4];
            int xb1 = xb0 + 16*XSP;
            ah1[0] = Xhi[xb1];            ah1[1] = Xhi[xb1 + 8*XSP];
            ah1[2] = Xhi[xb1 + 4];        ah1[3] = Xhi[xb1 + 8*XSP + 4];
            al1[0] = Xlo[xb1];            al1[1] = Xlo[xb1 + 8*XSP];
            al1[2] = Xlo[xb1 + 4];        al1[3] = Xlo[xb1 + 8*XSP + 4];
            int wb = (kt*8 + tig)*WSP + g;
            #pragma unroll
            for (int nt = 0; nt < 8; nt++) {
                unsigned bh[2] = { Whi[wb + nt*8], Whi[wb + nt*8 + 4*WSP] };
                unsigned bl[2] = { Wlo[wb + nt*8], Wlo[wb + nt*8 + 4*WSP] };
                mma_bf16(acc0[nt], ah0, bl);
                mma_bf16(acc0[nt], al0, bh);
                mma_bf16(acc0[nt], ah0, bh);
                mma_bf16(acc1[nt], ah1, bl);
                mma_bf16(acc1[nt], al1, bh);
                mma_bf16(acc1[nt], ah1, bh);
            }
        }

        if (COUT == 64) {
            float* yr = g_zB + (row0 + rbase)*(size_t)64 + 2*tig;
            #pragma unroll
            for (int nt = 0; nt < 8; nt++) {
                *(float2*)(yr + nt*8)           = make_float2(acc0[nt][0], acc0[nt][1]);
                *(float2*)(yr + 8*64 + nt*8)    = make_float2(acc0[nt][2], acc0[nt][3]);
                *(float2*)(yr + 16*64 + nt*8)   = make_float2(acc1[nt][0], acc1[nt][1]);
                *(float2*)(yr + 24*64 + nt*8)   = make_float2(acc1[nt][2], acc1[nt][3]);
            }
        }

        // stats (+ maxmin for COUT==128); warp covers exactly one (b,s) group (32 rows)
        #pragma unroll
        for (int nt = 0; nt < 8; nt++) {
            int c0 = nh*64 + nt*8 + 2*tig;
            float a0=acc0[nt][0], a1=acc0[nt][1], a2=acc0[nt][2], a3=acc0[nt][3];
            float b0=acc1[nt][0], b1=acc1[nt][1], b2=acc1[nt][2], b3=acc1[nt][3];
            float sc0 = (a0 + a2) + (b0 + b2);
            float sc1 = (a1 + a3) + (b1 + b3);
            float qc0 = (a0*a0 + a2*a2) + (b0*b0 + b2*b2);
            float qc1 = (a1*a1 + a3*a3) + (b1*b1 + b3*b3);
            #pragma unroll
            for (int off = 4; off <= 16; off <<= 1) {
                sc0 += __shfl_xor_sync(0xffffffffu, sc0, off);
                sc1 += __shfl_xor_sync(0xffffffffu, sc1, off);
                qc0 += __shfl_xor_sync(0xffffffffu, qc0, off);
                qc1 += __shfl_xor_sync(0xffffffffu, qc1, off);
            }
            if (g == 0) {
                atomicAdd(&sstat[c0],        sc0); atomicAdd(&sstat[c0+1],        sc1);
                atomicAdd(&sstat[COUT+c0],   qc0); atomicAdd(&sstat[COUT+c0+1],   qc1);
            }
            if (COUT == 128) {
                float m0 = fmaxf(fmaxf(a0, a2), fmaxf(b0, b2));
                float m1 = fmaxf(fmaxf(a1, a3), fmaxf(b1, b3));
                float n0 = fminf(fminf(a0, a2), fminf(b0, b2));
                float n1 = fminf(fminf(a1, a3), fminf(b1, b3));
                #pragma unroll
                for (int off = 4; off <= 16; off <<= 1) {
                    m0 = fmaxf(m0, __shfl_xor_sync(0xffffffffu, m0, off));
                    m1 = fmaxf(m1, __shfl_xor_sync(0xffffffffu, m1, off));
                    n0 = fminf(n0, __shfl_xor_sync(0xffffffffu, n0, off));
                    n1 = fminf(n1, __shfl_xor_sync(0xffffffffu, n1, off));
                }
                if (g == 0) {
                    size_t grp = (size_t)blockIdx.x*8 + w;
                    g_gmax[grp*128 + c0] = m0; g_gmax[grp*128 + c0+1] = m1;
                    g_gmin[grp*128 + c0] = n0; g_gmin[grp*128 + c0+1] = n1;
                }
            }
        }
    }
    __syncthreads();
    for (int i = t; i < COUT; i += 256) {
        atomicAdd(&g_stat[statOff + i],        (double)sstat[i]);
        atomicAdd(&g_stat[statOff + COUT + i], (double)sstat[COUT + i]);
    }
}

// ---- final output: BN2+ReLU+max via per-group extrema ----
__global__ void output_kernel(float* __restrict__ out) {
    int o = threadIdx.x;
    size_t bs = blockIdx.x;
    float sc = g_scale[128 + o], sh = g_shift[128 + o];
    float mx = g_gmax[bs*128 + o], mn = g_gmin[bs*128 + o];
    float v = (sc > 0.f) ? fmaf(sc, mx, sh) : fmaf(sc, mn, sh);
    int b = (int)(bs >> 10), s = (int)(bs & 1023);
    out[(size_t)NB*NS*3 + ((size_t)b*128 + o)*NS + s] = fmaxf(v, 0.f);
}

extern "C" void kernel_launch(void* const* d_in, const int* in_sizes, int n_in,
                              void* d_out, int out_size) {
    const float* xyz    = (const float*)d_in[0];
    const float* points = (const float*)d_in[1];
    const float* w0 = (const float*)d_in[2];
    const float* g0 = (const float*)d_in[3];
    const float* b0 = (const float*)d_in[4];
    const float* w1 = (const float*)d_in[5];
    const float* g1 = (const float*)d_in[6];
    const float* b1 = (const float*)d_in[7];
    const float* w2 = (const float*)d_in[8];
    const float* g2 = (const float*)d_in[9];
    const float* b2 = (const float*)d_in[10];
    float* out = (float*)d_out;

    const int FRONT_SMEM = 4*NPT*4;
    const int G64_SMEM   = (2*256*36 + 2*32*72)*4 + 2*64*4 + 320*4;   // 93952
    const int G128_SMEM  = (2*256*36 + 2*32*72)*4 + 2*128*4;          // 93184
    cudaFuncSetAttribute(front_kernel, cudaFuncAttributeMaxDynamicSharedMemorySize, FRONT_SMEM);
    cudaFuncSetAttribute(gemm_tc_kernel<64>,  cudaFuncAttributeMaxDynamicSharedMemorySize, G64_SMEM);
    cudaFuncSetAttribute(gemm_tc_kernel<128>, cudaFuncAttributeMaxDynamicSharedMemorySize, G128_SMEM);

    zero_kernel<<<1, 512>>>();
    front_kernel<<<1552, FTH, FRONT_SMEM>>>(xyz, points, w0, out);
    finalize_kernel<<<1, 128>>>(64, 0, 0, g0, b0);
    gemm_tc_kernel<64><<<MROWS/256, 256, G64_SMEM>>>(w1, w0, xyz, out);
    finalize_kernel<<<1, 128>>>(64, 128, 64, g1, b1);
    gemm_tc_kernel<128><<<MROWS/256, 256, G128_SMEM>>>(w2, nullptr, nullptr, nullptr);
    finalize_kernel<<<1, 128>>>(128, 256, 128, g2, b2);
    output_kernel<<<NB*NS, 128>>>(out);
    (void)in_sizes; (void)n_in; (void)out_size;
}

// round 13
// speedup vs baseline: 2.9393x; 1.0057x over previous
#include <cuda_runtime.h>
#include <cstddef>

#define NB 16
#define NPT 4096
#define NS 1024
#define NK 32
#define MROWS (NB*NS*NK)
#define FTH 512

__device__ __align__(16) float g_pprime[(size_t)NB*NPT*64];
__device__ int                 g_gidx[MROWS];
__device__ __align__(16) float g_zB[(size_t)MROWS*64];   // z1
__device__ __align__(16) float g_gmax[(size_t)NB*NS*128];
__device__ __align__(16) float g_gmin[(size_t)NB*NS*128];
__device__ double              g_stat[512];
__device__ float               g_scale[320];
__device__ float               g_shift[320];
__device__ int                 g_fpsprog[NB];
__device__ int                 g_bqdone[NB*32];
__device__ int                 g_ppcnt[NB];

__device__ __forceinline__ unsigned long long pk(float lo, float hi) {
    unsigned long long r;
    asm("mov.b64 %0, {%1,%2};" : "=l"(r) : "f"(lo), "f"(hi));
    return r;
}
__device__ __forceinline__ unsigned long long ffma2(unsigned long long a, unsigned long long b, unsigned long long c) {
    unsigned long long d;
    asm("fma.rn.f32x2 %0, %1, %2, %3;" : "=l"(d) : "l"(a), "l"(b), "l"(c));
    return d;
}
__device__ __forceinline__ unsigned long long add2(unsigned long long a, unsigned long long b) {
    unsigned long long d;
    asm("add.rn.f32x2 %0, %1, %2;" : "=l"(d) : "l"(a), "l"(b));
    return d;
}
__device__ __forceinline__ unsigned long long mul2(unsigned long long a, unsigned long long b) {
    unsigned long long d;
    asm("mul.rn.f32x2 %0, %1, %2;" : "=l"(d) : "l"(a), "l"(b));
    return d;
}
__device__ __forceinline__ void upk(unsigned long long v, float& lo, float& hi) {
    asm("mov.b64 {%0,%1}, %2;" : "=f"(lo), "=f"(hi) : "l"(v));
}
__device__ __forceinline__ unsigned redux_umax(unsigned v) {
    unsigned r;
    asm("redux.sync.max.u32 %0, %1, 0xffffffff;" : "=r"(r) : "r"(v));
    return r;
}
// pack (even,odd) floats into bf16x2 word: low 16 bits = even element
__device__ __forceinline__ unsigned pack_bf16x2(float even, float odd) {
    unsigned d;
    asm("cvt.rn.bf16x2.f32 %0, %1, %2;" : "=r"(d) : "f"(odd), "f"(even));
    return d;
}
__device__ __forceinline__ float bf16lo_f32(unsigned p) { return __uint_as_float(p << 16); }
__device__ __forceinline__ float bf16hi_f32(unsigned p) { return __uint_as_float(p & 0xffff0000u); }

__device__ __forceinline__ void mma_bf16(float* c, const unsigned* a, const unsigned* b) {
    asm volatile("mma.sync.aligned.m16n8k16.row.col.f32.bf16.bf16.f32 "
        "{%0,%1,%2,%3}, {%4,%5,%6,%7}, {%8,%9}, {%0,%1,%2,%3};"
        : "+f"(c[0]), "+f"(c[1]), "+f"(c[2]), "+f"(c[3])
        : "r"(a[0]), "r"(a[1]), "r"(a[2]), "r"(a[3]), "r"(b[0]), "r"(b[1]));
}
__device__ __forceinline__ void spin_until(volatile int* p, int target) {
    while (*p < target) __nanosleep(64);
}

__global__ void zero_kernel() {
    int t = threadIdx.x;
    if (t < 512) { g_stat[t] = 0.0; g_bqdone[t] = 0; }
    if (t < NB) { g_fpsprog[t] = 0; g_ppcnt[t] = 0; }
}

// =================== mega front kernel with fps progress pipelining (unchanged) ===================
__global__ void __launch_bounds__(FTH) front_kernel(const float* __restrict__ xyz,
                                                    const float* __restrict__ points,
                                                    const float* __restrict__ w0,
                                                    float* __restrict__ out_newxyz) {
    extern __shared__ float dsm[];
    int bid = blockIdx.x;
    int t = threadIdx.x;

    if (bid < 16) {
        int b = bid;
        float* sx = dsm; float* sy = dsm + NPT; float* sz = dsm + 2*NPT;
        unsigned* swhi = (unsigned*)(dsm + 3*NPT);
        unsigned* swlo = swhi + 32;
        int w = t >> 5, lane = t & 31;
        const float* p = xyz + (size_t)b*NPT*3;
        for (int i = t; i < NPT; i += FTH) { sx[i]=p[3*i]; sy[i]=p[3*i+1]; sz[i]=p[3*i+2]; }
        __syncthreads();
        unsigned long long pxp[4], pyp[4], pzp[4];
        float dist[8];
        const float INF = __int_as_float(0x7f800000);
        #pragma unroll
        for (int j = 0; j < 4; j++) {
            int p0 = t + (2*j)*FTH, p1 = t + (2*j+1)*FTH;
            pxp[j] = pk(sx[p0], sx[p1]);
            pyp[j] = pk(sy[p0], sy[p1]);
            pzp[j] = pk(sz[p0], sz[p1]);
            dist[2*j] = INF; dist[2*j+1] = INF;
        }
        int far = 0;
        for (int it = 0; it < NS; it++) {
            if (t == 0) {
                size_t o = ((size_t)b*NS + it)*3;
                out_newxyz[o] = sx[far]; out_newxyz[o+1] = sy[far]; out_newxyz[o+2] = sz[far];
                if (((it+1) & 31) == 0) { __threadfence(); atomicExch(&g_fpsprog[b], it+1); }
            }
            if (it == NS-1) break;
            float cx = sx[far], cy = sy[far], cz = sz[far];
            unsigned long long ncx = pk(-cx,-cx), ncy = pk(-cy,-cy), ncz = pk(-cz,-cz);
            #pragma unroll
            for (int j = 0; j < 4; j++) {
                unsigned long long dx = add2(pxp[j], ncx);
                unsigned long long dy = add2(pyp[j], ncy);
                unsigned long long dz = add2(pzp[j], ncz);
                unsigned long long d2 = add2(add2(mul2(dx,dx), mul2(dy,dy)), mul2(dz,dz));
                float d0, d1; upk(d2, d0, d1);
                dist[2*j]   = fminf(dist[2*j],   d0);
                dist[2*j+1] = fminf(dist[2*j+1], d1);
            }
            float m0 = fmaxf(dist[0], dist[1]), m1 = fmaxf(dist[2], dist[3]);
            float m2 = fmaxf(dist[4], dist[5]), m3 = fmaxf(dist[6], dist[7]);
            float best = fmaxf(fmaxf(m0, m1), fmaxf(m2, m3));
            unsigned inv = 0u;
            #pragma unroll
            for (int k = 0; k < 8; k++) {
                unsigned cand = 0xFFFFFFFFu - (unsigned)(t + k*FTH);
                if (dist[k] == best && cand > inv) inv = cand;
            }
            unsigned hi  = __float_as_uint(best);
            unsigned whi = redux_umax(hi);
            unsigned lo  = (hi == whi) ? inv : 0u;
            unsigned wlo = redux_umax(lo);
            int buf = (it & 1) << 4;
            if (lane == 0) { swhi[buf + w] = whi; swlo[buf + w] = wlo; }
            __syncthreads();
            unsigned h2 = swhi[buf + (lane & 15)];
            unsigned l2 = swlo[buf + (lane & 15)];
            unsigned mh = redux_umax(h2);
            unsigned ml = redux_umax((h2 == mh) ? l2 : 0u);
            far = (int)(0xFFFFFFFFu - ml);
        }

    } else if (bid < 528) {
        int idx = bid - 16;
        int b = idx >> 5, n0 = (idx & 31) * 128;
        float* Pts = dsm;
        float* Wt  = dsm + 64*128;
        for (int i = t; i < 64*64; i += FTH) { int o = i>>6, c = i&63; Wt[c*64 + o] = w0[o*67 + 3 + c]; }
        const float* pb = points + (size_t)b*64*NPT;
        for (int i = t; i < 64*128/4; i += FTH) {
            int e = i*4, c = e>>7, n = e&127;
            *(float4*)&Pts[c*128 + n] = *(const float4*)(pb + (size_t)c*NPT + n0 + n);
        }
        __syncthreads();
        int cg = t & 15, rg = t >> 4;
        unsigned long long acc[4][2];
        #pragma unroll
        for (int i = 0; i < 4; i++) { acc[i][0]=0ull; acc[i][1]=0ull; }
        #pragma unroll 4
        for (int c = 0; c < 64; c++) {
            ulonglong2 wv = *(const ulonglong2*)&Wt[c*64 + cg*4];
            #pragma unroll
            for (int i = 0; i < 4; i++) {
                float a = Pts[c*128 + rg*4 + i];
                unsigned long long aa = pk(a, a);
                acc[i][0] = ffma2(aa, wv.x, acc[i][0]);
                acc[i][1] = ffma2(aa, wv.y, acc[i][1]);
            }
        }
        float* outp = g_pprime + ((size_t)b*NPT + n0)*64;
        #pragma unroll
        for (int i = 0; i < 4; i++) {
            float4 v; upk(acc[i][0], v.x, v.y); upk(acc[i][1], v.z, v.w);
            *(float4*)(outp + (size_t)(rg*4+i)*64 + cg*4) = v;
        }
        __threadfence();
        __syncthreads();
        if (t == 0) atomicAdd(&g_ppcnt[b], 1);

    } else if (bid < 1040) {
        int idx = bid - 528;
        int b = idx >> 5, sb = idx & 31;
        float* sx = dsm; float* sy = dsm + NPT; float* sz = dsm + 2*NPT; float* spp = dsm + 3*NPT;
        int w = t>>5, lane = t&31;
        const float* p = xyz + (size_t)b*NPT*3;
        for (int i = t; i < NPT; i += FTH) {
            float px = p[3*i], py = p[3*i+1], pz = p[3*i+2];
            sx[i]=px; sy[i]=py; sz[i]=pz;
            spp[i] = __fadd_rn(__fadd_rn(__fmul_rn(px,px), __fmul_rn(py,py)), __fmul_rn(pz,pz));
        }
        if (t == 0) { spin_until(&g_fpsprog[b], (sb+1)*32); __threadfence(); }
        __syncthreads();
        const float* newxyz = out_newxyz;
        for (int q = 0; q < 2; q++) {
            int s = sb*32 + w*2 + q;
            const float* nc = newxyz + ((size_t)b*NS + s)*3;
            float cx = nc[0], cy = nc[1], cz = nc[2];
            float cc = __fadd_rn(__fadd_rn(__fmul_rn(cx,cx), __fmul_rn(cy,cy)), __fmul_rn(cz,cz));
            int count = 0, first = 0;
            int* go = g_gidx + ((size_t)b*NS + s)*NK;
            for (int base = 0; base < NPT && count < NK; base += 32) {
                int pi = base + lane;
                float px = sx[pi], py = sy[pi], pz = sz[pi];
                float pp  = spp[pi];
                float dot = __fadd_rn(__fadd_rn(__fmul_rn(cx,px), __fmul_rn(cy,py)), __fmul_rn(cz,pz));
                float sqr = __fadd_rn(__fadd_rn(cc, pp), -__fmul_rn(2.0f, dot));
                bool in = (sqr <= 0.04f);
                unsigned mask = __ballot_sync(0xffffffffu, in);
                if (count == 0 && mask) first = base + __ffs(mask) - 1;
                if (in) {
                    int pos = count + __popc(mask & ((1u << lane) - 1u));
                    if (pos < NK) go[pos] = pi;
                }
                count += __popc(mask);
            }
            if (count < NK && lane >= count) go[lane] = first;
        }
        __threadfence();
        __syncthreads();
        if (t == 0) atomicExch(&g_bqdone[b*32 + sb], 1);

    } else {
        int idx = bid - 1040;
        int b = idx >> 5, sb = idx & 31;
        float* wx = dsm; float* wy = dsm + 64; float* wz = dsm + 128;
        float* ssum = dsm + 192;
        float* ssq  = dsm + 192 + 512;
        if (t < 64) { wx[t]=w0[t*67]; wy[t]=w0[t*67+1]; wz[t]=w0[t*67+2]; }
        if (t == 0) {
            spin_until(&g_bqdone[b*32 + sb], 1);
            spin_until(&g_ppcnt[b], 32);
            __threadfence();
        }
        __syncthreads();
        int c = t & 63, rl = t >> 6;
        float wxc = wx[c], wyc = wy[c], wzc = wz[c];
        float s = 0.f, q = 0.f;
        size_t base = (size_t)b * (MROWS/NB) + (size_t)sb * 1024;
        const float* newxyz = out_newxyz;
        for (int i = 0; i < 128; i++) {
            size_t row = base + i*8 + rl;
            int g = g_gidx[row];
            int ss = (int)((row >> 5) & 1023);
            const float* nc = newxyz + ((size_t)b*NS + ss)*3;
            const float* pt = xyz + ((size_t)b*NPT + g)*3;
            float gx = pt[0]-nc[0], gy = pt[1]-nc[1], gz = pt[2]-nc[2];
            float v = g_pprime[((size_t)b*NPT + g)*64 + c];
            v = fmaf(wxc, gx, fmaf(wyc, gy, fmaf(wzc, gz, v)));
            s += v; q = fmaf(v, v, q);
        }
        ssum[rl*64 + c] = s; ssq[rl*64 + c] = q;
        __syncthreads();
        if (t < 64) {
            double S = 0.0, Q = 0.0;
            #pragma unroll
            for (int r = 0; r < 8; r++) { S += (double)ssum[r*64 + t]; Q += (double)ssq[r*64 + t]; }
            atomicAdd(&g_stat[t], S);
            atomicAdd(&g_stat[64 + t], Q);
        }
    }
}

__global__ void finalize_kernel(int C, int statOff, int bnOff,
                                const float* __restrict__ g, const float* __restrict__ bb) {
    int c = threadIdx.x;
    if (c >= C) return;
    double inv = 1.0 / (double)MROWS;
    double mean = g_stat[statOff + c] * inv;
    double var  = g_stat[statOff + C + c] * inv - mean*mean;
    double sc = (double)g[c] / sqrt(var + 1e-5);
    g_scale[bnOff + c] = (float)sc;
    g_shift[bnOff + c] = (float)((double)bb[c] - mean * sc);
}

// ---- TC GEMM v5: 3xBF16 m16n8k16, term-major MMA scheduling (RAW distance 8) ----
template<int COUT>
__global__ void __launch_bounds__(256, 2) gemm_tc_kernel(const float* __restrict__ W,
                                                      const float* __restrict__ w0,
                                                      const float* __restrict__ xyz,
                                                      const float* __restrict__ newxyz) {
    constexpr int XSP = 36;
    constexpr int WSP = 72;
    constexpr int NH  = COUT / 64;
    constexpr int statOff = (COUT == 64) ? 128 : 256;
    extern __shared__ float sm[];
    unsigned* Xhi   = (unsigned*)sm;                  // [256][36]
    unsigned* Xlo   = Xhi + 256*XSP;
    unsigned* Whi   = Xlo + 256*XSP;                  // [32][72]
    unsigned* Wlo   = Whi + 32*WSP;
    float*    sstat = (float*)(Wlo + 32*WSP);         // [2*COUT]
    float*    aux   = sstat + 2*COUT;
    int t = threadIdx.x;
    size_t row0 = (size_t)blockIdx.x * 256;

    for (int i = t; i < 2*COUT; i += 256) sstat[i] = 0.f;

    if (COUT == 64) {
        if (t < 64) {
            aux[t]     = w0[t*67];   aux[64+t]  = w0[t*67+1]; aux[128+t] = w0[t*67+2];
            aux[192+t] = g_scale[t]; aux[256+t] = g_shift[t];
        }
        __syncthreads();
        #pragma unroll
        for (int j = 0; j < 2; j++) {
            int idx = t + j*256;
            int r = idx >> 1, half = idx & 1;
            size_t row = row0 + r;
            int g = g_gidx[row];
            int ss = (int)((row >> 5) & 1023), b = (int)(row >> 15);
            const float* nc = newxyz + ((size_t)b*NS + ss)*3;
            const float* pt = xyz + ((size_t)b*NPT + g)*3;
            float gx = pt[0]-nc[0], gy = pt[1]-nc[1], gz = pt[2]-nc[2];
            const float4* pr = (const float4*)(g_pprime + ((size_t)b*NPT + g)*64 + half*32);
            #pragma unroll
            for (int qq = 0; qq < 8; qq++) {
                float4 v = pr[qq]; int c = half*32 + qq*4;
                float z0 = fmaf(aux[c  ], gx, fmaf(aux[64+c  ], gy, fmaf(aux[128+c  ], gz, v.x)));
                float z1 = fmaf(aux[c+1], gx, fmaf(aux[64+c+1], gy, fmaf(aux[128+c+1], gz, v.y)));
                float z2 = fmaf(aux[c+2], gx, fmaf(aux[64+c+2], gy, fmaf(aux[128+c+2], gz, v.z)));
                float z3 = fmaf(aux[c+3], gx, fmaf(aux[64+c+3], gy, fmaf(aux[128+c+3], gz, v.w)));
                float v0 = fmaxf(fmaf(z0, aux[192+c  ], aux[256+c  ]), 0.f);
                float v1 = fmaxf(fmaf(z1, aux[192+c+1], aux[256+c+1]), 0.f);
                float v2 = fmaxf(fmaf(z2, aux[192+c+2], aux[256+c+2]), 0.f);
                float v3 = fmaxf(fmaf(z3, aux[192+c+3], aux[256+c+3]), 0.f);
                unsigned ph0 = pack_bf16x2(v0, v1);
                unsigned ph1 = pack_bf16x2(v2, v3);
                unsigned pl0 = pack_bf16x2(v0 - bf16lo_f32(ph0), v1 - bf16hi_f32(ph0));
                unsigned pl1 = pack_bf16x2(v2 - bf16lo_f32(ph1), v3 - bf16hi_f32(ph1));
                int kp = c >> 1;
                *(uint2*)(Xhi + (size_t)r*XSP + kp) = make_uint2(ph0, ph1);
                *(uint2*)(Xlo + (size_t)r*XSP + kp) = make_uint2(pl0, pl1);
            }
        }
    } else {
        int c0 = (t*4) & 63;
        float s0=g_scale[64+c0], s1=g_scale[64+c0+1], s2=g_scale[64+c0+2], s3=g_scale[64+c0+3];
        float h0=g_shift[64+c0], h1=g_shift[64+c0+1], h2=g_shift[64+c0+2], h3=g_shift[64+c0+3];
        #pragma unroll
        for (int j = 0; j < 16; j++) {
            int e = t*4 + j*1024;
            float4 v = *(const float4*)(g_zB + row0*64 + e);
            int r = e >> 6;
            float v0 = fmaxf(fmaf(v.x, s0, h0), 0.f);
            float v1 = fmaxf(fmaf(v.y, s1, h1), 0.f);
            float v2 = fmaxf(fmaf(v.z, s2, h2), 0.f);
            float v3 = fmaxf(fmaf(v.w, s3, h3), 0.f);
            unsigned ph0 = pack_bf16x2(v0, v1);
            unsigned ph1 = pack_bf16x2(v2, v3);
            unsigned pl0 = pack_bf16x2(v0 - bf16lo_f32(ph0), v1 - bf16hi_f32(ph0));
            unsigned pl1 = pack_bf16x2(v2 - bf16lo_f32(ph1), v3 - bf16hi_f32(ph1));
            int kp = c0 >> 1;
            *(uint2*)(Xhi + (size_t)r*XSP + kp) = make_uint2(ph0, ph1);
            *(uint2*)(Xlo + (size_t)r*XSP + kp) = make_uint2(pl0, pl1);
        }
    }

    int w = t >> 5, lane = t & 31;
    int g = lane >> 2, tig = lane & 3;
    int rbase = w*32 + g;

    #pragma unroll
    for (int nh = 0; nh < NH; nh++) {
        __syncthreads();
        for (int i = t; i < 64*32; i += 256) {
            int n = i >> 5, kp = i & 31;
            float2 wv = *(const float2*)(W + (size_t)(nh*64 + n)*64 + 2*kp);
            unsigned ph = pack_bf16x2(wv.x, wv.y);
            unsigned pl = pack_bf16x2(wv.x - bf16lo_f32(ph), wv.y - bf16hi_f32(ph));
            Whi[kp*WSP + n] = ph;
            Wlo[kp*WSP + n] = pl;
        }
        __syncthreads();

        float acc0[8][4], acc1[8][4];
        #pragma unroll
        for (int nt = 0; nt < 8; nt++) {
            acc0[nt][0]=0.f; acc0[nt][1]=0.f; acc0[nt][2]=0.f; acc0[nt][3]=0.f;
            acc1[nt][0]=0.f; acc1[nt][1]=0.f; acc1[nt][2]=0.f; acc1[nt][3]=0.f;
        }
        #pragma unroll
        for (int kt = 0; kt < 4; kt++) {
            int xb0 = rbase*XSP + kt*8 + tig;
            unsigned ah0[4], al0[4], ah1[4], al1[4];
            ah0[0] = Xhi[xb0];            ah0[1] = Xhi[xb0 + 8*XSP];
            ah0[2] = Xhi[xb0 + 4];        ah0[3] = Xhi[xb0 + 8*XSP + 4];
            al0[0] = Xlo[xb0];            al0[1] = Xlo[xb0 + 8*XSP];
            al0[2] = Xlo[xb0 + 4];        al0[3] = Xlo[xb0 + 8*XSP + 4];
            int xb1 = xb0 + 16*XSP;
            ah1[0] = Xhi[xb1];            ah1[1] = Xhi[xb1 + 8*XSP];
            ah1[2] = Xhi[xb1 + 4];        ah1[3] = Xhi[xb1 + 8*XSP + 4];
            al1[0] = Xlo[xb1];            al1[1] = Xlo[xb1 + 8*XSP];
            al1[2] = Xlo[xb1 + 4];        al1[3] = Xlo[xb1 + 8*XSP + 4];
            int wb = (kt*8 + tig)*WSP + g;
            // nt chunks of 4: term-major issue, per-acc term order preserved
            #pragma unroll
            for (int cch = 0; cch < 2; cch++) {
                unsigned bh[4][2], bl[4][2];
                #pragma unroll
                for (int i = 0; i < 4; i++) {
                    int nt = cch*4 + i;
                    bh[i][0] = Whi[wb + nt*8]; bh[i][1] = Whi[wb + nt*8 + 4*WSP];
                    bl[i][0] = Wlo[wb + nt*8]; bl[i][1] = Wlo[wb + nt*8 + 4*WSP];
                }
                #pragma unroll
                for (int i = 0; i < 4; i++) {
                    mma_bf16(acc0[cch*4+i], ah0, bl[i]);
                    mma_bf16(acc1[cch*4+i], ah1, bl[i]);
                }
                #pragma unroll
                for (int i = 0; i < 4; i++) {
                    mma_bf16(acc0[cch*4+i], al0, bh[i]);
                    mma_bf16(acc1[cch*4+i], al1, bh[i]);
                }
                #pragma unroll
                for (int i = 0; i < 4; i++) {
                    mma_bf16(acc0[cch*4+i], ah0, bh[i]);
                    mma_bf16(acc1[cch*4+i], ah1, bh[i]);
                }
            }
        }

        if (COUT == 64) {
            float* yr = g_zB + (row0 + rbase)*(size_t)64 + 2*tig;
            #pragma unroll
            for (int nt = 0; nt < 8; nt++) {
                *(float2*)(yr + nt*8)           = make_float2(acc0[nt][0], acc0[nt][1]);
                *(float2*)(yr + 8*64 + nt*8)    = make_float2(acc0[nt][2], acc0[nt][3]);
                *(float2*)(yr + 16*64 + nt*8)   = make_float2(acc1[nt][0], acc1[nt][1]);
                *(float2*)(yr + 24*64 + nt*8)   = make_float2(acc1[nt][2], acc1[nt][3]);
            }
        }

        #pragma unroll
        for (int nt = 0; nt < 8; nt++) {
            int c0 = nh*64 + nt*8 + 2*tig;
            float a0=acc0[nt][0], a1=acc0[nt][1], a2=acc0[nt][2], a3=acc0[nt][3];
            float b0=acc1[nt][0], b1=acc1[nt][1], b2=acc1[nt][2], b3=acc1[nt][3];
            float sc0 = (a0 + a2) + (b0 + b2);
            float sc1 = (a1 + a3) + (b1 + b3);
            float qc0 = (a0*a0 + a2*a2) + (b0*b0 + b2*b2);
            float qc1 = (a1*a1 + a3*a3) + (b1*b1 + b3*b3);
            #pragma unroll
            for (int off = 4; off <= 16; off <<= 1) {
                sc0 += __shfl_xor_sync(0xffffffffu, sc0, off);
                sc1 += __shfl_xor_sync(0xffffffffu, sc1, off);
                qc0 += __shfl_xor_sync(0xffffffffu, qc0, off);
                qc1 += __shfl_xor_sync(0xffffffffu, qc1, off);
            }
            if (g == 0) {
                atomicAdd(&sstat[c0],        sc0); atomicAdd(&sstat[c0+1],        sc1);
                atomicAdd(&sstat[COUT+c0],   qc0); atomicAdd(&sstat[COUT+c0+1],   qc1);
            }
            if (COUT == 128) {
                float m0 = fmaxf(fmaxf(a0, a2), fmaxf(b0, b2));
                float m1 = fmaxf(fmaxf(a1, a3), fmaxf(b1, b3));
                float n0 = fminf(fminf(a0, a2), fminf(b0, b2));
                float n1 = fminf(fminf(a1, a3), fminf(b1, b3));
                #pragma unroll
                for (int off = 4; off <= 16; off <<= 1) {
                    m0 = fmaxf(m0, __shfl_xor_sync(0xffffffffu, m0, off));
                    m1 = fmaxf(m1, __shfl_xor_sync(0xffffffffu, m1, off));
                    n0 = fminf(n0, __shfl_xor_sync(0xffffffffu, n0, off));
                    n1 = fminf(n1, __shfl_xor_sync(0xffffffffu, n1, off));
                }
                if (g == 0) {
                    size_t grp = (size_t)blockIdx.x*8 + w;
                    g_gmax[grp*128 + c0] = m0; g_gmax[grp*128 + c0+1] = m1;
                    g_gmin[grp*128 + c0] = n0; g_gmin[grp*128 + c0+1] = n1;
                }
            }
        }
    }
    __syncthreads();
    for (int i = t; i < COUT; i += 256) {
        atomicAdd(&g_stat[statOff + i],        (double)sstat[i]);
        atomicAdd(&g_stat[statOff + COUT + i], (double)sstat[COUT + i]);
    }
}

// ---- final output: BN2+ReLU+max via per-group extrema ----
__global__ void output_kernel(float* __restrict__ out) {
    int o = threadIdx.x;
    size_t bs = blockIdx.x;
    float sc = g_scale[128 + o], sh = g_shift[128 + o];
    float mx = g_gmax[bs*128 + o], mn = g_gmin[bs*128 + o];
    float v = (sc > 0.f) ? fmaf(sc, mx, sh) : fmaf(sc, mn, sh);
    int b = (int)(bs >> 10), s = (int)(bs & 1023);
    out[(size_t)NB*NS*3 + ((size_t)b*128 + o)*NS + s] = fmaxf(v, 0.f);
}

extern "C" void kernel_launch(void* const* d_in, const int* in_sizes, int n_in,
                              void* d_out, int out_size) {
    const float* xyz    = (const float*)d_in[0];
    const float* points = (const float*)d_in[1];
    const float* w0 = (const float*)d_in[2];
    const float* g0 = (const float*)d_in[3];
    const float* b0 = (const float*)d_in[4];
    const float* w1 = (const float*)d_in[5];
    const float* g1 = (const float*)d_in[6];
    const float* b1 = (const float*)d_in[7];
    const float* w2 = (const float*)d_in[8];
    const float* g2 = (const float*)d_in[9];
    const float* b2 = (const float*)d_in[10];
    float* out = (float*)d_out;

    const int FRONT_SMEM = 4*NPT*4;
    const int G64_SMEM   = (2*256*36 + 2*32*72)*4 + 2*64*4 + 320*4;   // 93952
    const int G128_SMEM  = (2*256*36 + 2*32*72)*4 + 2*128*4;          // 93184
    cudaFuncSetAttribute(front_kernel, cudaFuncAttributeMaxDynamicSharedMemorySize, FRONT_SMEM);
    cudaFuncSetAttribute(gemm_tc_kernel<64>,  cudaFuncAttributeMaxDynamicSharedMemorySize, G64_SMEM);
    cudaFuncSetAttribute(gemm_tc_kernel<128>, cudaFuncAttributeMaxDynamicSharedMemorySize, G128_SMEM);

    zero_kernel<<<1, 512>>>();
    front_kernel<<<1552, FTH, FRONT_SMEM>>>(xyz, points, w0, out);
    finalize_kernel<<<1, 128>>>(64, 0, 0, g0, b0);
    gemm_tc_kernel<64><<<MROWS/256, 256, G64_SMEM>>>(w1, w0, xyz, out);
    finalize_kernel<<<1, 128>>>(64, 128, 64, g1, b1);
    gemm_tc_kernel<128><<<MROWS/256, 256, G128_SMEM>>>(w2, nullptr, nullptr, nullptr);
    finalize_kernel<<<1, 128>>>(128, 256, 128, g2, b2);
    output_kernel<<<NB*NS, 128>>>(out);
    (void)in_sizes; (void)n_in; (void)out_size;
}